// round 6
// baseline (speedup 1.0000x reference)
#include <cuda_runtime.h>
#include <cuda_bf16.h>
#include <cstdint>

typedef unsigned int u32;
typedef unsigned long long u64;

#define E_NODES 1000000

// Scratch activations + pre-split weights (alloc-free rule: __device__ globals)
__device__ float g_bufA[(size_t)E_NODES * 64];
__device__ float g_bufB[(size_t)E_NODES * 64];
__device__ __nv_bfloat16 g_W0[2 * 64 * 64];      // layer0: [term][n][kpad64]
__device__ __nv_bfloat16 g_WR[3 * 2 * 64 * 320]; // layers1-3: [l][term][n][k]

// ---------------------------------------------------------------------------
// helpers
// ---------------------------------------------------------------------------
__device__ __forceinline__ u32 s2u(const void* p) {
    u32 a;
    asm("{.reg .u64 t; cvta.to.shared.u64 t,%1; cvt.u32.u64 %0,t;}" : "=r"(a) : "l"(p));
    return a;
}
__device__ __forceinline__ u32 swz(u32 b) { return b ^ ((b >> 3) & 0x70); }

__device__ __forceinline__ void ldmx4(u32* r, u32 addr) {
    asm volatile("ldmatrix.sync.aligned.m8n8.x4.shared.b16 {%0,%1,%2,%3},[%4];"
                 : "=r"(r[0]), "=r"(r[1]), "=r"(r[2]), "=r"(r[3]) : "r"(addr));
}
__device__ __forceinline__ void mma16816(float* d, const u32* a, u32 b0, u32 b1) {
    asm volatile(
        "mma.sync.aligned.m16n8k16.row.col.f32.bf16.bf16.f32 "
        "{%0,%1,%2,%3},{%4,%5,%6,%7},{%8,%9},{%0,%1,%2,%3};"
        : "+f"(d[0]), "+f"(d[1]), "+f"(d[2]), "+f"(d[3])
        : "r"(a[0]), "r"(a[1]), "r"(a[2]), "r"(a[3]), "r"(b0), "r"(b1));
}

__device__ __forceinline__ u64 pk2(float lo, float hi) {
    u64 r; asm("mov.b64 %0,{%1,%2};" : "=l"(r) : "f"(lo), "f"(hi)); return r;
}
__device__ __forceinline__ void upk2(u64 v, float& lo, float& hi) {
    asm("mov.b64 {%0,%1},%2;" : "=f"(lo), "=f"(hi) : "l"(v));
}
__device__ __forceinline__ void ffma2(u64& d, u64 a, u64 b) {
    asm("fma.rn.f32x2 %0,%1,%2,%0;" : "+l"(d) : "l"(a), "l"(b));
}

__device__ __forceinline__ u32 bits2(__nv_bfloat162 v) {
    u32 u; __builtin_memcpy(&u, &v, 4); return u;
}
// write 4 consecutive k-cols of one A row, split hi/lo
__device__ __forceinline__ void wr4(char* hT, char* lT, int n, int kc,
                                    float v0, float v1, float v2, float v3) {
    __nv_bfloat162 h01 = __floats2bfloat162_rn(v0, v1);
    __nv_bfloat162 h23 = __floats2bfloat162_rn(v2, v3);
    __nv_bfloat162 l01 = __floats2bfloat162_rn(v0 - __bfloat162float(h01.x),
                                               v1 - __bfloat162float(h01.y));
    __nv_bfloat162 l23 = __floats2bfloat162_rn(v2 - __bfloat162float(h23.x),
                                               v3 - __bfloat162float(h23.y));
    u32 off = swz((u32)(n * 128 + kc * 2));
    *(uint2*)(hT + off) = make_uint2(bits2(h01), bits2(h23));
    *(uint2*)(lT + off) = make_uint2(bits2(l01), bits2(l23));
}
__device__ __forceinline__ void wr1(char* hT, char* lT, int n, int k, float v) {
    __nv_bfloat16 h = __float2bfloat16_rn(v);
    __nv_bfloat16 l = __float2bfloat16_rn(v - __bfloat162float(h));
    u32 off = swz((u32)(n * 128 + k * 2));
    *(__nv_bfloat16*)(hT + off) = h;
    *(__nv_bfloat16*)(lT + off) = l;
}

// ---------------------------------------------------------------------------
// weight prep: transpose to [n][k], split bf16 hi/lo, zero-pad layer0 K 55->64
// ---------------------------------------------------------------------------
__global__ void prep_w(const float* __restrict__ w0, const float* __restrict__ wr)
{
    int i = blockIdx.x * blockDim.x + threadIdx.x;
    if (i < 64 * 64) {
        int n = i >> 6, k = i & 63;
        float v = (k < 55) ? w0[k * 64 + n] : 0.f;
        __nv_bfloat16 h = __float2bfloat16_rn(v);
        g_W0[(0 * 64 + n) * 64 + k] = h;
        g_W0[(1 * 64 + n) * 64 + k] = __float2bfloat16_rn(v - __bfloat162float(h));
    }
    if (i < 3 * 64 * 320) {
        int l = i / (64 * 320), r = i % (64 * 320);
        int n = r / 320, k = r % 320;
        float v = wr[(size_t)l * 320 * 64 + (size_t)k * 64 + n];
        __nv_bfloat16 h = __float2bfloat16_rn(v);
        g_WR[((size_t)(l * 2 + 0) * 64 + n) * 320 + k] = h;
        g_WR[((size_t)(l * 2 + 1) * 64 + n) * 320 + k] =
            __float2bfloat16_rn(v - __bfloat162float(h));
    }
}

// ---------------------------------------------------------------------------
// smem layout (bytes)
// ---------------------------------------------------------------------------
constexpr int OFF_IDX = 0;            // 128 x int4 = 2048
constexpr int OFF_BIAS = 2048, OFF_G = 2304, OFF_LB = 2560;
constexpr int OFF_C1 = 2816;          // 64x32 f32 = 8192 (CLS only)
constexpr int OFF_B1 = 11008, OFF_C2 = 11136;
constexpr int OFF_A = 11264;          // 1024-aligned
__host__ __device__ constexpr int ntmax(int C) { return (C == 64) ? 2 : 1; }
__host__ __device__ constexpr int off_b(int C) { return OFF_A + ntmax(C) * 2 * 16384; }
__host__ __device__ constexpr int smem_sz(int C) { return off_b(C) + ntmax(C) * 2 * 8192; }

// ---------------------------------------------------------------------------
// fused mesh-conv layer on mma.sync HMMA (split-bf16, 3-term)
// warp tile: 32 rows x 32 cols (minimal fragment-reload perimeter)
// ---------------------------------------------------------------------------
template <int C, bool RESID, bool CLS>
__global__ __launch_bounds__(256, 2)
void mesh_hmma(const float* __restrict__ xin, const int* __restrict__ nbr,
               const __nv_bfloat16* __restrict__ Wt,   // [term][64][KT]
               const float* __restrict__ bias, const float* __restrict__ lng,
               const float* __restrict__ lnb,
               const float* __restrict__ cw1, const float* __restrict__ cb1,
               const float* __restrict__ cw2, const float* __restrict__ cb2,
               float* __restrict__ out)
{
    constexpr bool C64 = (C == 64);
    constexpr int KT = C64 ? 320 : 64;
    constexpr int A_T = 16384, B_T = 8192;
    constexpr int OFF_BW = off_b(C);

    extern __shared__ char smc[];
    const int tid = threadIdx.x, wid = tid >> 5, lane = tid & 31;
    const int node0 = blockIdx.x * 128;

    auto At = [&](int t, int m) -> char* { return smc + OFF_A + (t * 2 + m) * A_T; };
    auto Bt = [&](int t, int m) -> char* { return smc + OFF_BW + (t * 2 + m) * B_T; };

    // ---- stage params, idx, classifier weights ----
    if (tid < 128) {
        int node = node0 + tid;
        int4 v = (node < E_NODES) ? ((const int4*)nbr)[node] : make_int4(0, 0, 0, 0);
        ((int4*)(smc + OFF_IDX))[tid] = v;
    }
    if (tid >= 128 && tid < 192) {
        int i = tid - 128;
        ((float*)(smc + OFF_BIAS))[i] = bias[i];
        ((float*)(smc + OFF_G))[i]    = lng[i];
        ((float*)(smc + OFF_LB))[i]   = lnb[i];
    }
    if (CLS) {
        for (int i = tid; i < 512; i += 256)
            ((float4*)(smc + OFF_C1))[i] = ((const float4*)cw1)[i];
        if (tid >= 192 && tid < 224) {
            int i = tid - 192;
            ((float*)(smc + OFF_B1))[i] = cb1[i];
            ((float*)(smc + OFF_C2))[i] = cw2[i];
        }
    }
    __syncthreads();

    const int  n      = tid >> 1;
    const int  half   = tid & 1;
    const bool vOK    = (node0 + n) < E_NODES;
    const int* sIdx   = (const int*)(smc + OFF_IDX);

    // warp tile: rows RW..RW+31, cols CW..CW+31
    const int RW = (wid >> 1) * 32;
    const int CW = (wid & 1) * 32;
    const int P0 = CW >> 4;            // first 16-col B group index

    float acc[8][4];                   // [rb*4 + nq][4]
#pragma unroll
    for (int q = 0; q < 8; q++)
#pragma unroll
        for (int c = 0; c < 4; c++) acc[q][c] = 0.f;

    constexpr int NPH = C64 ? 3 : 1;
    for (int ph = 0; ph < NPH; ph++) {
        const int ntile = (C64 && ph > 0) ? 2 : 1;
        const int seg0  = (ph == 0) ? 0 : (ph == 1 ? 1 : 3);

        // ---- stage B tiles (pre-split, pre-transposed in global) ----
        for (int t = 0; t < ntile; t++)
            for (int term = 0; term < 2; term++) {
                const char* src = (const char*)(Wt + ((size_t)term * 64) * KT + (size_t)(seg0 + t) * 64);
                char* dst = Bt(t, term);
                for (int j = tid; j < 512; j += 256) {
                    int r = j >> 3, c = j & 7;
                    uint4 v = *(const uint4*)(src + (size_t)r * KT * 2 + c * 16);
                    *(uint4*)(dst + swz((u32)(r * 128 + c * 16))) = v;
                }
            }

        // ---- gather + split-convert A tiles ----
        if (vOK) {
            if (C64) {
                if (ph == 0) {
                    const float4* xr = (const float4*)(xin + (size_t)(node0 + n) * 64) + half * 8;
                    char* hT = At(0, 0); char* lT = At(0, 1);
#pragma unroll
                    for (int i = 0; i < 8; i++) {
                        float4 v = xr[i];
                        wr4(hT, lT, n, half * 32 + i * 4, v.x, v.y, v.z, v.w);
                    }
                } else {
                    const int ia = sIdx[4 * n + (ph == 1 ? 0 : 1)];
                    const int ic = sIdx[4 * n + (ph == 1 ? 2 : 3)];
                    const float4* ar = (const float4*)(xin + (size_t)ia * 64) + half * 8;
                    const float4* cr = (const float4*)(xin + (size_t)ic * 64) + half * 8;
                    char* hA = At(0, 0); char* lA = At(0, 1);
                    char* hS = At(1, 0); char* lS = At(1, 1);
#pragma unroll
                    for (int i = 0; i < 8; i++) {
                        float4 a = ar[i], c = cr[i];
                        int kc = half * 32 + i * 4;
                        wr4(hA, lA, n, kc, fabsf(a.x - c.x), fabsf(a.y - c.y),
                            fabsf(a.z - c.z), fabsf(a.w - c.w));
                        wr4(hS, lS, n, kc, a.x + c.x, a.y + c.y, a.z + c.z, a.w + c.w);
                    }
                }
            } else {
                // layer0: feats k map: x 0-10, |a-c| 11-21, a+c 22-32,
                // |b-d| 33-43, b+d 44-54, zero-pad 55-63
                char* hT = At(0, 0); char* lT = At(0, 1);
                if (half == 0) {
                    const float* xr = xin + (size_t)(node0 + n) * 11;
                    const float* A_ = xin + (size_t)sIdx[4 * n + 0] * 11;
                    const float* C_ = xin + (size_t)sIdx[4 * n + 2] * 11;
#pragma unroll
                    for (int ch = 0; ch < 11; ch++) {
                        wr1(hT, lT, n, ch, xr[ch]);
                        float a = A_[ch], c = C_[ch];
                        wr1(hT, lT, n, 11 + ch, fabsf(a - c));
                        wr1(hT, lT, n, 22 + ch, a + c);
                    }
                } else {
                    const float* B_ = xin + (size_t)sIdx[4 * n + 1] * 11;
                    const float* D_ = xin + (size_t)sIdx[4 * n + 3] * 11;
#pragma unroll
                    for (int ch = 0; ch < 11; ch++) {
                        float b = B_[ch], d = D_[ch];
                        wr1(hT, lT, n, 33 + ch, fabsf(b - d));
                        wr1(hT, lT, n, 44 + ch, b + d);
                    }
#pragma unroll
                    for (int k = 55; k < 64; k++) wr1(hT, lT, n, k, 0.f);
                }
            }
        }
        __syncthreads();

        // ---- warp-level HMMA over this phase's K tiles (32x32 warp tile) ----
        const int t4 = lane >> 3;
        for (int t = 0; t < ntile; t++) {
            const u32 ah_b = s2u(At(t, 0)), al_b = s2u(At(t, 1));
            const u32 bh_b = s2u(Bt(t, 0)), bl_b = s2u(Bt(t, 1));
#pragma unroll
            for (int k16 = 0; k16 < 4; k16++) {
                u32 ah[2][4], al[2][4];
#pragma unroll
                for (int rb = 0; rb < 2; rb++) {
                    u32 aoff = swz((u32)((RW + rb * 16 + (lane & 7) + ((t4 & 1) << 3)) * 128
                                         + k16 * 32 + ((t4 >> 1) << 4)));
                    ldmx4(ah[rb], ah_b + aoff);
                    ldmx4(al[rb], al_b + aoff);
                }
                u32 bh[8], bl[8];
#pragma unroll
                for (int pb = 0; pb < 2; pb++) {
                    u32 boff = swz((u32)(((2 * (P0 + pb) + (t4 >> 1)) * 8 + (lane & 7)) * 128
                                         + k16 * 32 + ((t4 & 1) << 4)));
                    ldmx4(bh + 4 * pb, bh_b + boff);
                    ldmx4(bl + 4 * pb, bl_b + boff);
                }
#pragma unroll
                for (int rb = 0; rb < 2; rb++)
#pragma unroll
                    for (int nq = 0; nq < 4; nq++) {
                        float* a_ = acc[rb * 4 + nq];
                        mma16816(a_, ah[rb], bh[2 * nq], bh[2 * nq + 1]);
                        mma16816(a_, al[rb], bh[2 * nq], bh[2 * nq + 1]);
                        mma16816(a_, ah[rb], bl[2 * nq], bl[2 * nq + 1]);
                    }
            }
        }
        __syncthreads();
    }

    // ---- store acc tile into smem C (stride 65), reusing A/B region ----
    float* sC = (float*)(smc + OFF_A);
    {
        int r0 = RW + (lane >> 2);
        int c0 = CW + 2 * (lane & 3);
#pragma unroll
        for (int rb = 0; rb < 2; rb++)
#pragma unroll
            for (int nq = 0; nq < 4; nq++) {
                float* a_ = acc[rb * 4 + nq];
                int rr = r0 + rb * 16;
                int cc = c0 + nq * 8;
                sC[rr * 65 + cc]           = a_[0];
                sC[rr * 65 + cc + 1]       = a_[1];
                sC[(rr + 8) * 65 + cc]     = a_[2];
                sC[(rr + 8) * 65 + cc + 1] = a_[3];
            }
    }
    __syncthreads();

    // ---- bias + LayerNorm + ReLU (one thread per node row) ----
    const float* sBias = (const float*)(smc + OFF_BIAS);
    const float* sG    = (const float*)(smc + OFF_G);
    const float* sB    = (const float*)(smc + OFF_LB);
    if (tid < 128 && (node0 + tid) < E_NODES) {
        const int row = tid;
        float mu = 0.f;
        for (int i = 0; i < 64; i++) mu += sC[row * 65 + i] + sBias[i];
        mu *= (1.f / 64.f);
        float var = 0.f;
        for (int i = 0; i < 64; i++) {
            float d = sC[row * 65 + i] + sBias[i] - mu;
            var += d * d;
        }
        var *= (1.f / 64.f);
        float rs = rsqrtf(var + 1e-5f);
        for (int i = 0; i < 64; i++) {
            float y = (sC[row * 65 + i] + sBias[i] - mu) * rs * sG[i] + sB[i];
            sC[row * 65 + i] = fmaxf(y, 0.f);
        }
    }
    __syncthreads();

    if (!CLS) {
        // residual + coalesced store (2 threads per node, float4)
        if (vOK) {
            const int node = node0 + n;
            float4* orow = (float4*)(out + (size_t)node * 64) + half * 8;
            const float4* xr = RESID ? ((const float4*)(xin + (size_t)node * 64) + half * 8)
                                     : (const float4*)0;
#pragma unroll
            for (int i = 0; i < 8; i++) {
                int c0 = half * 32 + i * 4;
                float4 r;
                r.x = sC[n * 65 + c0 + 0];
                r.y = sC[n * 65 + c0 + 1];
                r.z = sC[n * 65 + c0 + 2];
                r.w = sC[n * 65 + c0 + 3];
                if (RESID) {
                    float4 x4 = xr[i];
                    r.x += x4.x; r.y += x4.y; r.z += x4.z; r.w += x4.w;
                }
                orow[i] = r;
            }
        }
    } else {
        // residual add into smem, then fused classifier head
        if (RESID && vOK) {
            const float4* xr = (const float4*)(xin + (size_t)(node0 + n) * 64) + half * 8;
#pragma unroll
            for (int i = 0; i < 8; i++) {
                float4 x4 = xr[i];
                int c0 = half * 32 + i * 4;
                sC[n * 65 + c0 + 0] += x4.x;
                sC[n * 65 + c0 + 1] += x4.y;
                sC[n * 65 + c0 + 2] += x4.z;
                sC[n * 65 + c0 + 3] += x4.w;
            }
        }
        __syncthreads();
        if (tid < 128 && (node0 + tid) < E_NODES) {
            const int row = tid;
            const u64* zb = (const u64*)(smc + OFF_B1);
            u64 z[16];
#pragma unroll
            for (int j = 0; j < 16; j++) z[j] = zb[j];
            for (int i = 0; i < 64; i++) {
                float vi = sC[row * 65 + i];
                u64 v2 = pk2(vi, vi);
                const u64* wrow = (const u64*)(smc + OFF_C1 + i * 128);
#pragma unroll
                for (int j = 0; j < 16; j++) ffma2(z[j], v2, wrow[j]);
            }
            const float* sC2 = (const float*)(smc + OFF_C2);
            float logit = __ldg(cb2);
#pragma unroll
            for (int j = 0; j < 16; j++) {
                float lo, hi;
                upk2(z[j], lo, hi);
                logit += fmaxf(lo, 0.f) * sC2[2 * j] + fmaxf(hi, 0.f) * sC2[2 * j + 1];
            }
            out[node0 + row] = logit;
        }
    }
}

// ---------------------------------------------------------------------------

extern "C" void kernel_launch(void* const* d_in, const int* in_sizes, int n_in,
                              void* d_out, int out_size)
{
    const float* x      = (const float*)d_in[0];
    const int*   nbr    = (const int*)  d_in[1];
    const float* w0     = (const float*)d_in[2];
    const float* b0     = (const float*)d_in[3];
    const float* w_rest = (const float*)d_in[4];
    const float* b_rest = (const float*)d_in[5];
    const float* ln_g   = (const float*)d_in[6];
    const float* ln_b   = (const float*)d_in[7];
    const float* cw1    = (const float*)d_in[8];
    const float* cb1    = (const float*)d_in[9];
    const float* cw2    = (const float*)d_in[10];
    const float* cb2    = (const float*)d_in[11];
    float* out = (float*)d_out;

    float *bufA, *bufB;
    __nv_bfloat16 *W0p, *WRp;
    cudaGetSymbolAddress((void**)&bufA, g_bufA);
    cudaGetSymbolAddress((void**)&bufB, g_bufB);
    cudaGetSymbolAddress((void**)&W0p, g_W0);
    cudaGetSymbolAddress((void**)&WRp, g_WR);

    const int s11 = smem_sz(11);
    const int s64 = smem_sz(64);

    cudaFuncSetAttribute(mesh_hmma<11, false, false>,
                         cudaFuncAttributeMaxDynamicSharedMemorySize, s11);
    cudaFuncSetAttribute(mesh_hmma<64, true, false>,
                         cudaFuncAttributeMaxDynamicSharedMemorySize, s64);
    cudaFuncSetAttribute(mesh_hmma<64, true, true>,
                         cudaFuncAttributeMaxDynamicSharedMemorySize, s64);

    prep_w<<<240, 256>>>(w0, w_rest);

    dim3 grid((E_NODES + 127) / 128);
    dim3 block(256);

    mesh_hmma<11, false, false><<<grid, block, s11>>>(
        x, nbr, W0p, b0, ln_g, ln_b,
        nullptr, nullptr, nullptr, nullptr, bufA);

    mesh_hmma<64, true, false><<<grid, block, s64>>>(
        bufA, nbr, WRp, b_rest, ln_g + 64, ln_b + 64,
        nullptr, nullptr, nullptr, nullptr, bufB);

    mesh_hmma<64, true, false><<<grid, block, s64>>>(
        bufB, nbr, WRp + 2 * 64 * 320, b_rest + 64, ln_g + 128, ln_b + 128,
        nullptr, nullptr, nullptr, nullptr, bufA);

    mesh_hmma<64, true, true><<<grid, block, s64>>>(
        bufA, nbr, WRp + 4 * 64 * 320, b_rest + 128, ln_g + 192, ln_b + 192,
        cw1, cb1, cw2, cb2, out);
}

// round 7
// speedup vs baseline: 2.0035x; 2.0035x over previous
#include <cuda_runtime.h>
#include <cuda_bf16.h>
#include <cstdint>

typedef unsigned int u32;
typedef unsigned long long u64;

#define E_NODES 1000000

// Scratch activations + pre-split weights (alloc-free rule: __device__ globals)
__device__ float g_bufA[(size_t)E_NODES * 64];
__device__ float g_bufB[(size_t)E_NODES * 64];
__device__ __nv_bfloat16 g_W0[2 * 64 * 64];      // layer0: [term][n][kpad64]
__device__ __nv_bfloat16 g_WR[3 * 2 * 64 * 320]; // layers1-3: [l][term][n][k]

// ---------------------------------------------------------------------------
// helpers
// ---------------------------------------------------------------------------
__device__ __forceinline__ u32 s2u(const void* p) {
    u32 a;
    asm("{.reg .u64 t; cvta.to.shared.u64 t,%1; cvt.u32.u64 %0,t;}" : "=r"(a) : "l"(p));
    return a;
}
__device__ __forceinline__ u32 swz(u32 b) { return b ^ ((b >> 3) & 0x70); }

__device__ __forceinline__ void ldmx4(u32* r, u32 addr) {
    asm volatile("ldmatrix.sync.aligned.m8n8.x4.shared.b16 {%0,%1,%2,%3},[%4];"
                 : "=r"(r[0]), "=r"(r[1]), "=r"(r[2]), "=r"(r[3]) : "r"(addr));
}
__device__ __forceinline__ void mma16816(float* d, const u32* a, u32 b0, u32 b1) {
    asm volatile(
        "mma.sync.aligned.m16n8k16.row.col.f32.bf16.bf16.f32 "
        "{%0,%1,%2,%3},{%4,%5,%6,%7},{%8,%9},{%0,%1,%2,%3};"
        : "+f"(d[0]), "+f"(d[1]), "+f"(d[2]), "+f"(d[3])
        : "r"(a[0]), "r"(a[1]), "r"(a[2]), "r"(a[3]), "r"(b0), "r"(b1));
}

__device__ __forceinline__ u64 pk2(float lo, float hi) {
    u64 r; asm("mov.b64 %0,{%1,%2};" : "=l"(r) : "f"(lo), "f"(hi)); return r;
}
__device__ __forceinline__ void upk2(u64 v, float& lo, float& hi) {
    asm("mov.b64 {%0,%1},%2;" : "=f"(lo), "=f"(hi) : "l"(v));
}
__device__ __forceinline__ void ffma2(u64& d, u64 a, u64 b) {
    asm("fma.rn.f32x2 %0,%1,%2,%0;" : "+l"(d) : "l"(a), "l"(b));
}

__device__ __forceinline__ u32 bits2(__nv_bfloat162 v) {
    u32 u; __builtin_memcpy(&u, &v, 4); return u;
}
// split (a,b) fp32 pair into hi/lo bf16x2 packs
__device__ __forceinline__ void split2(float a, float b, u32& h, u32& l) {
    __nv_bfloat162 hh = __floats2bfloat162_rn(a, b);
    float ra = a - __bfloat162float(hh.x);
    float rb = b - __bfloat162float(hh.y);
    __nv_bfloat162 ll = __floats2bfloat162_rn(ra, rb);
    h = bits2(hh); l = bits2(ll);
}
// write 4 consecutive k-cols of one A row, split hi/lo (layer0 path)
__device__ __forceinline__ void wr4(char* hT, char* lT, int n, int kc,
                                    float v0, float v1, float v2, float v3) {
    u32 h01, l01, h23, l23;
    split2(v0, v1, h01, l01);
    split2(v2, v3, h23, l23);
    u32 off = swz((u32)(n * 128 + kc * 2));
    *(uint2*)(hT + off) = make_uint2(h01, h23);
    *(uint2*)(lT + off) = make_uint2(l01, l23);
}
__device__ __forceinline__ void wr1(char* hT, char* lT, int n, int k, float v) {
    __nv_bfloat16 h = __float2bfloat16_rn(v);
    __nv_bfloat16 l = __float2bfloat16_rn(v - __bfloat162float(h));
    u32 off = swz((u32)(n * 128 + k * 2));
    *(__nv_bfloat16*)(hT + off) = h;
    *(__nv_bfloat16*)(lT + off) = l;
}

// ---------------------------------------------------------------------------
// weight prep: transpose to [n][k], split bf16 hi/lo, zero-pad layer0 K 55->64
// ---------------------------------------------------------------------------
__global__ void prep_w(const float* __restrict__ w0, const float* __restrict__ wr)
{
    int i = blockIdx.x * blockDim.x + threadIdx.x;
    if (i < 64 * 64) {
        int n = i >> 6, k = i & 63;
        float v = (k < 55) ? w0[k * 64 + n] : 0.f;
        __nv_bfloat16 h = __float2bfloat16_rn(v);
        g_W0[(0 * 64 + n) * 64 + k] = h;
        g_W0[(1 * 64 + n) * 64 + k] = __float2bfloat16_rn(v - __bfloat162float(h));
    }
    if (i < 3 * 64 * 320) {
        int l = i / (64 * 320), r = i % (64 * 320);
        int n = r / 320, k = r % 320;
        float v = wr[(size_t)l * 320 * 64 + (size_t)k * 64 + n];
        __nv_bfloat16 h = __float2bfloat16_rn(v);
        g_WR[((size_t)(l * 2 + 0) * 64 + n) * 320 + k] = h;
        g_WR[((size_t)(l * 2 + 1) * 64 + n) * 320 + k] =
            __float2bfloat16_rn(v - __bfloat162float(h));
    }
}

// ===========================================================================
// Layer-0 kernel (C=11) — round-6 proven smem/ldmatrix path
// ===========================================================================
constexpr int OFF_IDX = 0;
constexpr int OFF_BIAS = 2048, OFF_G = 2304, OFF_LB = 2560;
constexpr int OFF_A0 = 2816 + 1024 - (2816 % 1024);   // 3072, 1024-aligned
constexpr int OFF_B0 = OFF_A0 + 2 * 16384;            // A: 1 tile x 2 terms
constexpr int SMEM0 = OFF_B0 + 2 * 8192;              // B: 1 tile x 2 terms

__global__ __launch_bounds__(256, 2)
void mesh_l0(const float* __restrict__ xin, const int* __restrict__ nbr,
             const __nv_bfloat16* __restrict__ Wt,    // [term][64][64]
             const float* __restrict__ bias, const float* __restrict__ lng,
             const float* __restrict__ lnb, float* __restrict__ out)
{
    extern __shared__ char smc[];
    const int tid = threadIdx.x, wid = tid >> 5, lane = tid & 31;
    const int node0 = blockIdx.x * 128;

    char* Ah = smc + OFF_A0;       char* Al = Ah + 16384;
    char* Bh = smc + OFF_B0;       char* Bl = Bh + 8192;

    if (tid < 128) {
        int node = node0 + tid;
        int4 v = (node < E_NODES) ? ((const int4*)nbr)[node] : make_int4(0, 0, 0, 0);
        ((int4*)(smc + OFF_IDX))[tid] = v;
    }
    if (tid >= 128 && tid < 192) {
        int i = tid - 128;
        ((float*)(smc + OFF_BIAS))[i] = bias[i];
        ((float*)(smc + OFF_G))[i]    = lng[i];
        ((float*)(smc + OFF_LB))[i]   = lnb[i];
    }
    // stage B (2 terms x 64 rows x 128B)
    for (int j = tid; j < 1024; j += 256) {
        int term = j >> 9, r = (j >> 3) & 63, c = j & 7;
        const char* src = (const char*)(Wt + (size_t)term * 64 * 64 + (size_t)r * 64) + c * 16;
        char* dst = (term ? Bl : Bh);
        *(uint4*)(dst + swz((u32)(r * 128 + c * 16))) = *(const uint4*)src;
    }
    __syncthreads();

    const int  n    = tid >> 1;
    const int  half = tid & 1;
    const bool vOK  = (node0 + n) < E_NODES;
    const int* sIdx = (const int*)(smc + OFF_IDX);

    // gather + split-convert A (feats k map: x 0-10 |a-c| 11-21 a+c 22-32
    // |b-d| 33-43 b+d 44-54 pad 55-63)
    if (vOK) {
        if (half == 0) {
            const float* xr = xin + (size_t)(node0 + n) * 11;
            const float* A_ = xin + (size_t)sIdx[4 * n + 0] * 11;
            const float* C_ = xin + (size_t)sIdx[4 * n + 2] * 11;
#pragma unroll
            for (int ch = 0; ch < 11; ch++) {
                wr1(Ah, Al, n, ch, xr[ch]);
                float a = A_[ch], c = C_[ch];
                wr1(Ah, Al, n, 11 + ch, fabsf(a - c));
                wr1(Ah, Al, n, 22 + ch, a + c);
            }
        } else {
            const float* B_ = xin + (size_t)sIdx[4 * n + 1] * 11;
            const float* D_ = xin + (size_t)sIdx[4 * n + 3] * 11;
#pragma unroll
            for (int ch = 0; ch < 11; ch++) {
                float b = B_[ch], d = D_[ch];
                wr1(Ah, Al, n, 33 + ch, fabsf(b - d));
                wr1(Ah, Al, n, 44 + ch, b + d);
            }
#pragma unroll
            for (int k = 55; k < 64; k++) wr1(Ah, Al, n, k, 0.f);
        }
    }
    __syncthreads();

    // warp tile 32x32
    const int RW = (wid >> 1) * 32;
    const int P0 = (wid & 1) * 2;
    float acc[8][4];
#pragma unroll
    for (int q = 0; q < 8; q++)
#pragma unroll
        for (int c = 0; c < 4; c++) acc[q][c] = 0.f;

    const int t4 = lane >> 3;
    const u32 ah_b = s2u(Ah), al_b = s2u(Al), bh_b = s2u(Bh), bl_b = s2u(Bl);
#pragma unroll
    for (int k16 = 0; k16 < 4; k16++) {
        u32 ah[2][4], al[2][4];
#pragma unroll
        for (int rb = 0; rb < 2; rb++) {
            u32 aoff = swz((u32)((RW + rb * 16 + (lane & 7) + ((t4 & 1) << 3)) * 128
                                 + k16 * 32 + ((t4 >> 1) << 4)));
            ldmx4(ah[rb], ah_b + aoff);
            ldmx4(al[rb], al_b + aoff);
        }
        u32 bh[8], bl[8];
#pragma unroll
        for (int pb = 0; pb < 2; pb++) {
            u32 boff = swz((u32)(((2 * (P0 + pb) + (t4 >> 1)) * 8 + (lane & 7)) * 128
                                 + k16 * 32 + ((t4 & 1) << 4)));
            ldmx4(bh + 4 * pb, bh_b + boff);
            ldmx4(bl + 4 * pb, bl_b + boff);
        }
#pragma unroll
        for (int rb = 0; rb < 2; rb++)
#pragma unroll
            for (int nq = 0; nq < 4; nq++) {
                float* a_ = acc[rb * 4 + nq];
                mma16816(a_, ah[rb], bh[2 * nq], bh[2 * nq + 1]);
                mma16816(a_, al[rb], bh[2 * nq], bh[2 * nq + 1]);
                mma16816(a_, ah[rb], bl[2 * nq], bl[2 * nq + 1]);
            }
    }
    __syncthreads();

    // C tile -> smem (stride 65), LN, store (no residual layer0)
    float* sC = (float*)(smc + OFF_A0);
    {
        int r0 = RW + (lane >> 2);
        int c0 = (wid & 1) * 32 + 2 * (lane & 3);
#pragma unroll
        for (int rb = 0; rb < 2; rb++)
#pragma unroll
            for (int nq = 0; nq < 4; nq++) {
                float* a_ = acc[rb * 4 + nq];
                int rr = r0 + rb * 16, cc = c0 + nq * 8;
                sC[rr * 65 + cc]           = a_[0];
                sC[rr * 65 + cc + 1]       = a_[1];
                sC[(rr + 8) * 65 + cc]     = a_[2];
                sC[(rr + 8) * 65 + cc + 1] = a_[3];
            }
    }
    __syncthreads();

    const float* sBias = (const float*)(smc + OFF_BIAS);
    const float* sG    = (const float*)(smc + OFF_G);
    const float* sB    = (const float*)(smc + OFF_LB);
    if (tid < 128 && (node0 + tid) < E_NODES) {
        const int row = tid;
        float mu = 0.f;
        for (int i = 0; i < 64; i++) mu += sC[row * 65 + i] + sBias[i];
        mu *= (1.f / 64.f);
        float var = 0.f;
        for (int i = 0; i < 64; i++) {
            float d = sC[row * 65 + i] + sBias[i] - mu;
            var += d * d;
        }
        var *= (1.f / 64.f);
        float rs = rsqrtf(var + 1e-5f);
        for (int i = 0; i < 64; i++) {
            float y = (sC[row * 65 + i] + sBias[i] - mu) * rs * sG[i] + sB[i];
            sC[row * 65 + i] = fmaxf(y, 0.f);
        }
    }
    __syncthreads();

    if (vOK) {
        const int node = node0 + n;
        float4* orow = (float4*)(out + (size_t)node * 64) + half * 8;
#pragma unroll
        for (int i = 0; i < 8; i++) {
            int c0 = half * 32 + i * 4;
            float4 r;
            r.x = sC[n * 65 + c0 + 0];
            r.y = sC[n * 65 + c0 + 1];
            r.z = sC[n * 65 + c0 + 2];
            r.w = sC[n * 65 + c0 + 3];
            orow[i] = r;
        }
    }
}

// ===========================================================================
// 64-ch layers: barrier-free mainloop, A-frags straight from global
// warp = 16 nodes x 64 outputs
// ===========================================================================
constexpr int NOFF_C1 = 0;                    // 8 KB (CLS)
constexpr int NOFF_B1 = 8192, NOFF_C2 = 8320;
constexpr int NOFF_B  = 9216;                 // 10 tiles x 8 KB
constexpr int NSMEM   = NOFF_B + 10 * 8192;   // 91136

template <bool CLS>
__global__ __launch_bounds__(256, 2)
void mesh_fast(const float* __restrict__ xin, const int* __restrict__ nbr,
               const __nv_bfloat16* __restrict__ Wt,   // [term][64][320]
               const float* __restrict__ bias, const float* __restrict__ lng,
               const float* __restrict__ lnb,
               const float* __restrict__ cw1, const float* __restrict__ cb1,
               const float* __restrict__ cw2, const float* __restrict__ cb2,
               float* __restrict__ out)
{
    extern __shared__ char smc[];
    const int tid = threadIdx.x, wid = tid >> 5, lane = tid & 31;
    const int node0 = blockIdx.x * 128;

    // ---- stage B: 5 segments x 2 terms, swizzled [n][k16-chunk] tiles ----
    for (int j = tid; j < 5120; j += 256) {
        int r = j >> 3, c = j & 7;
        int seg = r >> 7, term = (r >> 6) & 1, nrow = r & 63;
        const char* src = (const char*)(Wt + (size_t)term * 64 * 320
                                        + (size_t)nrow * 320 + seg * 64) + c * 16;
        char* dst = smc + NOFF_B + (seg * 2 + term) * 8192;
        *(uint4*)(dst + swz((u32)(nrow * 128 + c * 16))) = *(const uint4*)src;
    }
    if (CLS) {
        for (int i = tid; i < 512; i += 256)
            ((float4*)(smc + NOFF_C1))[i] = ((const float4*)cw1)[i];
        if (tid < 32) {
            ((float*)(smc + NOFF_B1))[tid] = cb1[tid];
            ((float*)(smc + NOFF_C2))[tid] = cw2[tid];
        }
    }
    __syncthreads();   // the ONLY mainloop barrier

    const int q  = lane >> 2;
    const int e2 = (lane & 3) * 2;
    const int t4 = lane >> 3;
    const int r0 = node0 + wid * 16 + q;
    const int r1 = r0 + 8;
    const bool v0 = r0 < E_NODES, v1 = r1 < E_NODES;
    const int rr0 = v0 ? r0 : 0, rr1 = v1 ? r1 : 0;

    float acc[8][4];   // [nq][ {row r c, c+1, row r+8 c, c+1} ]
#pragma unroll
    for (int i = 0; i < 8; i++)
#pragma unroll
        for (int c = 0; c < 4; c++) acc[i][c] = 0.f;

    auto bofs = [&](int pb, int k16) -> u32 {
        return swz((u32)(((2 * pb + (t4 >> 1)) * 8 + (lane & 7)) * 128
                         + k16 * 32 + ((t4 & 1) << 4)));
    };
    auto run_seg = [&](int seg, int k16, const u32* ah, const u32* al) {
        u32 bh[16], bl[16];
        u32 bh_b = s2u(smc + NOFF_B + (seg * 2 + 0) * 8192);
        u32 bl_b = s2u(smc + NOFF_B + (seg * 2 + 1) * 8192);
#pragma unroll
        for (int pb = 0; pb < 4; pb++) {
            ldmx4(bh + 4 * pb, bh_b + bofs(pb, k16));
            ldmx4(bl + 4 * pb, bl_b + bofs(pb, k16));
        }
#pragma unroll
        for (int nq = 0; nq < 8; nq++) {
            mma16816(acc[nq], ah, bh[2 * nq], bh[2 * nq + 1]);
            mma16816(acc[nq], al, bh[2 * nq], bh[2 * nq + 1]);
            mma16816(acc[nq], ah, bl[2 * nq], bl[2 * nq + 1]);
        }
    };

    // ---- phase 0: x (seg 0) ----
    {
        const float* x0 = xin + (size_t)rr0 * 64;
        const float* x1 = xin + (size_t)rr1 * 64;
#pragma unroll
        for (int j = 0; j < 4; j++) {
            int ch = 16 * j + e2;
            float2 p00 = *(const float2*)(x0 + ch), p08 = *(const float2*)(x0 + ch + 8);
            float2 p10 = *(const float2*)(x1 + ch), p18 = *(const float2*)(x1 + ch + 8);
            u32 ah[4], al[4];
            split2(p00.x, p00.y, ah[0], al[0]);
            split2(p10.x, p10.y, ah[1], al[1]);
            split2(p08.x, p08.y, ah[2], al[2]);
            split2(p18.x, p18.y, ah[3], al[3]);
            run_seg(0, j, ah, al);
        }
    }

    // ---- phases 1,2: neighbor pairs (segs 1,2 and 3,4) ----
#pragma unroll
    for (int ph = 0; ph < 2; ph++) {
        const int i0 = ph ? 1 : 0, i1 = ph ? 3 : 2;
        const int sd = ph ? 3 : 1;
        const int ia0 = __ldg(nbr + (size_t)rr0 * 4 + i0);
        const int ic0 = __ldg(nbr + (size_t)rr0 * 4 + i1);
        const int ia1 = __ldg(nbr + (size_t)rr1 * 4 + i0);
        const int ic1 = __ldg(nbr + (size_t)rr1 * 4 + i1);
        const float* A0 = xin + (size_t)ia0 * 64;
        const float* C0 = xin + (size_t)ic0 * 64;
        const float* A1 = xin + (size_t)ia1 * 64;
        const float* C1_ = xin + (size_t)ic1 * 64;
#pragma unroll
        for (int j = 0; j < 4; j++) {
            int ch = 16 * j + e2;
            float2 a00 = *(const float2*)(A0 + ch), a08 = *(const float2*)(A0 + ch + 8);
            float2 a10 = *(const float2*)(A1 + ch), a18 = *(const float2*)(A1 + ch + 8);
            float2 c00 = *(const float2*)(C0 + ch), c08 = *(const float2*)(C0 + ch + 8);
            float2 c10 = *(const float2*)(C1_ + ch), c18 = *(const float2*)(C1_ + ch + 8);
            u32 dh[4], dl[4], sh[4], sl[4];
            split2(fabsf(a00.x - c00.x), fabsf(a00.y - c00.y), dh[0], dl[0]);
            split2(fabsf(a10.x - c10.x), fabsf(a10.y - c10.y), dh[1], dl[1]);
            split2(fabsf(a08.x - c08.x), fabsf(a08.y - c08.y), dh[2], dl[2]);
            split2(fabsf(a18.x - c18.x), fabsf(a18.y - c18.y), dh[3], dl[3]);
            split2(a00.x + c00.x, a00.y + c00.y, sh[0], sl[0]);
            split2(a10.x + c10.x, a10.y + c10.y, sh[1], sl[1]);
            split2(a08.x + c08.x, a08.y + c08.y, sh[2], sl[2]);
            split2(a18.x + c18.x, a18.y + c18.y, sh[3], sl[3]);
            run_seg(sd, j, dh, dl);
            run_seg(sd + 1, j, sh, sl);
        }
    }

    // ---- epilogue: bias + LN + ReLU + residual, all in registers ----
#pragma unroll
    for (int rr = 0; rr < 2; rr++) {
        const bool vv = rr ? v1 : v0;
        const int row = rr ? r1 : r0;
        float t[16];
        float part = 0.f;
#pragma unroll
        for (int nq = 0; nq < 8; nq++) {
            int c = 8 * nq + e2;
            float2 b2 = *(const float2*)(bias + c);
            t[2 * nq]     = acc[nq][2 * rr]     + b2.x;
            t[2 * nq + 1] = acc[nq][2 * rr + 1] + b2.y;
            part += t[2 * nq] + t[2 * nq + 1];
        }
        part += __shfl_xor_sync(0xFFFFFFFFu, part, 1);
        part += __shfl_xor_sync(0xFFFFFFFFu, part, 2);
        float mu = part * (1.f / 64.f);
        float vp = 0.f;
#pragma unroll
        for (int i = 0; i < 16; i++) { float d = t[i] - mu; vp += d * d; }
        vp += __shfl_xor_sync(0xFFFFFFFFu, vp, 1);
        vp += __shfl_xor_sync(0xFFFFFFFFu, vp, 2);
        float rs = rsqrtf(vp * (1.f / 64.f) + 1e-5f);
#pragma unroll
        for (int nq = 0; nq < 8; nq++) {
            int c = 8 * nq + e2;
            float2 g2  = *(const float2*)(lng + c);
            float2 lb2 = *(const float2*)(lnb + c);
            float2 xr  = *(const float2*)(xin + (size_t)(vv ? row : 0) * 64 + c);
            float y0 = fmaxf((t[2 * nq]     - mu) * rs * g2.x + lb2.x, 0.f) + xr.x;
            float y1 = fmaxf((t[2 * nq + 1] - mu) * rs * g2.y + lb2.y, 0.f) + xr.y;
            if (!CLS) {
                if (vv) *(float2*)(out + (size_t)row * 64 + c) = make_float2(y0, y1);
            } else {
                acc[nq][2 * rr]     = y0;
                acc[nq][2 * rr + 1] = y1;
            }
        }
    }

    if (CLS) {
        __syncthreads();   // all warps done reading B before overlay
        float* sC = (float*)(smc + NOFF_B);
        const int ln0 = wid * 16 + q;
#pragma unroll
        for (int rr = 0; rr < 2; rr++)
#pragma unroll
            for (int nq = 0; nq < 8; nq++) {
                int c = 8 * nq + e2;
                sC[(ln0 + 8 * rr) * 65 + c]     = acc[nq][2 * rr];
                sC[(ln0 + 8 * rr) * 65 + c + 1] = acc[nq][2 * rr + 1];
            }
        __syncthreads();
        if (tid < 128 && (node0 + tid) < E_NODES) {
            const int row = tid;
            const u64* zb = (const u64*)(smc + NOFF_B1);
            u64 z[16];
#pragma unroll
            for (int j = 0; j < 16; j++) z[j] = zb[j];
            for (int i = 0; i < 64; i++) {
                float vi = sC[row * 65 + i];
                u64 v2 = pk2(vi, vi);
                const u64* wrow = (const u64*)(smc + NOFF_C1 + i * 128);
#pragma unroll
                for (int j = 0; j < 16; j++) ffma2(z[j], v2, wrow[j]);
            }
            const float* sC2 = (const float*)(smc + NOFF_C2);
            float logit = __ldg(cb2);
#pragma unroll
            for (int j = 0; j < 16; j++) {
                float lo, hi;
                upk2(z[j], lo, hi);
                logit += fmaxf(lo, 0.f) * sC2[2 * j] + fmaxf(hi, 0.f) * sC2[2 * j + 1];
            }
            out[node0 + row] = logit;
        }
    }
}

// ---------------------------------------------------------------------------

extern "C" void kernel_launch(void* const* d_in, const int* in_sizes, int n_in,
                              void* d_out, int out_size)
{
    const float* x      = (const float*)d_in[0];
    const int*   nbr    = (const int*)  d_in[1];
    const float* w0     = (const float*)d_in[2];
    const float* b0     = (const float*)d_in[3];
    const float* w_rest = (const float*)d_in[4];
    const float* b_rest = (const float*)d_in[5];
    const float* ln_g   = (const float*)d_in[6];
    const float* ln_b   = (const float*)d_in[7];
    const float* cw1    = (const float*)d_in[8];
    const float* cb1    = (const float*)d_in[9];
    const float* cw2    = (const float*)d_in[10];
    const float* cb2    = (const float*)d_in[11];
    float* out = (float*)d_out;

    float *bufA, *bufB;
    __nv_bfloat16 *W0p, *WRp;
    cudaGetSymbolAddress((void**)&bufA, g_bufA);
    cudaGetSymbolAddress((void**)&bufB, g_bufB);
    cudaGetSymbolAddress((void**)&W0p, g_W0);
    cudaGetSymbolAddress((void**)&WRp, g_WR);

    cudaFuncSetAttribute(mesh_l0, cudaFuncAttributeMaxDynamicSharedMemorySize, SMEM0);
    cudaFuncSetAttribute(mesh_fast<false>, cudaFuncAttributeMaxDynamicSharedMemorySize, NSMEM);
    cudaFuncSetAttribute(mesh_fast<true>,  cudaFuncAttributeMaxDynamicSharedMemorySize, NSMEM);

    prep_w<<<240, 256>>>(w0, w_rest);

    dim3 grid((E_NODES + 127) / 128);
    dim3 block(256);

    mesh_l0<<<grid, block, SMEM0>>>(x, nbr, W0p, b0, ln_g, ln_b, bufA);

    mesh_fast<false><<<grid, block, NSMEM>>>(
        bufA, nbr, WRp, b_rest, ln_g + 64, ln_b + 64,
        nullptr, nullptr, nullptr, nullptr, bufB);

    mesh_fast<false><<<grid, block, NSMEM>>>(
        bufB, nbr, WRp + 2 * 64 * 320, b_rest + 64, ln_g + 128, ln_b + 128,
        nullptr, nullptr, nullptr, nullptr, bufA);

    mesh_fast<true><<<grid, block, NSMEM>>>(
        bufA, nbr, WRp + 4 * 64 * 320, b_rest + 128, ln_g + 192, ln_b + 192,
        cw1, cb1, cw2, cb2, out);
}

// round 8
// speedup vs baseline: 2.3310x; 1.1634x over previous
#include <cuda_runtime.h>
#include <cuda_bf16.h>
#include <cstdint>

typedef unsigned int u32;
typedef unsigned long long u64;

#define E_NODES 1000000

// Scratch activations + pre-split weights (alloc-free rule: __device__ globals)
__device__ float g_bufA[(size_t)E_NODES * 64];
__device__ float g_bufB[(size_t)E_NODES * 64];
__device__ __nv_bfloat16 g_WR[3 * 2 * 64 * 320];      // [l][term][n][kperm]
__device__ __align__(16) u32 g_B0[2 * 4 * 8 * 32 * 2]; // l0 frag-packed B

// ---------------------------------------------------------------------------
// helpers
// ---------------------------------------------------------------------------
__device__ __forceinline__ u32 s2u(const void* p) {
    u32 a;
    asm("{.reg .u64 t; cvta.to.shared.u64 t,%1; cvt.u32.u64 %0,t;}" : "=r"(a) : "l"(p));
    return a;
}
__device__ __forceinline__ u32 swz(u32 b) { return b ^ ((b >> 3) & 0x70); }

__device__ __forceinline__ void ldmx4(u32* r, u32 addr) {
    asm volatile("ldmatrix.sync.aligned.m8n8.x4.shared.b16 {%0,%1,%2,%3},[%4];"
                 : "=r"(r[0]), "=r"(r[1]), "=r"(r[2]), "=r"(r[3]) : "r"(addr));
}
__device__ __forceinline__ void mma16816(float* d, const u32* a, u32 b0, u32 b1) {
    asm volatile(
        "mma.sync.aligned.m16n8k16.row.col.f32.bf16.bf16.f32 "
        "{%0,%1,%2,%3},{%4,%5,%6,%7},{%8,%9},{%0,%1,%2,%3};"
        : "+f"(d[0]), "+f"(d[1]), "+f"(d[2]), "+f"(d[3])
        : "r"(a[0]), "r"(a[1]), "r"(a[2]), "r"(a[3]), "r"(b0), "r"(b1));
}

__device__ __forceinline__ u64 pk2(float lo, float hi) {
    u64 r; asm("mov.b64 %0,{%1,%2};" : "=l"(r) : "f"(lo), "f"(hi)); return r;
}
__device__ __forceinline__ void upk2(u64 v, float& lo, float& hi) {
    asm("mov.b64 {%0,%1},%2;" : "=f"(lo), "=f"(hi) : "l"(v));
}
__device__ __forceinline__ void ffma2(u64& d, u64 a, u64 b) {
    asm("fma.rn.f32x2 %0,%1,%2,%0;" : "+l"(d) : "l"(a), "l"(b));
}

__device__ __forceinline__ u32 bits2(__nv_bfloat162 v) {
    u32 u; __builtin_memcpy(&u, &v, 4); return u;
}
// split (a,b) fp32 pair into hi/lo bf16x2 packs
__device__ __forceinline__ void split2(float a, float b, u32& h, u32& l) {
    __nv_bfloat162 hh = __floats2bfloat162_rn(a, b);
    float ra = a - __bfloat162float(hh.x);
    float rb = b - __bfloat162float(hh.y);
    __nv_bfloat162 ll = __floats2bfloat162_rn(ra, rb);
    h = bits2(hh); l = bits2(ll);
}

// ---------------------------------------------------------------------------
// weight prep:
//  - mids: transpose to [n][k], split hi/lo, K-PERMUTED within each 16-block
//  - l0:   frag-packed B (logical k, no perm), zero-pad K 55->64
// ---------------------------------------------------------------------------
__global__ void prep_w(const float* __restrict__ w0, const float* __restrict__ wr)
{
    int i = blockIdx.x * blockDim.x + threadIdx.x;
    if (i < 2048) {
        int lane = i & 31, nq = (i >> 5) & 7, j = (i >> 8) & 3, term = i >> 10;
        int g = lane >> 2, t = lane & 3, n = nq * 8 + g;
        int ks[4] = {16 * j + 2 * t, 16 * j + 2 * t + 1,
                     16 * j + 2 * t + 8, 16 * j + 2 * t + 9};
        __nv_bfloat16 b[4];
#pragma unroll
        for (int q = 0; q < 4; q++) {
            int k = ks[q];
            float v = (k < 55) ? w0[k * 64 + n] : 0.f;
            __nv_bfloat16 h = __float2bfloat16_rn(v);
            b[q] = term ? __float2bfloat16_rn(v - __bfloat162float(h)) : h;
        }
        __nv_bfloat162 p01; p01.x = b[0]; p01.y = b[1];
        __nv_bfloat162 p23; p23.x = b[2]; p23.y = b[3];
        g_B0[i * 2]     = bits2(p01);
        g_B0[i * 2 + 1] = bits2(p23);
    }
    if (i < 3 * 64 * 320) {
        int l = i / (64 * 320), r = i % (64 * 320);
        int n = r / 320, k = r % 320;
        float v = wr[(size_t)l * 320 * 64 + (size_t)k * 64 + n];
        int kk = k & 15;
        int kp = (k & ~15) | (2 * (kk >> 2) + (kk & 1) + 8 * ((kk >> 1) & 1));
        __nv_bfloat16 h = __float2bfloat16_rn(v);
        g_WR[((size_t)(l * 2 + 0) * 64 + n) * 320 + kp] = h;
        g_WR[((size_t)(l * 2 + 1) * 64 + n) * 320 + kp] =
            __float2bfloat16_rn(v - __bfloat162float(h));
    }
}

// ===========================================================================
// Layer 0 (C=11): barrier-free, warp-private frag-packed A, prepacked B frags
// 256 threads, warp = 16 nodes, block = 128 nodes
// ===========================================================================
constexpr int L0_B0 = 0;                  // 16 KB prepacked B frags
constexpr int L0_A  = 16384;              // 8 warps x 4 KB (hi 2KB | lo 2KB)
constexpr int SMEM_L0 = L0_A + 8 * 4096;  // 49152

__global__ __launch_bounds__(256)
void mesh_l0(const float* __restrict__ xin, const int* __restrict__ nbr,
             const u32* __restrict__ B0, const float* __restrict__ bias,
             const float* __restrict__ lng, const float* __restrict__ lnb,
             float* __restrict__ out)
{
    extern __shared__ char smc[];
    const int tid = threadIdx.x, wid = tid >> 5, lane = tid & 31;
    const int node0 = blockIdx.x * 128;

    // stage prepacked B frags (16 KB)
    for (int i = tid; i < 1024; i += 256)
        ((uint4*)(smc + L0_B0))[i] = ((const uint4*)B0)[i];
    __syncthreads();

    char* Aw = smc + L0_A + wid * 4096;

    // gather: 2 lanes per node, write frag-packed A (logical k slots)
    const int  w     = lane >> 1;
    const int  half  = lane & 1;
    const int  node  = node0 + wid * 16 + w;
    const bool valid = node < E_NODES;

    auto wrA = [&](int k, float v) {
        __nv_bfloat16 h = __float2bfloat16_rn(v);
        __nv_bfloat16 l = __float2bfloat16_rn(v - __bfloat162float(h));
        int j = k >> 4, kk = k & 15;
        int pair = kk >> 3, t = (kk >> 1) & 3, ii = kk & 1;
        int reg = pair * 2 + (w >> 3);
        u32 off = (u32)(((j * 32 + (w & 7) * 4 + t) << 4) + reg * 4 + ii * 2);
        *(__nv_bfloat16*)(Aw + off)        = h;
        *(__nv_bfloat16*)(Aw + 2048 + off) = l;
    };

    if (valid) {
        int4 nb = ((const int4*)nbr)[node];
        if (half == 0) {
            const float* xr = xin + (size_t)node * 11;
            const float* A_ = xin + (size_t)nb.x * 11;
            const float* C_ = xin + (size_t)nb.z * 11;
#pragma unroll
            for (int ch = 0; ch < 11; ch++) {
                wrA(ch, xr[ch]);
                float a = A_[ch], c = C_[ch];
                wrA(11 + ch, fabsf(a - c));
                wrA(22 + ch, a + c);
            }
        } else {
            const float* B_ = xin + (size_t)nb.y * 11;
            const float* D_ = xin + (size_t)nb.w * 11;
#pragma unroll
            for (int ch = 0; ch < 11; ch++) {
                float b = B_[ch], d = D_[ch];
                wrA(33 + ch, fabsf(b - d));
                wrA(44 + ch, b + d);
            }
#pragma unroll
            for (int k = 55; k < 64; k++) wrA(k, 0.f);
        }
    }
    __syncwarp();

    const int g = lane >> 2, t = lane & 3;
    float acc[8][4];
#pragma unroll
    for (int q = 0; q < 8; q++)
#pragma unroll
        for (int c = 0; c < 4; c++) acc[q][c] = 0.f;

#pragma unroll
    for (int j = 0; j < 4; j++) {
        uint4 avh = *(const uint4*)(Aw + (j * 32 + lane) * 16);
        uint4 avl = *(const uint4*)(Aw + 2048 + (j * 32 + lane) * 16);
        u32 ah[4] = {avh.x, avh.y, avh.z, avh.w};
        u32 al[4] = {avl.x, avl.y, avl.z, avl.w};
#pragma unroll
        for (int nq = 0; nq < 8; nq++) {
            uint2 bh = *(const uint2*)(smc + L0_B0 + (size_t)(((0 * 4 + j) * 8 + nq) * 32 + lane) * 8);
            uint2 bl = *(const uint2*)(smc + L0_B0 + (size_t)(((1 * 4 + j) * 8 + nq) * 32 + lane) * 8);
            mma16816(acc[nq], ah, bh.x, bh.y);
            mma16816(acc[nq], al, bh.x, bh.y);
            mma16816(acc[nq], ah, bl.x, bl.y);
        }
    }

    // epilogue: bias + LN + ReLU (no residual), rows g and g+8
#pragma unroll
    for (int hf = 0; hf < 2; hf++) {
        int row = node0 + wid * 16 + g + 8 * hf;
        bool vv = row < E_NODES;
        float tv[16];
        float part = 0.f;
#pragma unroll
        for (int nq = 0; nq < 8; nq++) {
            int c = 8 * nq + 2 * t;
            float2 b2 = *(const float2*)(bias + c);
            tv[2 * nq]     = acc[nq][2 * hf]     + b2.x;
            tv[2 * nq + 1] = acc[nq][2 * hf + 1] + b2.y;
            part += tv[2 * nq] + tv[2 * nq + 1];
        }
        part += __shfl_xor_sync(0xFFFFFFFFu, part, 1);
        part += __shfl_xor_sync(0xFFFFFFFFu, part, 2);
        float mu = part * (1.f / 64.f);
        float vp = 0.f;
#pragma unroll
        for (int i = 0; i < 16; i++) { float d = tv[i] - mu; vp += d * d; }
        vp += __shfl_xor_sync(0xFFFFFFFFu, vp, 1);
        vp += __shfl_xor_sync(0xFFFFFFFFu, vp, 2);
        float rs = rsqrtf(vp * (1.f / 64.f) + 1e-5f);
#pragma unroll
        for (int nq = 0; nq < 8; nq++) {
            int c = 8 * nq + 2 * t;
            float2 g2  = *(const float2*)(lng + c);
            float2 lb2 = *(const float2*)(lnb + c);
            float y0 = fmaxf((tv[2 * nq]     - mu) * rs * g2.x + lb2.x, 0.f);
            float y1 = fmaxf((tv[2 * nq + 1] - mu) * rs * g2.y + lb2.y, 0.f);
            if (vv) *(float2*)(out + (size_t)row * 64 + c) = make_float2(y0, y1);
        }
    }
}

// ===========================================================================
// 64-ch layers: barrier-free, float4 k-permuted gather -> A frags in regs
// 128 threads, 4 warps, warp = 32 nodes, block = 128 nodes
// ===========================================================================
constexpr int NOFF_C1 = 0;                    // 8 KB (CLS)
constexpr int NOFF_B1 = 8192, NOFF_C2 = 8320;
constexpr int NOFF_B  = 9216;                 // 10 tiles x 8 KB
constexpr int NSMEM   = NOFF_B + 10 * 8192;   // 91136

template <bool CLS>
__global__ __launch_bounds__(128)
void mesh_fast(const float* __restrict__ xin, const int* __restrict__ nbr,
               const __nv_bfloat16* __restrict__ Wt,   // [term][64][320] (k-perm)
               const float* __restrict__ bias, const float* __restrict__ lng,
               const float* __restrict__ lnb,
               const float* __restrict__ cw1, const float* __restrict__ cb1,
               const float* __restrict__ cw2, const float* __restrict__ cb2,
               float* __restrict__ out)
{
    extern __shared__ char smc[];
    const int tid = threadIdx.x, wid = tid >> 5, lane = tid & 31;
    const int node0 = blockIdx.x * 128;

    // ---- stage B: 5 segments x 2 terms, swizzled rows for ldmatrix ----
    for (int j = tid; j < 5120; j += 128) {
        int r = j >> 3, c = j & 7;
        int seg = r >> 7, term = (r >> 6) & 1, nrow = r & 63;
        const char* src = (const char*)(Wt + (size_t)term * 64 * 320
                                        + (size_t)nrow * 320 + seg * 64) + c * 16;
        char* dst = smc + NOFF_B + (seg * 2 + term) * 8192;
        *(uint4*)(dst + swz((u32)(nrow * 128 + c * 16))) = *(const uint4*)src;
    }
    if (CLS) {
        for (int i = tid; i < 512; i += 128)
            ((float4*)(smc + NOFF_C1))[i] = ((const float4*)cw1)[i];
        if (tid < 32) {
            ((float*)(smc + NOFF_B1))[tid] = cb1[tid];
            ((float*)(smc + NOFF_C2))[tid] = cw2[tid];
        }
    }
    __syncthreads();   // the ONLY block barrier in the mainloop

    const int g = lane >> 2, t = lane & 3, t4 = lane >> 3;
    const int base = node0 + wid * 32 + g;
    int  rr[4]; bool vv[4];
#pragma unroll
    for (int rs = 0; rs < 4; rs++) {
        int row = base + 8 * rs;
        vv[rs] = row < E_NODES;
        rr[rs] = vv[rs] ? row : 0;
    }

    float acc[2][8][4];
#pragma unroll
    for (int rb = 0; rb < 2; rb++)
#pragma unroll
        for (int q = 0; q < 8; q++)
#pragma unroll
            for (int c = 0; c < 4; c++) acc[rb][q][c] = 0.f;

    auto bofs = [&](int pb, int k16) -> u32 {
        return swz((u32)(((2 * pb + (t4 >> 1)) * 8 + (lane & 7)) * 128
                         + k16 * 32 + ((t4 & 1) << 4)));
    };
    auto run_seg = [&](int seg, int k16, u32 (&ah)[2][4], u32 (&al)[2][4]) {
        u32 bh[16], bl[16];
        u32 bh_b = s2u(smc + NOFF_B + (seg * 2 + 0) * 8192);
        u32 bl_b = s2u(smc + NOFF_B + (seg * 2 + 1) * 8192);
#pragma unroll
        for (int pb = 0; pb < 4; pb++) {
            ldmx4(bh + 4 * pb, bh_b + bofs(pb, k16));
            ldmx4(bl + 4 * pb, bl_b + bofs(pb, k16));
        }
#pragma unroll
        for (int rb = 0; rb < 2; rb++)
#pragma unroll
            for (int nq = 0; nq < 8; nq++) {
                float* a_ = acc[rb][nq];
                mma16816(a_, ah[rb], bh[2 * nq], bh[2 * nq + 1]);
                mma16816(a_, al[rb], bh[2 * nq], bh[2 * nq + 1]);
                mma16816(a_, ah[rb], bl[2 * nq], bl[2 * nq + 1]);
            }
    };

    // ---- phase 0: x (seg 0) ----
#pragma unroll
    for (int j = 0; j < 4; j++) {
        const int fo = 16 * j + 4 * t;
        float4 v[4];
#pragma unroll
        for (int rs = 0; rs < 4; rs++)
            v[rs] = *(const float4*)(xin + (size_t)rr[rs] * 64 + fo);
        u32 ah[2][4], al[2][4];
#pragma unroll
        for (int rb = 0; rb < 2; rb++) {
            split2(v[2 * rb].x,     v[2 * rb].y,     ah[rb][0], al[rb][0]);
            split2(v[2 * rb + 1].x, v[2 * rb + 1].y, ah[rb][1], al[rb][1]);
            split2(v[2 * rb].z,     v[2 * rb].w,     ah[rb][2], al[rb][2]);
            split2(v[2 * rb + 1].z, v[2 * rb + 1].w, ah[rb][3], al[rb][3]);
        }
        run_seg(0, j, ah, al);
    }

    // ---- phases 1,2: neighbor pairs (segs 1,2 and 3,4) ----
#pragma unroll
    for (int ph = 0; ph < 2; ph++) {
        const int i0 = ph ? 1 : 0, i1 = ph ? 3 : 2;
        const int sd = ph ? 3 : 1;
        int ia[4], ic[4];
#pragma unroll
        for (int rs = 0; rs < 4; rs++) {
            ia[rs] = __ldg(nbr + (size_t)rr[rs] * 4 + i0);
            ic[rs] = __ldg(nbr + (size_t)rr[rs] * 4 + i1);
        }
#pragma unroll
        for (int j = 0; j < 4; j++) {
            const int fo = 16 * j + 4 * t;
            float4 va[4], vc[4];
#pragma unroll
            for (int rs = 0; rs < 4; rs++) {
                va[rs] = *(const float4*)(xin + (size_t)ia[rs] * 64 + fo);
                vc[rs] = *(const float4*)(xin + (size_t)ic[rs] * 64 + fo);
            }
            u32 dh[2][4], dl[2][4], sh[2][4], sl[2][4];
#pragma unroll
            for (int rb = 0; rb < 2; rb++) {
                int q0 = 2 * rb, q1 = 2 * rb + 1;
                split2(fabsf(va[q0].x - vc[q0].x), fabsf(va[q0].y - vc[q0].y), dh[rb][0], dl[rb][0]);
                split2(fabsf(va[q1].x - vc[q1].x), fabsf(va[q1].y - vc[q1].y), dh[rb][1], dl[rb][1]);
                split2(fabsf(va[q0].z - vc[q0].z), fabsf(va[q0].w - vc[q0].w), dh[rb][2], dl[rb][2]);
                split2(fabsf(va[q1].z - vc[q1].z), fabsf(va[q1].w - vc[q1].w), dh[rb][3], dl[rb][3]);
                split2(va[q0].x + vc[q0].x, va[q0].y + vc[q0].y, sh[rb][0], sl[rb][0]);
                split2(va[q1].x + vc[q1].x, va[q1].y + vc[q1].y, sh[rb][1], sl[rb][1]);
                split2(va[q0].z + vc[q0].z, va[q0].w + vc[q0].w, sh[rb][2], sl[rb][2]);
                split2(va[q1].z + vc[q1].z, va[q1].w + vc[q1].w, sh[rb][3], sl[rb][3]);
            }
            run_seg(sd, j, dh, dl);
            run_seg(sd + 1, j, sh, sl);
        }
    }

    // ---- epilogue: bias + LN + ReLU + residual, in registers ----
#pragma unroll
    for (int rs = 0; rs < 4; rs++) {
        const int rb = rs >> 1, hf = rs & 1;
        const int row = base + 8 * rs;
        const bool v_ = vv[rs];
        float tv[16];
        float part = 0.f;
#pragma unroll
        for (int nq = 0; nq < 8; nq++) {
            int c = 8 * nq + 2 * t;
            float2 b2 = *(const float2*)(bias + c);
            tv[2 * nq]     = acc[rb][nq][2 * hf]     + b2.x;
            tv[2 * nq + 1] = acc[rb][nq][2 * hf + 1] + b2.y;
            part += tv[2 * nq] + tv[2 * nq + 1];
        }
        part += __shfl_xor_sync(0xFFFFFFFFu, part, 1);
        part += __shfl_xor_sync(0xFFFFFFFFu, part, 2);
        float mu = part * (1.f / 64.f);
        float vp = 0.f;
#pragma unroll
        for (int i = 0; i < 16; i++) { float d = tv[i] - mu; vp += d * d; }
        vp += __shfl_xor_sync(0xFFFFFFFFu, vp, 1);
        vp += __shfl_xor_sync(0xFFFFFFFFu, vp, 2);
        float rsv = rsqrtf(vp * (1.f / 64.f) + 1e-5f);
#pragma unroll
        for (int nq = 0; nq < 8; nq++) {
            int c = 8 * nq + 2 * t;
            float2 g2  = *(const float2*)(lng + c);
            float2 lb2 = *(const float2*)(lnb + c);
            float2 xr  = *(const float2*)(xin + (size_t)(v_ ? row : 0) * 64 + c);
            float y0 = fmaxf((tv[2 * nq]     - mu) * rsv * g2.x + lb2.x, 0.f) + xr.x;
            float y1 = fmaxf((tv[2 * nq + 1] - mu) * rsv * g2.y + lb2.y, 0.f) + xr.y;
            if (!CLS) {
                if (v_) *(float2*)(out + (size_t)row * 64 + c) = make_float2(y0, y1);
            } else {
                acc[rb][nq][2 * hf]     = y0;
                acc[rb][nq][2 * hf + 1] = y1;
            }
        }
    }

    if (CLS) {
        __syncthreads();   // all warps done reading B before overlay
        float* sC = (float*)(smc + NOFF_B);
#pragma unroll
        for (int rs = 0; rs < 4; rs++) {
            int ln = wid * 32 + g + 8 * rs;
            int rb = rs >> 1, hf = rs & 1;
#pragma unroll
            for (int nq = 0; nq < 8; nq++) {
                int c = 8 * nq + 2 * t;
                sC[ln * 65 + c]     = acc[rb][nq][2 * hf];
                sC[ln * 65 + c + 1] = acc[rb][nq][2 * hf + 1];
            }
        }
        __syncthreads();
        if ((node0 + tid) < E_NODES) {
            const int row = tid;
            const u64* zb = (const u64*)(smc + NOFF_B1);
            u64 z[16];
#pragma unroll
            for (int j = 0; j < 16; j++) z[j] = zb[j];
            for (int i = 0; i < 64; i++) {
                float vi = sC[row * 65 + i];
                u64 v2 = pk2(vi, vi);
                const u64* wrow = (const u64*)(smc + NOFF_C1 + i * 128);
#pragma unroll
                for (int j = 0; j < 16; j++) ffma2(z[j], v2, wrow[j]);
            }
            const float* sC2 = (const float*)(smc + NOFF_C2);
            float logit = __ldg(cb2);
#pragma unroll
            for (int j = 0; j < 16; j++) {
                float lo, hi;
                upk2(z[j], lo, hi);
                logit += fmaxf(lo, 0.f) * sC2[2 * j] + fmaxf(hi, 0.f) * sC2[2 * j + 1];
            }
            out[node0 + row] = logit;
        }
    }
}

// ---------------------------------------------------------------------------

extern "C" void kernel_launch(void* const* d_in, const int* in_sizes, int n_in,
                              void* d_out, int out_size)
{
    const float* x      = (const float*)d_in[0];
    const int*   nbr    = (const int*)  d_in[1];
    const float* w0     = (const float*)d_in[2];
    const float* b0     = (const float*)d_in[3];
    const float* w_rest = (const float*)d_in[4];
    const float* b_rest = (const float*)d_in[5];
    const float* ln_g   = (const float*)d_in[6];
    const float* ln_b   = (const float*)d_in[7];
    const float* cw1    = (const float*)d_in[8];
    const float* cb1    = (const float*)d_in[9];
    const float* cw2    = (const float*)d_in[10];
    const float* cb2    = (const float*)d_in[11];
    float* out = (float*)d_out;

    float *bufA, *bufB;
    __nv_bfloat16 *WRp;
    u32 *B0p;
    cudaGetSymbolAddress((void**)&bufA, g_bufA);
    cudaGetSymbolAddress((void**)&bufB, g_bufB);
    cudaGetSymbolAddress((void**)&WRp, g_WR);
    cudaGetSymbolAddress((void**)&B0p, g_B0);

    cudaFuncSetAttribute(mesh_l0, cudaFuncAttributeMaxDynamicSharedMemorySize, SMEM_L0);
    cudaFuncSetAttribute(mesh_fast<false>, cudaFuncAttributeMaxDynamicSharedMemorySize, NSMEM);
    cudaFuncSetAttribute(mesh_fast<true>,  cudaFuncAttributeMaxDynamicSharedMemorySize, NSMEM);

    prep_w<<<240, 256>>>(w0, w_rest);

    dim3 grid((E_NODES + 127) / 128);

    mesh_l0<<<grid, 256, SMEM_L0>>>(x, nbr, B0p, b0, ln_g, ln_b, bufA);

    mesh_fast<false><<<grid, 128, NSMEM>>>(
        bufA, nbr, WRp, b_rest, ln_g + 64, ln_b + 64,
        nullptr, nullptr, nullptr, nullptr, bufB);

    mesh_fast<false><<<grid, 128, NSMEM>>>(
        bufB, nbr, WRp + 2 * 64 * 320, b_rest + 64, ln_g + 128, ln_b + 128,
        nullptr, nullptr, nullptr, nullptr, bufA);

    mesh_fast<true><<<grid, 128, NSMEM>>>(
        bufA, nbr, WRp + 4 * 64 * 320, b_rest + 128, ln_g + 192, ln_b + 192,
        cw1, cb1, cw2, cb2, out);
}

// round 9
// speedup vs baseline: 2.3940x; 1.0270x over previous
#include <cuda_runtime.h>
#include <cuda_bf16.h>
#include <cstdint>

typedef unsigned int u32;
typedef unsigned long long u64;

#define E_NODES 1000000

// Scratch activations + pre-split weights (alloc-free rule: __device__ globals)
__device__ float g_bufA[(size_t)E_NODES * 64];
__device__ float g_bufB[(size_t)E_NODES * 64];
__device__ __nv_bfloat16 g_WR[3 * 2 * 64 * 320];      // [l][term][n][kperm]
__device__ __align__(16) u32 g_B0[2 * 4 * 8 * 32 * 2]; // l0 frag-packed B

// ---------------------------------------------------------------------------
// helpers
// ---------------------------------------------------------------------------
__device__ __forceinline__ u32 s2u(const void* p) {
    u32 a;
    asm("{.reg .u64 t; cvta.to.shared.u64 t,%1; cvt.u32.u64 %0,t;}" : "=r"(a) : "l"(p));
    return a;
}
__device__ __forceinline__ u32 swz(u32 b) { return b ^ ((b >> 3) & 0x70); }

__device__ __forceinline__ void ldmx4(u32* r, u32 addr) {
    asm volatile("ldmatrix.sync.aligned.m8n8.x4.shared.b16 {%0,%1,%2,%3},[%4];"
                 : "=r"(r[0]), "=r"(r[1]), "=r"(r[2]), "=r"(r[3]) : "r"(addr));
}
__device__ __forceinline__ void mma16816(float* d, const u32* a, u32 b0, u32 b1) {
    asm volatile(
        "mma.sync.aligned.m16n8k16.row.col.f32.bf16.bf16.f32 "
        "{%0,%1,%2,%3},{%4,%5,%6,%7},{%8,%9},{%0,%1,%2,%3};"
        : "+f"(d[0]), "+f"(d[1]), "+f"(d[2]), "+f"(d[3])
        : "r"(a[0]), "r"(a[1]), "r"(a[2]), "r"(a[3]), "r"(b0), "r"(b1));
}

__device__ __forceinline__ u64 pk2(float lo, float hi) {
    u64 r; asm("mov.b64 %0,{%1,%2};" : "=l"(r) : "f"(lo), "f"(hi)); return r;
}
__device__ __forceinline__ void upk2(u64 v, float& lo, float& hi) {
    asm("mov.b64 {%0,%1},%2;" : "=f"(lo), "=f"(hi) : "l"(v));
}
__device__ __forceinline__ void ffma2(u64& d, u64 a, u64 b) {
    asm("fma.rn.f32x2 %0,%1,%2,%0;" : "+l"(d) : "l"(a), "l"(b));
}

__device__ __forceinline__ u32 bits2(__nv_bfloat162 v) {
    u32 u; __builtin_memcpy(&u, &v, 4); return u;
}
// split (a,b) fp32 pair into hi/lo bf16x2 packs
__device__ __forceinline__ void split2(float a, float b, u32& h, u32& l) {
    __nv_bfloat162 hh = __floats2bfloat162_rn(a, b);
    float ra = a - __bfloat162float(hh.x);
    float rb = b - __bfloat162float(hh.y);
    __nv_bfloat162 ll = __floats2bfloat162_rn(ra, rb);
    h = bits2(hh); l = bits2(ll);
}

// ---------------------------------------------------------------------------
// weight prep:
//  - mids: transpose to [n][k], split hi/lo, K-PERMUTED within each 16-block
//  - l0:   frag-packed B (logical k, no perm), zero-pad K 55->64
// ---------------------------------------------------------------------------
__global__ void prep_w(const float* __restrict__ w0, const float* __restrict__ wr)
{
    int i = blockIdx.x * blockDim.x + threadIdx.x;
    if (i < 2048) {
        int lane = i & 31, nq = (i >> 5) & 7, j = (i >> 8) & 3, term = i >> 10;
        int g = lane >> 2, t = lane & 3, n = nq * 8 + g;
        int ks[4] = {16 * j + 2 * t, 16 * j + 2 * t + 1,
                     16 * j + 2 * t + 8, 16 * j + 2 * t + 9};
        __nv_bfloat16 b[4];
#pragma unroll
        for (int q = 0; q < 4; q++) {
            int k = ks[q];
            float v = (k < 55) ? w0[k * 64 + n] : 0.f;
            __nv_bfloat16 h = __float2bfloat16_rn(v);
            b[q] = term ? __float2bfloat16_rn(v - __bfloat162float(h)) : h;
        }
        __nv_bfloat162 p01; p01.x = b[0]; p01.y = b[1];
        __nv_bfloat162 p23; p23.x = b[2]; p23.y = b[3];
        g_B0[i * 2]     = bits2(p01);
        g_B0[i * 2 + 1] = bits2(p23);
    }
    if (i < 3 * 64 * 320) {
        int l = i / (64 * 320), r = i % (64 * 320);
        int n = r / 320, k = r % 320;
        float v = wr[(size_t)l * 320 * 64 + (size_t)k * 64 + n];
        int kk = k & 15;
        int kp = (k & ~15) | (2 * (kk >> 2) + (kk & 1) + 8 * ((kk >> 1) & 1));
        __nv_bfloat16 h = __float2bfloat16_rn(v);
        g_WR[((size_t)(l * 2 + 0) * 64 + n) * 320 + kp] = h;
        g_WR[((size_t)(l * 2 + 1) * 64 + n) * 320 + kp] =
            __float2bfloat16_rn(v - __bfloat162float(h));
    }
}

// ===========================================================================
// Layer 0 (C=11): barrier-free, warp-private frag-packed A, prepacked B frags
// 256 threads, warp = 16 nodes, block = 128 nodes
// ===========================================================================
constexpr int L0_B0 = 0;                  // 16 KB prepacked B frags
constexpr int L0_A  = 16384;              // 8 warps x 4 KB (hi 2KB | lo 2KB)
constexpr int SMEM_L0 = L0_A + 8 * 4096;  // 49152

__global__ __launch_bounds__(256)
void mesh_l0(const float* __restrict__ xin, const int* __restrict__ nbr,
             const u32* __restrict__ B0, const float* __restrict__ bias,
             const float* __restrict__ lng, const float* __restrict__ lnb,
             float* __restrict__ out)
{
    extern __shared__ char smc[];
    const int tid = threadIdx.x, wid = tid >> 5, lane = tid & 31;
    const int node0 = blockIdx.x * 128;

    // stage prepacked B frags (16 KB)
    for (int i = tid; i < 1024; i += 256)
        ((uint4*)(smc + L0_B0))[i] = ((const uint4*)B0)[i];
    __syncthreads();

    char* Aw = smc + L0_A + wid * 4096;

    // gather: 2 lanes per node, write frag-packed A (logical k slots)
    const int  w     = lane >> 1;
    const int  half  = lane & 1;
    const int  node  = node0 + wid * 16 + w;
    const bool valid = node < E_NODES;

    auto wrA = [&](int k, float v) {
        __nv_bfloat16 h = __float2bfloat16_rn(v);
        __nv_bfloat16 l = __float2bfloat16_rn(v - __bfloat162float(h));
        int j = k >> 4, kk = k & 15;
        int pair = kk >> 3, t = (kk >> 1) & 3, ii = kk & 1;
        int reg = pair * 2 + (w >> 3);
        u32 off = (u32)(((j * 32 + (w & 7) * 4 + t) << 4) + reg * 4 + ii * 2);
        *(__nv_bfloat16*)(Aw + off)        = h;
        *(__nv_bfloat16*)(Aw + 2048 + off) = l;
    };

    if (valid) {
        int4 nb = ((const int4*)nbr)[node];
        if (half == 0) {
            const float* xr = xin + (size_t)node * 11;
            const float* A_ = xin + (size_t)nb.x * 11;
            const float* C_ = xin + (size_t)nb.z * 11;
#pragma unroll
            for (int ch = 0; ch < 11; ch++) {
                wrA(ch, xr[ch]);
                float a = A_[ch], c = C_[ch];
                wrA(11 + ch, fabsf(a - c));
                wrA(22 + ch, a + c);
            }
        } else {
            const float* B_ = xin + (size_t)nb.y * 11;
            const float* D_ = xin + (size_t)nb.w * 11;
#pragma unroll
            for (int ch = 0; ch < 11; ch++) {
                float b = B_[ch], d = D_[ch];
                wrA(33 + ch, fabsf(b - d));
                wrA(44 + ch, b + d);
            }
#pragma unroll
            for (int k = 55; k < 64; k++) wrA(k, 0.f);
        }
    }
    __syncwarp();

    const int g = lane >> 2, t = lane & 3;
    float acc[8][4];
#pragma unroll
    for (int q = 0; q < 8; q++)
#pragma unroll
        for (int c = 0; c < 4; c++) acc[q][c] = 0.f;

#pragma unroll
    for (int j = 0; j < 4; j++) {
        uint4 avh = *(const uint4*)(Aw + (j * 32 + lane) * 16);
        uint4 avl = *(const uint4*)(Aw + 2048 + (j * 32 + lane) * 16);
        u32 ah[4] = {avh.x, avh.y, avh.z, avh.w};
        u32 al[4] = {avl.x, avl.y, avl.z, avl.w};
#pragma unroll
        for (int nq = 0; nq < 8; nq++) {
            uint2 bh = *(const uint2*)(smc + L0_B0 + (size_t)(((0 * 4 + j) * 8 + nq) * 32 + lane) * 8);
            uint2 bl = *(const uint2*)(smc + L0_B0 + (size_t)(((1 * 4 + j) * 8 + nq) * 32 + lane) * 8);
            mma16816(acc[nq], ah, bh.x, bh.y);
            mma16816(acc[nq], al, bh.x, bh.y);
            mma16816(acc[nq], ah, bl.x, bl.y);
        }
    }

    // epilogue: bias + LN + ReLU (no residual), rows g and g+8
#pragma unroll
    for (int hf = 0; hf < 2; hf++) {
        int row = node0 + wid * 16 + g + 8 * hf;
        bool vv = row < E_NODES;
        float tv[16];
        float part = 0.f;
#pragma unroll
        for (int nq = 0; nq < 8; nq++) {
            int c = 8 * nq + 2 * t;
            float2 b2 = *(const float2*)(bias + c);
            tv[2 * nq]     = acc[nq][2 * hf]     + b2.x;
            tv[2 * nq + 1] = acc[nq][2 * hf + 1] + b2.y;
            part += tv[2 * nq] + tv[2 * nq + 1];
        }
        part += __shfl_xor_sync(0xFFFFFFFFu, part, 1);
        part += __shfl_xor_sync(0xFFFFFFFFu, part, 2);
        float mu = part * (1.f / 64.f);
        float vp = 0.f;
#pragma unroll
        for (int i = 0; i < 16; i++) { float d = tv[i] - mu; vp += d * d; }
        vp += __shfl_xor_sync(0xFFFFFFFFu, vp, 1);
        vp += __shfl_xor_sync(0xFFFFFFFFu, vp, 2);
        float rs = rsqrtf(vp * (1.f / 64.f) + 1e-5f);
#pragma unroll
        for (int nq = 0; nq < 8; nq++) {
            int c = 8 * nq + 2 * t;
            float2 g2  = *(const float2*)(lng + c);
            float2 lb2 = *(const float2*)(lnb + c);
            float y0 = fmaxf((tv[2 * nq]     - mu) * rs * g2.x + lb2.x, 0.f);
            float y1 = fmaxf((tv[2 * nq + 1] - mu) * rs * g2.y + lb2.y, 0.f);
            if (vv) *(float2*)(out + (size_t)row * 64 + c) = make_float2(y0, y1);
        }
    }
}

// ===========================================================================
// 64-ch layers: barrier-free, float4 k-permuted gather -> A frags in regs
// 256 threads, 8 warps, warp = 16 nodes, block = 128 nodes (occ = 16 warps/SM)
// ===========================================================================
constexpr int NOFF_C1 = 0;                    // 8 KB (CLS)
constexpr int NOFF_B1 = 8192, NOFF_C2 = 8320;
constexpr int NOFF_B  = 9216;                 // 10 tiles x 8 KB
constexpr int NSMEM   = NOFF_B + 10 * 8192;   // 91136

template <bool CLS>
__global__ __launch_bounds__(256, 2)
void mesh_fast(const float* __restrict__ xin, const int* __restrict__ nbr,
               const __nv_bfloat16* __restrict__ Wt,   // [term][64][320] (k-perm)
               const float* __restrict__ bias, const float* __restrict__ lng,
               const float* __restrict__ lnb,
               const float* __restrict__ cw1, const float* __restrict__ cb1,
               const float* __restrict__ cw2, const float* __restrict__ cb2,
               float* __restrict__ out)
{
    extern __shared__ char smc[];
    const int tid = threadIdx.x, wid = tid >> 5, lane = tid & 31;
    const int node0 = blockIdx.x * 128;

    // ---- stage B: 5 segments x 2 terms, swizzled rows for ldmatrix ----
    for (int j = tid; j < 5120; j += 256) {
        int r = j >> 3, c = j & 7;
        int seg = r >> 7, term = (r >> 6) & 1, nrow = r & 63;
        const char* src = (const char*)(Wt + (size_t)term * 64 * 320
                                        + (size_t)nrow * 320 + seg * 64) + c * 16;
        char* dst = smc + NOFF_B + (seg * 2 + term) * 8192;
        *(uint4*)(dst + swz((u32)(nrow * 128 + c * 16))) = *(const uint4*)src;
    }
    if (CLS) {
        for (int i = tid; i < 512; i += 256)
            ((float4*)(smc + NOFF_C1))[i] = ((const float4*)cw1)[i];
        if (tid < 32) {
            ((float*)(smc + NOFF_B1))[tid] = cb1[tid];
            ((float*)(smc + NOFF_C2))[tid] = cw2[tid];
        }
    }
    __syncthreads();   // the ONLY block barrier in the mainloop

    const int g = lane >> 2, t = lane & 3, t4 = lane >> 3;
    const int base = node0 + wid * 16 + g;
    const int row0 = base, row1 = base + 8;
    const bool v0 = row0 < E_NODES, v1 = row1 < E_NODES;
    const int rr0 = v0 ? row0 : 0, rr1 = v1 ? row1 : 0;

    // early neighbor-index fetch (one int4 per row) — off the critical path
    const int4 nb0 = ((const int4*)nbr)[rr0];
    const int4 nb1 = ((const int4*)nbr)[rr1];

    float acc[8][4];
#pragma unroll
    for (int q = 0; q < 8; q++)
#pragma unroll
        for (int c = 0; c < 4; c++) acc[q][c] = 0.f;

    auto bofs = [&](int pb, int k16) -> u32 {
        return swz((u32)(((2 * pb + (t4 >> 1)) * 8 + (lane & 7)) * 128
                         + k16 * 32 + ((t4 & 1) << 4)));
    };
    auto run_seg = [&](int seg, int k16, u32 (&ah)[4], u32 (&al)[4]) {
        u32 bh[16], bl[16];
        u32 bh_b = s2u(smc + NOFF_B + (seg * 2 + 0) * 8192);
        u32 bl_b = s2u(smc + NOFF_B + (seg * 2 + 1) * 8192);
#pragma unroll
        for (int pb = 0; pb < 4; pb++) {
            ldmx4(bh + 4 * pb, bh_b + bofs(pb, k16));
            ldmx4(bl + 4 * pb, bl_b + bofs(pb, k16));
        }
#pragma unroll
        for (int nq = 0; nq < 8; nq++) {
            mma16816(acc[nq], ah, bh[2 * nq], bh[2 * nq + 1]);
            mma16816(acc[nq], al, bh[2 * nq], bh[2 * nq + 1]);
            mma16816(acc[nq], ah, bl[2 * nq], bl[2 * nq + 1]);
        }
    };

    // ---- phase 0: x (seg 0) ----
#pragma unroll
    for (int j = 0; j < 4; j++) {
        const int fo = 16 * j + 4 * t;
        float4 p0 = *(const float4*)(xin + (size_t)rr0 * 64 + fo);
        float4 p1 = *(const float4*)(xin + (size_t)rr1 * 64 + fo);
        u32 ah[4], al[4];
        split2(p0.x, p0.y, ah[0], al[0]);
        split2(p1.x, p1.y, ah[1], al[1]);
        split2(p0.z, p0.w, ah[2], al[2]);
        split2(p1.z, p1.w, ah[3], al[3]);
        run_seg(0, j, ah, al);
    }

    // ---- phases 1,2: neighbor pairs (segs 1,2 and 3,4) ----
#pragma unroll
    for (int ph = 0; ph < 2; ph++) {
        const int sd = ph ? 3 : 1;
        const int ia0 = ph ? nb0.y : nb0.x;
        const int ic0 = ph ? nb0.w : nb0.z;
        const int ia1 = ph ? nb1.y : nb1.x;
        const int ic1 = ph ? nb1.w : nb1.z;
        const float* A0 = xin + (size_t)ia0 * 64;
        const float* C0 = xin + (size_t)ic0 * 64;
        const float* A1 = xin + (size_t)ia1 * 64;
        const float* C1_ = xin + (size_t)ic1 * 64;
#pragma unroll
        for (int j = 0; j < 4; j++) {
            const int fo = 16 * j + 4 * t;
            float4 a0 = *(const float4*)(A0 + fo);
            float4 a1 = *(const float4*)(A1 + fo);
            float4 c0 = *(const float4*)(C0 + fo);
            float4 c1 = *(const float4*)(C1_ + fo);
            u32 dh[4], dl[4], sh[4], sl[4];
            split2(fabsf(a0.x - c0.x), fabsf(a0.y - c0.y), dh[0], dl[0]);
            split2(fabsf(a1.x - c1.x), fabsf(a1.y - c1.y), dh[1], dl[1]);
            split2(fabsf(a0.z - c0.z), fabsf(a0.w - c0.w), dh[2], dl[2]);
            split2(fabsf(a1.z - c1.z), fabsf(a1.w - c1.w), dh[3], dl[3]);
            split2(a0.x + c0.x, a0.y + c0.y, sh[0], sl[0]);
            split2(a1.x + c1.x, a1.y + c1.y, sh[1], sl[1]);
            split2(a0.z + c0.z, a0.w + c0.w, sh[2], sl[2]);
            split2(a1.z + c1.z, a1.w + c1.w, sh[3], sl[3]);
            run_seg(sd, j, dh, dl);
            run_seg(sd + 1, j, sh, sl);
        }
    }

    // ---- epilogue: bias + LN + ReLU + residual, in registers ----
#pragma unroll
    for (int hf = 0; hf < 2; hf++) {
        const int row = hf ? row1 : row0;
        const bool v_ = hf ? v1 : v0;
        float tv[16];
        float part = 0.f;
#pragma unroll
        for (int nq = 0; nq < 8; nq++) {
            int c = 8 * nq + 2 * t;
            float2 b2 = *(const float2*)(bias + c);
            tv[2 * nq]     = acc[nq][2 * hf]     + b2.x;
            tv[2 * nq + 1] = acc[nq][2 * hf + 1] + b2.y;
            part += tv[2 * nq] + tv[2 * nq + 1];
        }
        part += __shfl_xor_sync(0xFFFFFFFFu, part, 1);
        part += __shfl_xor_sync(0xFFFFFFFFu, part, 2);
        float mu = part * (1.f / 64.f);
        float vp = 0.f;
#pragma unroll
        for (int i = 0; i < 16; i++) { float d = tv[i] - mu; vp += d * d; }
        vp += __shfl_xor_sync(0xFFFFFFFFu, vp, 1);
        vp += __shfl_xor_sync(0xFFFFFFFFu, vp, 2);
        float rsv = rsqrtf(vp * (1.f / 64.f) + 1e-5f);
#pragma unroll
        for (int nq = 0; nq < 8; nq++) {
            int c = 8 * nq + 2 * t;
            float2 g2  = *(const float2*)(lng + c);
            float2 lb2 = *(const float2*)(lnb + c);
            float2 xr  = *(const float2*)(xin + (size_t)(v_ ? row : 0) * 64 + c);
            float y0 = fmaxf((tv[2 * nq]     - mu) * rsv * g2.x + lb2.x, 0.f) + xr.x;
            float y1 = fmaxf((tv[2 * nq + 1] - mu) * rsv * g2.y + lb2.y, 0.f) + xr.y;
            if (!CLS) {
                if (v_) *(float2*)(out + (size_t)row * 64 + c) = make_float2(y0, y1);
            } else {
                acc[nq][2 * hf]     = y0;
                acc[nq][2 * hf + 1] = y1;
            }
        }
    }

    if (CLS) {
        __syncthreads();   // all warps done reading B before overlay
        float* sC = (float*)(smc + NOFF_B);
#pragma unroll
        for (int hf = 0; hf < 2; hf++) {
            int ln = wid * 16 + g + 8 * hf;
#pragma unroll
            for (int nq = 0; nq < 8; nq++) {
                int c = 8 * nq + 2 * t;
                sC[ln * 65 + c]     = acc[nq][2 * hf];
                sC[ln * 65 + c + 1] = acc[nq][2 * hf + 1];
            }
        }
        __syncthreads();
        if (tid < 128 && (node0 + tid) < E_NODES) {
            const int row = tid;
            const u64* zb = (const u64*)(smc + NOFF_B1);
            u64 z[16];
#pragma unroll
            for (int j = 0; j < 16; j++) z[j] = zb[j];
            for (int i = 0; i < 64; i++) {
                float vi = sC[row * 65 + i];
                u64 v2 = pk2(vi, vi);
                const u64* wrow = (const u64*)(smc + NOFF_C1 + i * 128);
#pragma unroll
                for (int j = 0; j < 16; j++) ffma2(z[j], v2, wrow[j]);
            }
            const float* sC2 = (const float*)(smc + NOFF_C2);
            float logit = __ldg(cb2);
#pragma unroll
            for (int j = 0; j < 16; j++) {
                float lo, hi;
                upk2(z[j], lo, hi);
                logit += fmaxf(lo, 0.f) * sC2[2 * j] + fmaxf(hi, 0.f) * sC2[2 * j + 1];
            }
            out[node0 + row] = logit;
        }
    }
}

// ---------------------------------------------------------------------------

extern "C" void kernel_launch(void* const* d_in, const int* in_sizes, int n_in,
                              void* d_out, int out_size)
{
    const float* x      = (const float*)d_in[0];
    const int*   nbr    = (const int*)  d_in[1];
    const float* w0     = (const float*)d_in[2];
    const float* b0     = (const float*)d_in[3];
    const float* w_rest = (const float*)d_in[4];
    const float* b_rest = (const float*)d_in[5];
    const float* ln_g   = (const float*)d_in[6];
    const float* ln_b   = (const float*)d_in[7];
    const float* cw1    = (const float*)d_in[8];
    const float* cb1    = (const float*)d_in[9];
    const float* cw2    = (const float*)d_in[10];
    const float* cb2    = (const float*)d_in[11];
    float* out = (float*)d_out;

    float *bufA, *bufB;
    __nv_bfloat16 *WRp;
    u32 *B0p;
    cudaGetSymbolAddress((void**)&bufA, g_bufA);
    cudaGetSymbolAddress((void**)&bufB, g_bufB);
    cudaGetSymbolAddress((void**)&WRp, g_WR);
    cudaGetSymbolAddress((void**)&B0p, g_B0);

    cudaFuncSetAttribute(mesh_l0, cudaFuncAttributeMaxDynamicSharedMemorySize, SMEM_L0);
    cudaFuncSetAttribute(mesh_fast<false>, cudaFuncAttributeMaxDynamicSharedMemorySize, NSMEM);
    cudaFuncSetAttribute(mesh_fast<true>,  cudaFuncAttributeMaxDynamicSharedMemorySize, NSMEM);

    prep_w<<<240, 256>>>(w0, w_rest);

    dim3 grid((E_NODES + 127) / 128);

    mesh_l0<<<grid, 256, SMEM_L0>>>(x, nbr, B0p, b0, ln_g, ln_b, bufA);

    mesh_fast<false><<<grid, 256, NSMEM>>>(
        bufA, nbr, WRp, b_rest, ln_g + 64, ln_b + 64,
        nullptr, nullptr, nullptr, nullptr, bufB);

    mesh_fast<false><<<grid, 256, NSMEM>>>(
        bufB, nbr, WRp + 2 * 64 * 320, b_rest + 64, ln_g + 128, ln_b + 128,
        nullptr, nullptr, nullptr, nullptr, bufA);

    mesh_fast<true><<<grid, 256, NSMEM>>>(
        bufA, nbr, WRp + 4 * 64 * 320, b_rest + 128, ln_g + 192, ln_b + 192,
        cw1, cb1, cw2, cb2, out);
}

// round 10
// speedup vs baseline: 2.6079x; 1.0893x over previous
#include <cuda_runtime.h>
#include <cuda_bf16.h>
#include <cstdint>

typedef unsigned int u32;
typedef unsigned long long u64;

#define E_NODES 1000000

// Scratch activations + pre-split weights (alloc-free rule: __device__ globals)
__device__ float g_bufA[(size_t)E_NODES * 64];
__device__ float g_bufB[(size_t)E_NODES * 64];
__device__ __nv_bfloat16 g_WR[3 * 2 * 64 * 320];      // [l][term][n][kperm]
__device__ __align__(16) u32 g_B0[2 * 4 * 8 * 32 * 2]; // l0 frag-packed B
__device__ __align__(16) __nv_bfloat16 g_C1[2 * 32 * 64]; // cls W1 frag tiles

// ---------------------------------------------------------------------------
// helpers
// ---------------------------------------------------------------------------
__device__ __forceinline__ u32 s2u(const void* p) {
    u32 a;
    asm("{.reg .u64 t; cvta.to.shared.u64 t,%1; cvt.u32.u64 %0,t;}" : "=r"(a) : "l"(p));
    return a;
}
__device__ __forceinline__ u32 swz(u32 b) { return b ^ ((b >> 3) & 0x70); }

__device__ __forceinline__ void ldmx4(u32* r, u32 addr) {
    asm volatile("ldmatrix.sync.aligned.m8n8.x4.shared.b16 {%0,%1,%2,%3},[%4];"
                 : "=r"(r[0]), "=r"(r[1]), "=r"(r[2]), "=r"(r[3]) : "r"(addr));
}
__device__ __forceinline__ void mma16816(float* d, const u32* a, u32 b0, u32 b1) {
    asm volatile(
        "mma.sync.aligned.m16n8k16.row.col.f32.bf16.bf16.f32 "
        "{%0,%1,%2,%3},{%4,%5,%6,%7},{%8,%9},{%0,%1,%2,%3};"
        : "+f"(d[0]), "+f"(d[1]), "+f"(d[2]), "+f"(d[3])
        : "r"(a[0]), "r"(a[1]), "r"(a[2]), "r"(a[3]), "r"(b0), "r"(b1));
}

__device__ __forceinline__ u32 bits2(__nv_bfloat162 v) {
    u32 u; __builtin_memcpy(&u, &v, 4); return u;
}
// split (a,b) fp32 pair into hi/lo bf16x2 packs
__device__ __forceinline__ void split2(float a, float b, u32& h, u32& l) {
    __nv_bfloat162 hh = __floats2bfloat162_rn(a, b);
    float ra = a - __bfloat162float(hh.x);
    float rb = b - __bfloat162float(hh.y);
    __nv_bfloat162 ll = __floats2bfloat162_rn(ra, rb);
    h = bits2(hh); l = bits2(ll);
}

// ---------------------------------------------------------------------------
// weight prep:
//  - mids: transpose to [n][k], split hi/lo, K-PERMUTED within each 16-block
//  - l0:   frag-packed B (logical k, no perm), zero-pad K 55->64
//  - cls:  cw1 -> [term][32 n][64 k] swizzled frag tiles (8 KB)
// ---------------------------------------------------------------------------
__global__ void prep_w(const float* __restrict__ w0, const float* __restrict__ wr,
                       const float* __restrict__ cw1)
{
    int i = blockIdx.x * blockDim.x + threadIdx.x;
    if (i < 2048) {
        int lane = i & 31, nq = (i >> 5) & 7, j = (i >> 8) & 3, term = i >> 10;
        int g = lane >> 2, t = lane & 3, n = nq * 8 + g;
        int ks[4] = {16 * j + 2 * t, 16 * j + 2 * t + 1,
                     16 * j + 2 * t + 8, 16 * j + 2 * t + 9};
        __nv_bfloat16 b[4];
#pragma unroll
        for (int q = 0; q < 4; q++) {
            int k = ks[q];
            float v = (k < 55) ? w0[k * 64 + n] : 0.f;
            __nv_bfloat16 h = __float2bfloat16_rn(v);
            b[q] = term ? __float2bfloat16_rn(v - __bfloat162float(h)) : h;
        }
        __nv_bfloat162 p01; p01.x = b[0]; p01.y = b[1];
        __nv_bfloat162 p23; p23.x = b[2]; p23.y = b[3];
        g_B0[i * 2]     = bits2(p01);
        g_B0[i * 2 + 1] = bits2(p23);
    }
    if (i < 4096) {
        int term = i >> 11, r = i & 2047, n = r >> 6, k = r & 63;
        float v = cw1[k * 32 + n];
        __nv_bfloat16 h = __float2bfloat16_rn(v);
        __nv_bfloat16 o = term ? __float2bfloat16_rn(v - __bfloat162float(h)) : h;
        *(__nv_bfloat16*)((char*)g_C1 + term * 4096 + swz((u32)(n * 128 + k * 2))) = o;
    }
    if (i < 3 * 64 * 320) {
        int l = i / (64 * 320), r = i % (64 * 320);
        int n = r / 320, k = r % 320;
        float v = wr[(size_t)l * 320 * 64 + (size_t)k * 64 + n];
        int kk = k & 15;
        int kp = (k & ~15) | (2 * (kk >> 2) + (kk & 1) + 8 * ((kk >> 1) & 1));
        __nv_bfloat16 h = __float2bfloat16_rn(v);
        g_WR[((size_t)(l * 2 + 0) * 64 + n) * 320 + kp] = h;
        g_WR[((size_t)(l * 2 + 1) * 64 + n) * 320 + kp] =
            __float2bfloat16_rn(v - __bfloat162float(h));
    }
}

// ===========================================================================
// Layer 0 (C=11): barrier-free, warp-private frag-packed A, prepacked B frags
// 256 threads, warp = 16 nodes, block = 128 nodes
// ===========================================================================
constexpr int L0_B0 = 0;                  // 16 KB prepacked B frags
constexpr int L0_A  = 16384;              // 8 warps x 4 KB (hi 2KB | lo 2KB)
constexpr int SMEM_L0 = L0_A + 8 * 4096;  // 49152

__global__ __launch_bounds__(256)
void mesh_l0(const float* __restrict__ xin, const int* __restrict__ nbr,
             const u32* __restrict__ B0, const float* __restrict__ bias,
             const float* __restrict__ lng, const float* __restrict__ lnb,
             float* __restrict__ out)
{
    extern __shared__ char smc[];
    const int tid = threadIdx.x, wid = tid >> 5, lane = tid & 31;
    const int node0 = blockIdx.x * 128;

    // stage prepacked B frags (16 KB)
    for (int i = tid; i < 1024; i += 256)
        ((uint4*)(smc + L0_B0))[i] = ((const uint4*)B0)[i];
    __syncthreads();

    char* Aw = smc + L0_A + wid * 4096;

    // gather: 2 lanes per node, write frag-packed A (logical k slots)
    const int  w     = lane >> 1;
    const int  half  = lane & 1;
    const int  node  = node0 + wid * 16 + w;
    const bool valid = node < E_NODES;

    auto wrA = [&](int k, float v) {
        __nv_bfloat16 h = __float2bfloat16_rn(v);
        __nv_bfloat16 l = __float2bfloat16_rn(v - __bfloat162float(h));
        int j = k >> 4, kk = k & 15;
        int pair = kk >> 3, t = (kk >> 1) & 3, ii = kk & 1;
        int reg = pair * 2 + (w >> 3);
        u32 off = (u32)(((j * 32 + (w & 7) * 4 + t) << 4) + reg * 4 + ii * 2);
        *(__nv_bfloat16*)(Aw + off)        = h;
        *(__nv_bfloat16*)(Aw + 2048 + off) = l;
    };

    if (valid) {
        int4 nb = ((const int4*)nbr)[node];
        if (half == 0) {
            const float* xr = xin + (size_t)node * 11;
            const float* A_ = xin + (size_t)nb.x * 11;
            const float* C_ = xin + (size_t)nb.z * 11;
#pragma unroll
            for (int ch = 0; ch < 11; ch++) {
                wrA(ch, xr[ch]);
                float a = A_[ch], c = C_[ch];
                wrA(11 + ch, fabsf(a - c));
                wrA(22 + ch, a + c);
            }
        } else {
            const float* B_ = xin + (size_t)nb.y * 11;
            const float* D_ = xin + (size_t)nb.w * 11;
#pragma unroll
            for (int ch = 0; ch < 11; ch++) {
                float b = B_[ch], d = D_[ch];
                wrA(33 + ch, fabsf(b - d));
                wrA(44 + ch, b + d);
            }
#pragma unroll
            for (int k = 55; k < 64; k++) wrA(k, 0.f);
        }
    }
    __syncwarp();

    const int g = lane >> 2, t = lane & 3;
    float acc[8][4];
#pragma unroll
    for (int q = 0; q < 8; q++)
#pragma unroll
        for (int c = 0; c < 4; c++) acc[q][c] = 0.f;

#pragma unroll
    for (int j = 0; j < 4; j++) {
        uint4 avh = *(const uint4*)(Aw + (j * 32 + lane) * 16);
        uint4 avl = *(const uint4*)(Aw + 2048 + (j * 32 + lane) * 16);
        u32 ah[4] = {avh.x, avh.y, avh.z, avh.w};
        u32 al[4] = {avl.x, avl.y, avl.z, avl.w};
#pragma unroll
        for (int nq = 0; nq < 8; nq++) {
            uint2 bh = *(const uint2*)(smc + L0_B0 + (size_t)(((0 * 4 + j) * 8 + nq) * 32 + lane) * 8);
            uint2 bl = *(const uint2*)(smc + L0_B0 + (size_t)(((1 * 4 + j) * 8 + nq) * 32 + lane) * 8);
            mma16816(acc[nq], ah, bh.x, bh.y);
            mma16816(acc[nq], al, bh.x, bh.y);
            mma16816(acc[nq], ah, bl.x, bl.y);
        }
    }

    // epilogue: bias + LN + ReLU (no residual), rows g and g+8
#pragma unroll
    for (int hf = 0; hf < 2; hf++) {
        int row = node0 + wid * 16 + g + 8 * hf;
        bool vv = row < E_NODES;
        float tv[16];
        float part = 0.f;
#pragma unroll
        for (int nq = 0; nq < 8; nq++) {
            int c = 8 * nq + 2 * t;
            float2 b2 = *(const float2*)(bias + c);
            tv[2 * nq]     = acc[nq][2 * hf]     + b2.x;
            tv[2 * nq + 1] = acc[nq][2 * hf + 1] + b2.y;
            part += tv[2 * nq] + tv[2 * nq + 1];
        }
        part += __shfl_xor_sync(0xFFFFFFFFu, part, 1);
        part += __shfl_xor_sync(0xFFFFFFFFu, part, 2);
        float mu = part * (1.f / 64.f);
        float vp = 0.f;
#pragma unroll
        for (int i = 0; i < 16; i++) { float d = tv[i] - mu; vp += d * d; }
        vp += __shfl_xor_sync(0xFFFFFFFFu, vp, 1);
        vp += __shfl_xor_sync(0xFFFFFFFFu, vp, 2);
        float rs = rsqrtf(vp * (1.f / 64.f) + 1e-5f);
#pragma unroll
        for (int nq = 0; nq < 8; nq++) {
            int c = 8 * nq + 2 * t;
            float2 g2  = *(const float2*)(lng + c);
            float2 lb2 = *(const float2*)(lnb + c);
            float y0 = fmaxf((tv[2 * nq]     - mu) * rs * g2.x + lb2.x, 0.f);
            float y1 = fmaxf((tv[2 * nq + 1] - mu) * rs * g2.y + lb2.y, 0.f);
            if (vv) *(float2*)(out + (size_t)row * 64 + c) = make_float2(y0, y1);
        }
    }
}

// ===========================================================================
// 64-ch layers: barrier-free, float4 k-permuted gather -> A frags in regs
// 256 threads, 8 warps, warp = 16 nodes, block = 128 nodes
// CLS: head GEMM (y@cw1) runs on HMMA straight from acc fragments
// ===========================================================================
constexpr int NOFF_B  = 9216;                 // 10 tiles x 8 KB
constexpr int NSMEM   = NOFF_B + 10 * 8192;   // 91136 (C1 frag tiles live at 0)

template <bool CLS>
__global__ __launch_bounds__(256, 2)
void mesh_fast(const float* __restrict__ xin, const int* __restrict__ nbr,
               const __nv_bfloat16* __restrict__ Wt,   // [term][64][320] (k-perm)
               const float* __restrict__ bias, const float* __restrict__ lng,
               const float* __restrict__ lnb,
               const __nv_bfloat16* __restrict__ c1t,  // cls frag tiles (8 KB)
               const float* __restrict__ cb1,
               const float* __restrict__ cw2, const float* __restrict__ cb2,
               float* __restrict__ out)
{
    extern __shared__ char smc[];
    const int tid = threadIdx.x, wid = tid >> 5, lane = tid & 31;
    const int node0 = blockIdx.x * 128;

    // ---- stage B: 5 segments x 2 terms, swizzled rows for ldmatrix ----
    for (int j = tid; j < 5120; j += 256) {
        int r = j >> 3, c = j & 7;
        int seg = r >> 7, term = (r >> 6) & 1, nrow = r & 63;
        const char* src = (const char*)(Wt + (size_t)term * 64 * 320
                                        + (size_t)nrow * 320 + seg * 64) + c * 16;
        char* dst = smc + NOFF_B + (seg * 2 + term) * 8192;
        *(uint4*)(dst + swz((u32)(nrow * 128 + c * 16))) = *(const uint4*)src;
    }
    if (CLS) {
        for (int i = tid; i < 512; i += 256)
            ((uint4*)smc)[i] = ((const uint4*)c1t)[i];
    }
    __syncthreads();   // the ONLY block barrier

    const int g = lane >> 2, t = lane & 3, t4 = lane >> 3;
    const int base = node0 + wid * 16 + g;
    const int row0 = base, row1 = base + 8;
    const bool v0 = row0 < E_NODES, v1 = row1 < E_NODES;
    const int rr0 = v0 ? row0 : 0, rr1 = v1 ? row1 : 0;

    // early neighbor-index fetch (one int4 per row) — off the critical path
    const int4 nb0 = ((const int4*)nbr)[rr0];
    const int4 nb1 = ((const int4*)nbr)[rr1];

    float acc[8][4];
#pragma unroll
    for (int q = 0; q < 8; q++)
#pragma unroll
        for (int c = 0; c < 4; c++) acc[q][c] = 0.f;

    auto bofs = [&](int pb, int k16) -> u32 {
        return swz((u32)(((2 * pb + (t4 >> 1)) * 8 + (lane & 7)) * 128
                         + k16 * 32 + ((t4 & 1) << 4)));
    };
    auto run_seg = [&](int seg, int k16, u32 (&ah)[4], u32 (&al)[4]) {
        u32 bh[16], bl[16];
        u32 bh_b = s2u(smc + NOFF_B + (seg * 2 + 0) * 8192);
        u32 bl_b = s2u(smc + NOFF_B + (seg * 2 + 1) * 8192);
#pragma unroll
        for (int pb = 0; pb < 4; pb++) {
            ldmx4(bh + 4 * pb, bh_b + bofs(pb, k16));
            ldmx4(bl + 4 * pb, bl_b + bofs(pb, k16));
        }
#pragma unroll
        for (int nq = 0; nq < 8; nq++) {
            mma16816(acc[nq], ah, bh[2 * nq], bh[2 * nq + 1]);
            mma16816(acc[nq], al, bh[2 * nq], bh[2 * nq + 1]);
            mma16816(acc[nq], ah, bl[2 * nq], bl[2 * nq + 1]);
        }
    };

    // ---- phase 0: x (seg 0) ----
#pragma unroll
    for (int j = 0; j < 4; j++) {
        const int fo = 16 * j + 4 * t;
        float4 p0 = *(const float4*)(xin + (size_t)rr0 * 64 + fo);
        float4 p1 = *(const float4*)(xin + (size_t)rr1 * 64 + fo);
        u32 ah[4], al[4];
        split2(p0.x, p0.y, ah[0], al[0]);
        split2(p1.x, p1.y, ah[1], al[1]);
        split2(p0.z, p0.w, ah[2], al[2]);
        split2(p1.z, p1.w, ah[3], al[3]);
        run_seg(0, j, ah, al);
    }

    // ---- phases 1,2: neighbor pairs (segs 1,2 and 3,4) ----
#pragma unroll
    for (int ph = 0; ph < 2; ph++) {
        const int sd = ph ? 3 : 1;
        const int ia0 = ph ? nb0.y : nb0.x;
        const int ic0 = ph ? nb0.w : nb0.z;
        const int ia1 = ph ? nb1.y : nb1.x;
        const int ic1 = ph ? nb1.w : nb1.z;
        const float* A0 = xin + (size_t)ia0 * 64;
        const float* C0 = xin + (size_t)ic0 * 64;
        const float* A1 = xin + (size_t)ia1 * 64;
        const float* C1_ = xin + (size_t)ic1 * 64;
#pragma unroll
        for (int j = 0; j < 4; j++) {
            const int fo = 16 * j + 4 * t;
            float4 a0 = *(const float4*)(A0 + fo);
            float4 a1 = *(const float4*)(A1 + fo);
            float4 c0 = *(const float4*)(C0 + fo);
            float4 c1 = *(const float4*)(C1_ + fo);
            u32 dh[4], dl[4], sh[4], sl[4];
            split2(fabsf(a0.x - c0.x), fabsf(a0.y - c0.y), dh[0], dl[0]);
            split2(fabsf(a1.x - c1.x), fabsf(a1.y - c1.y), dh[1], dl[1]);
            split2(fabsf(a0.z - c0.z), fabsf(a0.w - c0.w), dh[2], dl[2]);
            split2(fabsf(a1.z - c1.z), fabsf(a1.w - c1.w), dh[3], dl[3]);
            split2(a0.x + c0.x, a0.y + c0.y, sh[0], sl[0]);
            split2(a1.x + c1.x, a1.y + c1.y, sh[1], sl[1]);
            split2(a0.z + c0.z, a0.w + c0.w, sh[2], sl[2]);
            split2(a1.z + c1.z, a1.w + c1.w, sh[3], sl[3]);
            run_seg(sd, j, dh, dl);
            run_seg(sd + 1, j, sh, sl);
        }
    }

    // ---- epilogue: bias + LN + ReLU + residual, in registers ----
#pragma unroll
    for (int hf = 0; hf < 2; hf++) {
        const int row = hf ? row1 : row0;
        const bool v_ = hf ? v1 : v0;
        float tv[16];
        float part = 0.f;
#pragma unroll
        for (int nq = 0; nq < 8; nq++) {
            int c = 8 * nq + 2 * t;
            float2 b2 = *(const float2*)(bias + c);
            tv[2 * nq]     = acc[nq][2 * hf]     + b2.x;
            tv[2 * nq + 1] = acc[nq][2 * hf + 1] + b2.y;
            part += tv[2 * nq] + tv[2 * nq + 1];
        }
        part += __shfl_xor_sync(0xFFFFFFFFu, part, 1);
        part += __shfl_xor_sync(0xFFFFFFFFu, part, 2);
        float mu = part * (1.f / 64.f);
        float vp = 0.f;
#pragma unroll
        for (int i = 0; i < 16; i++) { float d = tv[i] - mu; vp += d * d; }
        vp += __shfl_xor_sync(0xFFFFFFFFu, vp, 1);
        vp += __shfl_xor_sync(0xFFFFFFFFu, vp, 2);
        float rsv = rsqrtf(vp * (1.f / 64.f) + 1e-5f);
#pragma unroll
        for (int nq = 0; nq < 8; nq++) {
            int c = 8 * nq + 2 * t;
            float2 g2  = *(const float2*)(lng + c);
            float2 lb2 = *(const float2*)(lnb + c);
            float2 xr  = *(const float2*)(xin + (size_t)(v_ ? row : 0) * 64 + c);
            float y0 = fmaxf((tv[2 * nq]     - mu) * rsv * g2.x + lb2.x, 0.f) + xr.x;
            float y1 = fmaxf((tv[2 * nq + 1] - mu) * rsv * g2.y + lb2.y, 0.f) + xr.y;
            if (!CLS) {
                if (v_) *(float2*)(out + (size_t)row * 64 + c) = make_float2(y0, y1);
            } else {
                acc[nq][2 * hf]     = y0;
                acc[nq][2 * hf + 1] = y1;
            }
        }
    }

    if (CLS) {
        // ---- head GEMM z = y@cw1 + cb1 on HMMA, A-frags direct from acc ----
        float zacc[4][4];
#pragma unroll
        for (int nq = 0; nq < 4; nq++) {
            float b0 = __ldg(cb1 + 8 * nq + 2 * t);
            float b1 = __ldg(cb1 + 8 * nq + 2 * t + 1);
            zacc[nq][0] = b0; zacc[nq][1] = b1; zacc[nq][2] = b0; zacc[nq][3] = b1;
        }
        const u32 c1h = s2u(smc), c1l = s2u(smc + 4096);
#pragma unroll
        for (int j = 0; j < 4; j++) {
            u32 ah[4], al[4];
            split2(acc[2 * j][0],     acc[2 * j][1],     ah[0], al[0]);
            split2(acc[2 * j][2],     acc[2 * j][3],     ah[1], al[1]);
            split2(acc[2 * j + 1][0], acc[2 * j + 1][1], ah[2], al[2]);
            split2(acc[2 * j + 1][2], acc[2 * j + 1][3], ah[3], al[3]);
            u32 bh[8], bl[8];
#pragma unroll
            for (int pb = 0; pb < 2; pb++) {
                ldmx4(bh + 4 * pb, c1h + bofs(pb, j));
                ldmx4(bl + 4 * pb, c1l + bofs(pb, j));
            }
#pragma unroll
            for (int nq = 0; nq < 4; nq++) {
                mma16816(zacc[nq], ah, bh[2 * nq], bh[2 * nq + 1]);
                mma16816(zacc[nq], al, bh[2 * nq], bh[2 * nq + 1]);
                mma16816(zacc[nq], ah, bl[2 * nq], bl[2 * nq + 1]);
            }
        }
        // ---- logit = relu(z)@cw2 + cb2, quad shuffle reduce ----
        float p0 = 0.f, p1 = 0.f;
#pragma unroll
        for (int nq = 0; nq < 4; nq++) {
            float w0 = __ldg(cw2 + 8 * nq + 2 * t);
            float w1 = __ldg(cw2 + 8 * nq + 2 * t + 1);
            p0 += fmaxf(zacc[nq][0], 0.f) * w0 + fmaxf(zacc[nq][1], 0.f) * w1;
            p1 += fmaxf(zacc[nq][2], 0.f) * w0 + fmaxf(zacc[nq][3], 0.f) * w1;
        }
        p0 += __shfl_xor_sync(0xFFFFFFFFu, p0, 1);
        p0 += __shfl_xor_sync(0xFFFFFFFFu, p0, 2);
        p1 += __shfl_xor_sync(0xFFFFFFFFu, p1, 1);
        p1 += __shfl_xor_sync(0xFFFFFFFFu, p1, 2);
        if (t == 0) {
            float c2 = __ldg(cb2);
            if (v0) out[row0] = p0 + c2;
            if (v1) out[row1] = p1 + c2;
        }
    }
}

// ---------------------------------------------------------------------------

extern "C" void kernel_launch(void* const* d_in, const int* in_sizes, int n_in,
                              void* d_out, int out_size)
{
    const float* x      = (const float*)d_in[0];
    const int*   nbr    = (const int*)  d_in[1];
    const float* w0     = (const float*)d_in[2];
    const float* b0     = (const float*)d_in[3];
    const float* w_rest = (const float*)d_in[4];
    const float* b_rest = (const float*)d_in[5];
    const float* ln_g   = (const float*)d_in[6];
    const float* ln_b   = (const float*)d_in[7];
    const float* cw1    = (const float*)d_in[8];
    const float* cb1    = (const float*)d_in[9];
    const float* cw2    = (const float*)d_in[10];
    const float* cb2    = (const float*)d_in[11];
    float* out = (float*)d_out;

    float *bufA, *bufB;
    __nv_bfloat16 *WRp, *C1p;
    u32 *B0p;
    cudaGetSymbolAddress((void**)&bufA, g_bufA);
    cudaGetSymbolAddress((void**)&bufB, g_bufB);
    cudaGetSymbolAddress((void**)&WRp, g_WR);
    cudaGetSymbolAddress((void**)&B0p, g_B0);
    cudaGetSymbolAddress((void**)&C1p, g_C1);

    cudaFuncSetAttribute(mesh_l0, cudaFuncAttributeMaxDynamicSharedMemorySize, SMEM_L0);
    cudaFuncSetAttribute(mesh_fast<false>, cudaFuncAttributeMaxDynamicSharedMemorySize, NSMEM);
    cudaFuncSetAttribute(mesh_fast<true>,  cudaFuncAttributeMaxDynamicSharedMemorySize, NSMEM);

    prep_w<<<240, 256>>>(w0, w_rest, cw1);

    dim3 grid((E_NODES + 127) / 128);

    mesh_l0<<<grid, 256, SMEM_L0>>>(x, nbr, B0p, b0, ln_g, ln_b, bufA);

    mesh_fast<false><<<grid, 256, NSMEM>>>(
        bufA, nbr, WRp, b_rest, ln_g + 64, ln_b + 64,
        nullptr, nullptr, nullptr, nullptr, bufB);

    mesh_fast<false><<<grid, 256, NSMEM>>>(
        bufB, nbr, WRp + 2 * 64 * 320, b_rest + 64, ln_g + 128, ln_b + 128,
        nullptr, nullptr, nullptr, nullptr, bufA);

    mesh_fast<true><<<grid, 256, NSMEM>>>(
        bufA, nbr, WRp + 4 * 64 * 320, b_rest + 128, ln_g + 192, ln_b + 192,
        C1p, cb1, cw2, cb2, out);
}

// round 11
// speedup vs baseline: 2.9736x; 1.1403x over previous
#include <cuda_runtime.h>
#include <cuda_bf16.h>
#include <cstdint>

typedef unsigned int u32;
typedef unsigned long long u64;

#define E_NODES 1000000
#define NTILES ((E_NODES + 127) / 128)
#define PGRID 304

// Scratch activations + pre-split weights (alloc-free rule: __device__ globals)
__device__ float g_bufA[(size_t)E_NODES * 64];
__device__ float g_bufB[(size_t)E_NODES * 64];
__device__ __nv_bfloat16 g_WR[3 * 2 * 64 * 320];      // [l][term][n][kperm]
__device__ __align__(16) u32 g_B0[2 * 4 * 8 * 32 * 2]; // l0 frag-packed B
__device__ __align__(16) __nv_bfloat16 g_C1[2 * 32 * 64]; // cls W1 frag tiles

// ---------------------------------------------------------------------------
// helpers
// ---------------------------------------------------------------------------
__device__ __forceinline__ u32 s2u(const void* p) {
    u32 a;
    asm("{.reg .u64 t; cvta.to.shared.u64 t,%1; cvt.u32.u64 %0,t;}" : "=r"(a) : "l"(p));
    return a;
}
__device__ __forceinline__ u32 swz(u32 b) { return b ^ ((b >> 3) & 0x70); }

__device__ __forceinline__ void ldmx4(u32* r, u32 addr) {
    asm volatile("ldmatrix.sync.aligned.m8n8.x4.shared.b16 {%0,%1,%2,%3},[%4];"
                 : "=r"(r[0]), "=r"(r[1]), "=r"(r[2]), "=r"(r[3]) : "r"(addr));
}
__device__ __forceinline__ void mma16816(float* d, const u32* a, u32 b0, u32 b1) {
    asm volatile(
        "mma.sync.aligned.m16n8k16.row.col.f32.bf16.bf16.f32 "
        "{%0,%1,%2,%3},{%4,%5,%6,%7},{%8,%9},{%0,%1,%2,%3};"
        : "+f"(d[0]), "+f"(d[1]), "+f"(d[2]), "+f"(d[3])
        : "r"(a[0]), "r"(a[1]), "r"(a[2]), "r"(a[3]), "r"(b0), "r"(b1));
}

__device__ __forceinline__ u32 bits2(__nv_bfloat162 v) {
    u32 u; __builtin_memcpy(&u, &v, 4); return u;
}
// split (a,b) fp32 pair into hi/lo bf16x2 packs
__device__ __forceinline__ void split2(float a, float b, u32& h, u32& l) {
    __nv_bfloat162 hh = __floats2bfloat162_rn(a, b);
    float ra = a - __bfloat162float(hh.x);
    float rb = b - __bfloat162float(hh.y);
    __nv_bfloat162 ll = __floats2bfloat162_rn(ra, rb);
    h = bits2(hh); l = bits2(ll);
}

// ---------------------------------------------------------------------------
// weight prep:
//  - mids: transpose to [n][k], split hi/lo, K-PERMUTED within each 16-block
//  - l0:   frag-packed B (logical k, no perm), zero-pad K 55->64
//  - cls:  cw1 -> [term][32 n][64 k] swizzled frag tiles (8 KB)
// ---------------------------------------------------------------------------
__global__ void prep_w(const float* __restrict__ w0, const float* __restrict__ wr,
                       const float* __restrict__ cw1)
{
    int i = blockIdx.x * blockDim.x + threadIdx.x;
    if (i < 2048) {
        int lane = i & 31, nq = (i >> 5) & 7, j = (i >> 8) & 3, term = i >> 10;
        int g = lane >> 2, t = lane & 3, n = nq * 8 + g;
        int ks[4] = {16 * j + 2 * t, 16 * j + 2 * t + 1,
                     16 * j + 2 * t + 8, 16 * j + 2 * t + 9};
        __nv_bfloat16 b[4];
#pragma unroll
        for (int q = 0; q < 4; q++) {
            int k = ks[q];
            float v = (k < 55) ? w0[k * 64 + n] : 0.f;
            __nv_bfloat16 h = __float2bfloat16_rn(v);
            b[q] = term ? __float2bfloat16_rn(v - __bfloat162float(h)) : h;
        }
        __nv_bfloat162 p01; p01.x = b[0]; p01.y = b[1];
        __nv_bfloat162 p23; p23.x = b[2]; p23.y = b[3];
        g_B0[i * 2]     = bits2(p01);
        g_B0[i * 2 + 1] = bits2(p23);
    }
    if (i < 4096) {
        int term = i >> 11, r = i & 2047, n = r >> 6, k = r & 63;
        float v = cw1[k * 32 + n];
        __nv_bfloat16 h = __float2bfloat16_rn(v);
        __nv_bfloat16 o = term ? __float2bfloat16_rn(v - __bfloat162float(h)) : h;
        *(__nv_bfloat16*)((char*)g_C1 + term * 4096 + swz((u32)(n * 128 + k * 2))) = o;
    }
    if (i < 3 * 64 * 320) {
        int l = i / (64 * 320), r = i % (64 * 320);
        int n = r / 320, k = r % 320;
        float v = wr[(size_t)l * 320 * 64 + (size_t)k * 64 + n];
        int kk = k & 15;
        int kp = (k & ~15) | (2 * (kk >> 2) + (kk & 1) + 8 * ((kk >> 1) & 1));
        __nv_bfloat16 h = __float2bfloat16_rn(v);
        g_WR[((size_t)(l * 2 + 0) * 64 + n) * 320 + kp] = h;
        g_WR[((size_t)(l * 2 + 1) * 64 + n) * 320 + kp] =
            __float2bfloat16_rn(v - __bfloat162float(h));
    }
}

// ===========================================================================
// Layer 0 (C=11): persistent, barrier-free, warp-private frag-packed A
// 256 threads, warp = 16 nodes, tile = 128 nodes
// ===========================================================================
constexpr int L0_B0 = 0;                  // 16 KB prepacked B frags
constexpr int L0_A  = 16384;              // 8 warps x 4 KB (hi 2KB | lo 2KB)
constexpr int SMEM_L0 = L0_A + 8 * 4096;  // 49152

__global__ __launch_bounds__(256, 2)
void mesh_l0(const float* __restrict__ xin, const int* __restrict__ nbr,
             const u32* __restrict__ B0, const float* __restrict__ bias,
             const float* __restrict__ lng, const float* __restrict__ lnb,
             float* __restrict__ out)
{
    extern __shared__ char smc[];
    const int tid = threadIdx.x, wid = tid >> 5, lane = tid & 31;

    // stage prepacked B frags once (16 KB)
    for (int i = tid; i < 1024; i += 256)
        ((uint4*)(smc + L0_B0))[i] = ((const uint4*)B0)[i];
    __syncthreads();

    char* Aw = smc + L0_A + wid * 4096;
    const int  w     = lane >> 1;
    const int  half  = lane & 1;
    const int  g = lane >> 2, t = lane & 3;

    for (int tile = blockIdx.x; tile < NTILES; tile += gridDim.x) {
        const int node0 = tile * 128;
        const int node  = node0 + wid * 16 + w;
        const bool valid = node < E_NODES;

        __syncwarp();   // prior-iter frag reads complete before rewriting Aw

        auto wrA = [&](int k, float v) {
            __nv_bfloat16 h = __float2bfloat16_rn(v);
            __nv_bfloat16 l = __float2bfloat16_rn(v - __bfloat162float(h));
            int j = k >> 4, kk = k & 15;
            int pair = kk >> 3, tt = (kk >> 1) & 3, ii = kk & 1;
            int reg = pair * 2 + (w >> 3);
            u32 off = (u32)(((j * 32 + (w & 7) * 4 + tt) << 4) + reg * 4 + ii * 2);
            *(__nv_bfloat16*)(Aw + off)        = h;
            *(__nv_bfloat16*)(Aw + 2048 + off) = l;
        };

        if (valid) {
            int4 nb = ((const int4*)nbr)[node];
            if (half == 0) {
                const float* xr = xin + (size_t)node * 11;
                const float* A_ = xin + (size_t)nb.x * 11;
                const float* C_ = xin + (size_t)nb.z * 11;
#pragma unroll
                for (int ch = 0; ch < 11; ch++) {
                    wrA(ch, xr[ch]);
                    float a = A_[ch], c = C_[ch];
                    wrA(11 + ch, fabsf(a - c));
                    wrA(22 + ch, a + c);
                }
            } else {
                const float* B_ = xin + (size_t)nb.y * 11;
                const float* D_ = xin + (size_t)nb.w * 11;
#pragma unroll
                for (int ch = 0; ch < 11; ch++) {
                    float b = B_[ch], d = D_[ch];
                    wrA(33 + ch, fabsf(b - d));
                    wrA(44 + ch, b + d);
                }
#pragma unroll
                for (int k = 55; k < 64; k++) wrA(k, 0.f);
            }
        }
        __syncwarp();

        float acc[8][4];
#pragma unroll
        for (int q = 0; q < 8; q++)
#pragma unroll
            for (int c = 0; c < 4; c++) acc[q][c] = 0.f;

#pragma unroll
        for (int j = 0; j < 4; j++) {
            uint4 avh = *(const uint4*)(Aw + (j * 32 + lane) * 16);
            uint4 avl = *(const uint4*)(Aw + 2048 + (j * 32 + lane) * 16);
            u32 ah[4] = {avh.x, avh.y, avh.z, avh.w};
            u32 al[4] = {avl.x, avl.y, avl.z, avl.w};
#pragma unroll
            for (int nq = 0; nq < 8; nq++) {
                uint2 bh = *(const uint2*)(smc + L0_B0 + (size_t)(((0 * 4 + j) * 8 + nq) * 32 + lane) * 8);
                uint2 bl = *(const uint2*)(smc + L0_B0 + (size_t)(((1 * 4 + j) * 8 + nq) * 32 + lane) * 8);
                mma16816(acc[nq], ah, bh.x, bh.y);
                mma16816(acc[nq], al, bh.x, bh.y);
                mma16816(acc[nq], ah, bl.x, bl.y);
            }
        }

        // epilogue: bias + LN + ReLU (no residual), rows g and g+8
#pragma unroll
        for (int hf = 0; hf < 2; hf++) {
            int row = node0 + wid * 16 + g + 8 * hf;
            bool vv = row < E_NODES;
            float tv[16];
            float part = 0.f;
#pragma unroll
            for (int nq = 0; nq < 8; nq++) {
                int c = 8 * nq + 2 * t;
                float2 b2 = *(const float2*)(bias + c);
                tv[2 * nq]     = acc[nq][2 * hf]     + b2.x;
                tv[2 * nq + 1] = acc[nq][2 * hf + 1] + b2.y;
                part += tv[2 * nq] + tv[2 * nq + 1];
            }
            part += __shfl_xor_sync(0xFFFFFFFFu, part, 1);
            part += __shfl_xor_sync(0xFFFFFFFFu, part, 2);
            float mu = part * (1.f / 64.f);
            float vp = 0.f;
#pragma unroll
            for (int i = 0; i < 16; i++) { float d = tv[i] - mu; vp += d * d; }
            vp += __shfl_xor_sync(0xFFFFFFFFu, vp, 1);
            vp += __shfl_xor_sync(0xFFFFFFFFu, vp, 2);
            float rs = rsqrtf(vp * (1.f / 64.f) + 1e-5f);
#pragma unroll
            for (int nq = 0; nq < 8; nq++) {
                int c = 8 * nq + 2 * t;
                float2 g2  = *(const float2*)(lng + c);
                float2 lb2 = *(const float2*)(lnb + c);
                float y0 = fmaxf((tv[2 * nq]     - mu) * rs * g2.x + lb2.x, 0.f);
                float y1 = fmaxf((tv[2 * nq + 1] - mu) * rs * g2.y + lb2.y, 0.f);
                if (vv) *(float2*)(out + (size_t)row * 64 + c) = make_float2(y0, y1);
            }
        }
    }
}

// ===========================================================================
// 64-ch layers: persistent, barrier-free, float4 k-permuted gather
// 256 threads, 8 warps, warp = 16 nodes, tile = 128 nodes
// CLS: head GEMM (y@cw1) runs on HMMA straight from acc fragments
// ===========================================================================
constexpr int NOFF_B  = 9216;                 // 10 tiles x 8 KB
constexpr int NSMEM   = NOFF_B + 10 * 8192;   // 91136 (C1 frag tiles live at 0)

template <bool CLS>
__global__ __launch_bounds__(256, 2)
void mesh_fast(const float* __restrict__ xin, const int* __restrict__ nbr,
               const __nv_bfloat16* __restrict__ Wt,   // [term][64][320] (k-perm)
               const float* __restrict__ bias, const float* __restrict__ lng,
               const float* __restrict__ lnb,
               const __nv_bfloat16* __restrict__ c1t,  // cls frag tiles (8 KB)
               const float* __restrict__ cb1,
               const float* __restrict__ cw2, const float* __restrict__ cb2,
               float* __restrict__ out)
{
    extern __shared__ char smc[];
    const int tid = threadIdx.x, wid = tid >> 5, lane = tid & 31;

    // ---- stage B once: 5 segments x 2 terms, swizzled rows for ldmatrix ----
    for (int j = tid; j < 5120; j += 256) {
        int r = j >> 3, c = j & 7;
        int seg = r >> 7, term = (r >> 6) & 1, nrow = r & 63;
        const char* src = (const char*)(Wt + (size_t)term * 64 * 320
                                        + (size_t)nrow * 320 + seg * 64) + c * 16;
        char* dst = smc + NOFF_B + (seg * 2 + term) * 8192;
        *(uint4*)(dst + swz((u32)(nrow * 128 + c * 16))) = *(const uint4*)src;
    }
    if (CLS) {
        for (int i = tid; i < 512; i += 256)
            ((uint4*)smc)[i] = ((const uint4*)c1t)[i];
    }
    __syncthreads();   // the ONLY block barrier

    const int g = lane >> 2, t = lane & 3, t4 = lane >> 3;

    auto bofs = [&](int pb, int k16) -> u32 {
        return swz((u32)(((2 * pb + (t4 >> 1)) * 8 + (lane & 7)) * 128
                         + k16 * 32 + ((t4 & 1) << 4)));
    };

    for (int tile = blockIdx.x; tile < NTILES; tile += gridDim.x) {
        const int node0 = tile * 128;
        const int base = node0 + wid * 16 + g;
        const int row0 = base, row1 = base + 8;
        const bool v0 = row0 < E_NODES, v1 = row1 < E_NODES;
        const int rr0 = v0 ? row0 : 0, rr1 = v1 ? row1 : 0;

        // early neighbor-index fetch (one int4 per row)
        const int4 nb0 = ((const int4*)nbr)[rr0];
        const int4 nb1 = ((const int4*)nbr)[rr1];

        float acc[8][4];
#pragma unroll
        for (int q = 0; q < 8; q++)
#pragma unroll
            for (int c = 0; c < 4; c++) acc[q][c] = 0.f;

        auto run_seg = [&](int seg, int k16, u32 (&ah)[4], u32 (&al)[4]) {
            u32 bh[16], bl[16];
            u32 bh_b = s2u(smc + NOFF_B + (seg * 2 + 0) * 8192);
            u32 bl_b = s2u(smc + NOFF_B + (seg * 2 + 1) * 8192);
#pragma unroll
            for (int pb = 0; pb < 4; pb++) {
                ldmx4(bh + 4 * pb, bh_b + bofs(pb, k16));
                ldmx4(bl + 4 * pb, bl_b + bofs(pb, k16));
            }
#pragma unroll
            for (int nq = 0; nq < 8; nq++) {
                mma16816(acc[nq], ah, bh[2 * nq], bh[2 * nq + 1]);
                mma16816(acc[nq], al, bh[2 * nq], bh[2 * nq + 1]);
                mma16816(acc[nq], ah, bl[2 * nq], bl[2 * nq + 1]);
            }
        };

        // ---- phase 0: x (seg 0) ----
#pragma unroll
        for (int j = 0; j < 4; j++) {
            const int fo = 16 * j + 4 * t;
            float4 p0 = *(const float4*)(xin + (size_t)rr0 * 64 + fo);
            float4 p1 = *(const float4*)(xin + (size_t)rr1 * 64 + fo);
            u32 ah[4], al[4];
            split2(p0.x, p0.y, ah[0], al[0]);
            split2(p1.x, p1.y, ah[1], al[1]);
            split2(p0.z, p0.w, ah[2], al[2]);
            split2(p1.z, p1.w, ah[3], al[3]);
            run_seg(0, j, ah, al);
        }

        // ---- phases 1,2: neighbor pairs (segs 1,2 and 3,4) ----
#pragma unroll
        for (int ph = 0; ph < 2; ph++) {
            const int sd = ph ? 3 : 1;
            const int ia0 = ph ? nb0.y : nb0.x;
            const int ic0 = ph ? nb0.w : nb0.z;
            const int ia1 = ph ? nb1.y : nb1.x;
            const int ic1 = ph ? nb1.w : nb1.z;
            const float* A0 = xin + (size_t)ia0 * 64;
            const float* C0 = xin + (size_t)ic0 * 64;
            const float* A1 = xin + (size_t)ia1 * 64;
            const float* C1_ = xin + (size_t)ic1 * 64;
#pragma unroll
            for (int j = 0; j < 4; j++) {
                const int fo = 16 * j + 4 * t;
                float4 a0 = *(const float4*)(A0 + fo);
                float4 a1 = *(const float4*)(A1 + fo);
                float4 c0 = *(const float4*)(C0 + fo);
                float4 c1 = *(const float4*)(C1_ + fo);
                u32 dh[4], dl[4], sh[4], sl[4];
                split2(fabsf(a0.x - c0.x), fabsf(a0.y - c0.y), dh[0], dl[0]);
                split2(fabsf(a1.x - c1.x), fabsf(a1.y - c1.y), dh[1], dl[1]);
                split2(fabsf(a0.z - c0.z), fabsf(a0.w - c0.w), dh[2], dl[2]);
                split2(fabsf(a1.z - c1.z), fabsf(a1.w - c1.w), dh[3], dl[3]);
                split2(a0.x + c0.x, a0.y + c0.y, sh[0], sl[0]);
                split2(a1.x + c1.x, a1.y + c1.y, sh[1], sl[1]);
                split2(a0.z + c0.z, a0.w + c0.w, sh[2], sl[2]);
                split2(a1.z + c1.z, a1.w + c1.w, sh[3], sl[3]);
                run_seg(sd, j, dh, dl);
                run_seg(sd + 1, j, sh, sl);
            }
        }

        // ---- epilogue: bias + LN + ReLU + residual, in registers ----
#pragma unroll
        for (int hf = 0; hf < 2; hf++) {
            const int row = hf ? row1 : row0;
            const bool v_ = hf ? v1 : v0;
            float tv[16];
            float part = 0.f;
#pragma unroll
            for (int nq = 0; nq < 8; nq++) {
                int c = 8 * nq + 2 * t;
                float2 b2 = *(const float2*)(bias + c);
                tv[2 * nq]     = acc[nq][2 * hf]     + b2.x;
                tv[2 * nq + 1] = acc[nq][2 * hf + 1] + b2.y;
                part += tv[2 * nq] + tv[2 * nq + 1];
            }
            part += __shfl_xor_sync(0xFFFFFFFFu, part, 1);
            part += __shfl_xor_sync(0xFFFFFFFFu, part, 2);
            float mu = part * (1.f / 64.f);
            float vp = 0.f;
#pragma unroll
            for (int i = 0; i < 16; i++) { float d = tv[i] - mu; vp += d * d; }
            vp += __shfl_xor_sync(0xFFFFFFFFu, vp, 1);
            vp += __shfl_xor_sync(0xFFFFFFFFu, vp, 2);
            float rsv = rsqrtf(vp * (1.f / 64.f) + 1e-5f);
#pragma unroll
            for (int nq = 0; nq < 8; nq++) {
                int c = 8 * nq + 2 * t;
                float2 g2  = *(const float2*)(lng + c);
                float2 lb2 = *(const float2*)(lnb + c);
                float2 xr  = *(const float2*)(xin + (size_t)(v_ ? row : 0) * 64 + c);
                float y0 = fmaxf((tv[2 * nq]     - mu) * rsv * g2.x + lb2.x, 0.f) + xr.x;
                float y1 = fmaxf((tv[2 * nq + 1] - mu) * rsv * g2.y + lb2.y, 0.f) + xr.y;
                if (!CLS) {
                    if (v_) *(float2*)(out + (size_t)row * 64 + c) = make_float2(y0, y1);
                } else {
                    acc[nq][2 * hf]     = y0;
                    acc[nq][2 * hf + 1] = y1;
                }
            }
        }

        if (CLS) {
            // ---- head GEMM z = y@cw1 + cb1 on HMMA, A-frags direct from acc ----
            float zacc[4][4];
#pragma unroll
            for (int nq = 0; nq < 4; nq++) {
                float b0 = __ldg(cb1 + 8 * nq + 2 * t);
                float b1 = __ldg(cb1 + 8 * nq + 2 * t + 1);
                zacc[nq][0] = b0; zacc[nq][1] = b1; zacc[nq][2] = b0; zacc[nq][3] = b1;
            }
            const u32 c1h = s2u(smc), c1l = s2u(smc + 4096);
#pragma unroll
            for (int j = 0; j < 4; j++) {
                u32 ah[4], al[4];
                split2(acc[2 * j][0],     acc[2 * j][1],     ah[0], al[0]);
                split2(acc[2 * j][2],     acc[2 * j][3],     ah[1], al[1]);
                split2(acc[2 * j + 1][0], acc[2 * j + 1][1], ah[2], al[2]);
                split2(acc[2 * j + 1][2], acc[2 * j + 1][3], ah[3], al[3]);
                u32 bh[8], bl[8];
#pragma unroll
                for (int pb = 0; pb < 2; pb++) {
                    ldmx4(bh + 4 * pb, c1h + bofs(pb, j));
                    ldmx4(bl + 4 * pb, c1l + bofs(pb, j));
                }
#pragma unroll
                for (int nq = 0; nq < 4; nq++) {
                    mma16816(zacc[nq], ah, bh[2 * nq], bh[2 * nq + 1]);
                    mma16816(zacc[nq], al, bh[2 * nq], bh[2 * nq + 1]);
                    mma16816(zacc[nq], ah, bl[2 * nq], bl[2 * nq + 1]);
                }
            }
            // ---- logit = relu(z)@cw2 + cb2, quad shuffle reduce ----
            float p0 = 0.f, p1 = 0.f;
#pragma unroll
            for (int nq = 0; nq < 4; nq++) {
                float w0 = __ldg(cw2 + 8 * nq + 2 * t);
                float w1 = __ldg(cw2 + 8 * nq + 2 * t + 1);
                p0 += fmaxf(zacc[nq][0], 0.f) * w0 + fmaxf(zacc[nq][1], 0.f) * w1;
                p1 += fmaxf(zacc[nq][2], 0.f) * w0 + fmaxf(zacc[nq][3], 0.f) * w1;
            }
            p0 += __shfl_xor_sync(0xFFFFFFFFu, p0, 1);
            p0 += __shfl_xor_sync(0xFFFFFFFFu, p0, 2);
            p1 += __shfl_xor_sync(0xFFFFFFFFu, p1, 1);
            p1 += __shfl_xor_sync(0xFFFFFFFFu, p1, 2);
            if (t == 0) {
                float c2 = __ldg(cb2);
                if (v0) out[row0] = p0 + c2;
                if (v1) out[row1] = p1 + c2;
            }
        }
    }
}

// ---------------------------------------------------------------------------

extern "C" void kernel_launch(void* const* d_in, const int* in_sizes, int n_in,
                              void* d_out, int out_size)
{
    const float* x      = (const float*)d_in[0];
    const int*   nbr    = (const int*)  d_in[1];
    const float* w0     = (const float*)d_in[2];
    const float* b0     = (const float*)d_in[3];
    const float* w_rest = (const float*)d_in[4];
    const float* b_rest = (const float*)d_in[5];
    const float* ln_g   = (const float*)d_in[6];
    const float* ln_b   = (const float*)d_in[7];
    const float* cw1    = (const float*)d_in[8];
    const float* cb1    = (const float*)d_in[9];
    const float* cw2    = (const float*)d_in[10];
    const float* cb2    = (const float*)d_in[11];
    float* out = (float*)d_out;

    float *bufA, *bufB;
    __nv_bfloat16 *WRp, *C1p;
    u32 *B0p;
    cudaGetSymbolAddress((void**)&bufA, g_bufA);
    cudaGetSymbolAddress((void**)&bufB, g_bufB);
    cudaGetSymbolAddress((void**)&WRp, g_WR);
    cudaGetSymbolAddress((void**)&B0p, g_B0);
    cudaGetSymbolAddress((void**)&C1p, g_C1);

    cudaFuncSetAttribute(mesh_l0, cudaFuncAttributeMaxDynamicSharedMemorySize, SMEM_L0);
    cudaFuncSetAttribute(mesh_fast<false>, cudaFuncAttributeMaxDynamicSharedMemorySize, NSMEM);
    cudaFuncSetAttribute(mesh_fast<true>,  cudaFuncAttributeMaxDynamicSharedMemorySize, NSMEM);

    prep_w<<<240, 256>>>(w0, w_rest, cw1);

    mesh_l0<<<PGRID, 256, SMEM_L0>>>(x, nbr, B0p, b0, ln_g, ln_b, bufA);

    mesh_fast<false><<<PGRID, 256, NSMEM>>>(
        bufA, nbr, WRp, b_rest, ln_g + 64, ln_b + 64,
        nullptr, nullptr, nullptr, nullptr, bufB);

    mesh_fast<false><<<PGRID, 256, NSMEM>>>(
        bufB, nbr, WRp + 2 * 64 * 320, b_rest + 64, ln_g + 128, ln_b + 128,
        nullptr, nullptr, nullptr, nullptr, bufA);

    mesh_fast<true><<<PGRID, 256, NSMEM>>>(
        bufA, nbr, WRp + 4 * 64 * 320, b_rest + 128, ln_g + 192, ln_b + 192,
        C1p, cb1, cw2, cb2, out);
}

// round 12
// speedup vs baseline: 3.7416x; 1.2582x over previous
#include <cuda_runtime.h>
#include <cuda_fp16.h>
#include <cstdint>

typedef unsigned int u32;
typedef unsigned long long u64;

#define E_NODES 1000000
#define NTILES ((E_NODES + 127) / 128)
#define PGRID 304

// Scratch activations + pre-split weights (alloc-free rule: __device__ globals)
__device__ float g_bufA[(size_t)E_NODES * 64];
__device__ float g_bufB[(size_t)E_NODES * 64];
__device__ __half g_WR[3 * 64 * 320];                // [l][n][kperm]  fp16
__device__ __align__(16) u32 g_B0[4 * 8 * 32 * 2];   // l0 frag-packed B (fp16)
__device__ __align__(16) __half g_C1[32 * 64];       // cls W1 frag tile (fp16)

// ---------------------------------------------------------------------------
// helpers
// ---------------------------------------------------------------------------
__device__ __forceinline__ u32 s2u(const void* p) {
    u32 a;
    asm("{.reg .u64 t; cvta.to.shared.u64 t,%1; cvt.u32.u64 %0,t;}" : "=r"(a) : "l"(p));
    return a;
}
__device__ __forceinline__ u32 swz(u32 b) { return b ^ ((b >> 3) & 0x70); }

__device__ __forceinline__ void ldmx4(u32* r, u32 addr) {
    asm volatile("ldmatrix.sync.aligned.m8n8.x4.shared.b16 {%0,%1,%2,%3},[%4];"
                 : "=r"(r[0]), "=r"(r[1]), "=r"(r[2]), "=r"(r[3]) : "r"(addr));
}
// fp16 HMMA, fp32 accumulate
__device__ __forceinline__ void mma_h(float* d, const u32* a, u32 b0, u32 b1) {
    asm volatile(
        "mma.sync.aligned.m16n8k16.row.col.f32.f16.f16.f32 "
        "{%0,%1,%2,%3},{%4,%5,%6,%7},{%8,%9},{%0,%1,%2,%3};"
        : "+f"(d[0]), "+f"(d[1]), "+f"(d[2]), "+f"(d[3])
        : "r"(a[0]), "r"(a[1]), "r"(a[2]), "r"(a[3]), "r"(b0), "r"(b1));
}

__device__ __forceinline__ u32 bits2h(__half2 v) {
    u32 u; __builtin_memcpy(&u, &v, 4); return u;
}
// split (a,b) fp32 pair into hi/lo fp16x2 packs (hi 11 bits, lo next 11)
__device__ __forceinline__ void split2h(float a, float b, u32& h, u32& l) {
    __half2 hh = __floats2half2_rn(a, b);
    float ra = a - __half2float(__low2half(hh));
    float rb = b - __half2float(__high2half(hh));
    __half2 ll = __floats2half2_rn(ra, rb);
    h = bits2h(hh); l = bits2h(ll);
}

// ---------------------------------------------------------------------------
// weight prep (all fp16 single-plane):
//  - mids: transpose to [n][k], K-PERMUTED within each 16-block
//  - l0:   frag-packed B (logical k, no perm), zero-pad K 55->64
//  - cls:  cw1 -> [32 n][64 k] swizzled frag tile (4 KB)
// ---------------------------------------------------------------------------
__global__ void prep_w(const float* __restrict__ w0, const float* __restrict__ wr,
                       const float* __restrict__ cw1)
{
    int i = blockIdx.x * blockDim.x + threadIdx.x;
    if (i < 1024) {
        int lane = i & 31, nq = (i >> 5) & 7, j = (i >> 8) & 3;
        int g = lane >> 2, t = lane & 3, n = nq * 8 + g;
        int ks[4] = {16 * j + 2 * t, 16 * j + 2 * t + 1,
                     16 * j + 2 * t + 8, 16 * j + 2 * t + 9};
        __half b[4];
#pragma unroll
        for (int q = 0; q < 4; q++) {
            int k = ks[q];
            float v = (k < 55) ? w0[k * 64 + n] : 0.f;
            b[q] = __float2half_rn(v);
        }
        __half2 p01; p01 = __halves2half2(b[0], b[1]);
        __half2 p23; p23 = __halves2half2(b[2], b[3]);
        g_B0[i * 2]     = bits2h(p01);
        g_B0[i * 2 + 1] = bits2h(p23);
    }
    if (i < 2048) {
        int n = i >> 6, k = i & 63;
        float v = cw1[k * 32 + n];
        *(__half*)((char*)g_C1 + swz((u32)(n * 128 + k * 2))) = __float2half_rn(v);
    }
    if (i < 3 * 64 * 320) {
        int l = i / (64 * 320), r = i % (64 * 320);
        int n = r / 320, k = r % 320;
        float v = wr[(size_t)l * 320 * 64 + (size_t)k * 64 + n];
        int kk = k & 15;
        int kp = (k & ~15) | (2 * (kk >> 2) + (kk & 1) + 8 * ((kk >> 1) & 1));
        g_WR[((size_t)l * 64 + n) * 320 + kp] = __float2half_rn(v);
    }
}

// ===========================================================================
// Layer 0 (C=11): persistent, barrier-free, warp-private frag-packed A
// 256 threads, warp = 16 nodes, tile = 128 nodes
// ===========================================================================
constexpr int L0_B0 = 0;                  // 8 KB prepacked B frags (fp16)
constexpr int L0_A  = 8192;               // 8 warps x 4 KB (hi 2KB | lo 2KB)
constexpr int SMEM_L0 = L0_A + 8 * 4096;  // 40960

__global__ __launch_bounds__(256, 2)
void mesh_l0(const float* __restrict__ xin, const int* __restrict__ nbr,
             const u32* __restrict__ B0, const float* __restrict__ bias,
             const float* __restrict__ lng, const float* __restrict__ lnb,
             float* __restrict__ out)
{
    extern __shared__ char smc[];
    const int tid = threadIdx.x, wid = tid >> 5, lane = tid & 31;

    // stage prepacked B frags once (8 KB)
    for (int i = tid; i < 512; i += 256)
        ((uint4*)(smc + L0_B0))[i] = ((const uint4*)B0)[i];
    __syncthreads();

    char* Aw = smc + L0_A + wid * 4096;
    const int  w     = lane >> 1;
    const int  half_ = lane & 1;
    const int  g = lane >> 2, t = lane & 3;

    for (int tile = blockIdx.x; tile < NTILES; tile += gridDim.x) {
        const int node0 = tile * 128;
        const int node  = node0 + wid * 16 + w;
        const bool valid = node < E_NODES;

        __syncwarp();   // prior-iter frag reads complete before rewriting Aw

        auto wrA = [&](int k, float v) {
            __half hh = __float2half_rn(v);
            __half ll = __float2half_rn(v - __half2float(hh));
            int j = k >> 4, kk = k & 15;
            int pair = kk >> 3, tt = (kk >> 1) & 3, ii = kk & 1;
            int reg = pair * 2 + (w >> 3);
            u32 off = (u32)(((j * 32 + (w & 7) * 4 + tt) << 4) + reg * 4 + ii * 2);
            *(__half*)(Aw + off)        = hh;
            *(__half*)(Aw + 2048 + off) = ll;
        };

        if (valid) {
            int4 nb = ((const int4*)nbr)[node];
            if (half_ == 0) {
                const float* xr = xin + (size_t)node * 11;
                const float* A_ = xin + (size_t)nb.x * 11;
                const float* C_ = xin + (size_t)nb.z * 11;
#pragma unroll
                for (int ch = 0; ch < 11; ch++) {
                    wrA(ch, xr[ch]);
                    float a = A_[ch], c = C_[ch];
                    wrA(11 + ch, fabsf(a - c));
                    wrA(22 + ch, a + c);
                }
            } else {
                const float* B_ = xin + (size_t)nb.y * 11;
                const float* D_ = xin + (size_t)nb.w * 11;
#pragma unroll
                for (int ch = 0; ch < 11; ch++) {
                    float b = B_[ch], d = D_[ch];
                    wrA(33 + ch, fabsf(b - d));
                    wrA(44 + ch, b + d);
                }
#pragma unroll
                for (int k = 55; k < 64; k++) wrA(k, 0.f);
            }
        }
        __syncwarp();

        float acc[8][4];
#pragma unroll
        for (int q = 0; q < 8; q++)
#pragma unroll
            for (int c = 0; c < 4; c++) acc[q][c] = 0.f;

#pragma unroll
        for (int j = 0; j < 4; j++) {
            uint4 avh = *(const uint4*)(Aw + (j * 32 + lane) * 16);
            uint4 avl = *(const uint4*)(Aw + 2048 + (j * 32 + lane) * 16);
            u32 ah[4] = {avh.x, avh.y, avh.z, avh.w};
            u32 al[4] = {avl.x, avl.y, avl.z, avl.w};
#pragma unroll
            for (int nq = 0; nq < 8; nq++) {
                uint2 bh = *(const uint2*)(smc + L0_B0 + (size_t)((j * 8 + nq) * 32 + lane) * 8);
                mma_h(acc[nq], ah, bh.x, bh.y);
                mma_h(acc[nq], al, bh.x, bh.y);
            }
        }

        // epilogue: bias + LN + ReLU (no residual), rows g and g+8
#pragma unroll
        for (int hf = 0; hf < 2; hf++) {
            int row = node0 + wid * 16 + g + 8 * hf;
            bool vv = row < E_NODES;
            float tv[16];
            float part = 0.f;
#pragma unroll
            for (int nq = 0; nq < 8; nq++) {
                int c = 8 * nq + 2 * t;
                float2 b2 = *(const float2*)(bias + c);
                tv[2 * nq]     = acc[nq][2 * hf]     + b2.x;
                tv[2 * nq + 1] = acc[nq][2 * hf + 1] + b2.y;
                part += tv[2 * nq] + tv[2 * nq + 1];
            }
            part += __shfl_xor_sync(0xFFFFFFFFu, part, 1);
            part += __shfl_xor_sync(0xFFFFFFFFu, part, 2);
            float mu = part * (1.f / 64.f);
            float vp = 0.f;
#pragma unroll
            for (int i = 0; i < 16; i++) { float d = tv[i] - mu; vp += d * d; }
            vp += __shfl_xor_sync(0xFFFFFFFFu, vp, 1);
            vp += __shfl_xor_sync(0xFFFFFFFFu, vp, 2);
            float rs = rsqrtf(vp * (1.f / 64.f) + 1e-5f);
#pragma unroll
            for (int nq = 0; nq < 8; nq++) {
                int c = 8 * nq + 2 * t;
                float2 g2  = *(const float2*)(lng + c);
                float2 lb2 = *(const float2*)(lnb + c);
                float y0 = fmaxf((tv[2 * nq]     - mu) * rs * g2.x + lb2.x, 0.f);
                float y1 = fmaxf((tv[2 * nq + 1] - mu) * rs * g2.y + lb2.y, 0.f);
                if (vv) *(float2*)(out + (size_t)row * 64 + c) = make_float2(y0, y1);
            }
        }
    }
}

// ===========================================================================
// 64-ch layers: persistent, barrier-free, float4 k-permuted gather
// fp16 2-term (A hi/lo x B single). 256 threads, warp = 16 nodes
// CLS: head GEMM (y@cw1) runs on HMMA straight from acc fragments
// ===========================================================================
constexpr int NOFF_B  = 8192;                // C1 frag tile lives at 0 (4 KB)
constexpr int NSMEM   = NOFF_B + 5 * 8192;   // 49152

template <bool CLS>
__global__ __launch_bounds__(256, 2)
void mesh_fast(const float* __restrict__ xin, const int* __restrict__ nbr,
               const __half* __restrict__ Wt,          // [64][320] (k-perm) fp16
               const float* __restrict__ bias, const float* __restrict__ lng,
               const float* __restrict__ lnb,
               const __half* __restrict__ c1t,         // cls frag tile (4 KB)
               const float* __restrict__ cb1,
               const float* __restrict__ cw2, const float* __restrict__ cb2,
               float* __restrict__ out)
{
    extern __shared__ char smc[];
    const int tid = threadIdx.x, wid = tid >> 5, lane = tid & 31;

    // ---- stage B once: 5 segments, swizzled rows for ldmatrix (40 KB) ----
    for (int j = tid; j < 2560; j += 256) {
        int r = j >> 3, c = j & 7;
        int seg = r >> 6, nrow = r & 63;
        const char* src = (const char*)Wt + (size_t)nrow * 640 + seg * 128 + c * 16;
        char* dst = smc + NOFF_B + seg * 8192;
        *(uint4*)(dst + swz((u32)(nrow * 128 + c * 16))) = *(const uint4*)src;
    }
    if (CLS) {
        for (int i = tid; i < 256; i += 256)
            ((uint4*)smc)[i] = ((const uint4*)c1t)[i];
    }
    __syncthreads();   // the ONLY block barrier

    const int g = lane >> 2, t = lane & 3, t4 = lane >> 3;

    auto bofs = [&](int pb, int k16) -> u32 {
        return swz((u32)(((2 * pb + (t4 >> 1)) * 8 + (lane & 7)) * 128
                         + k16 * 32 + ((t4 & 1) << 4)));
    };

    for (int tile = blockIdx.x; tile < NTILES; tile += gridDim.x) {
        const int node0 = tile * 128;
        const int base = node0 + wid * 16 + g;
        const int row0 = base, row1 = base + 8;
        const bool v0 = row0 < E_NODES, v1 = row1 < E_NODES;
        const int rr0 = v0 ? row0 : 0, rr1 = v1 ? row1 : 0;

        // early neighbor-index fetch (one int4 per row)
        const int4 nb0 = ((const int4*)nbr)[rr0];
        const int4 nb1 = ((const int4*)nbr)[rr1];

        float acc[8][4];
#pragma unroll
        for (int q = 0; q < 8; q++)
#pragma unroll
            for (int c = 0; c < 4; c++) acc[q][c] = 0.f;

        auto run_seg = [&](int seg, int k16, u32 (&ah)[4], u32 (&al)[4]) {
            u32 bh[16];
            u32 bh_b = s2u(smc + NOFF_B + seg * 8192);
#pragma unroll
            for (int pb = 0; pb < 4; pb++)
                ldmx4(bh + 4 * pb, bh_b + bofs(pb, k16));
#pragma unroll
            for (int nq = 0; nq < 8; nq++) {
                mma_h(acc[nq], ah, bh[2 * nq], bh[2 * nq + 1]);
                mma_h(acc[nq], al, bh[2 * nq], bh[2 * nq + 1]);
            }
        };

        // ---- phase 0: x (seg 0) ----
#pragma unroll
        for (int j = 0; j < 4; j++) {
            const int fo = 16 * j + 4 * t;
            float4 p0 = *(const float4*)(xin + (size_t)rr0 * 64 + fo);
            float4 p1 = *(const float4*)(xin + (size_t)rr1 * 64 + fo);
            u32 ah[4], al[4];
            split2h(p0.x, p0.y, ah[0], al[0]);
            split2h(p1.x, p1.y, ah[1], al[1]);
            split2h(p0.z, p0.w, ah[2], al[2]);
            split2h(p1.z, p1.w, ah[3], al[3]);
            run_seg(0, j, ah, al);
        }

        // ---- phases 1,2: neighbor pairs (segs 1,2 and 3,4) ----
#pragma unroll
        for (int ph = 0; ph < 2; ph++) {
            const int sd = ph ? 3 : 1;
            const int ia0 = ph ? nb0.y : nb0.x;
            const int ic0 = ph ? nb0.w : nb0.z;
            const int ia1 = ph ? nb1.y : nb1.x;
            const int ic1 = ph ? nb1.w : nb1.z;
            const float* A0 = xin + (size_t)ia0 * 64;
            const float* C0 = xin + (size_t)ic0 * 64;
            const float* A1 = xin + (size_t)ia1 * 64;
            const float* C1_ = xin + (size_t)ic1 * 64;
#pragma unroll
            for (int j = 0; j < 4; j++) {
                const int fo = 16 * j + 4 * t;
                float4 a0 = *(const float4*)(A0 + fo);
                float4 a1 = *(const float4*)(A1 + fo);
                float4 c0 = *(const float4*)(C0 + fo);
                float4 c1 = *(const float4*)(C1_ + fo);
                u32 dh[4], dl[4], sh[4], sl[4];
                split2h(fabsf(a0.x - c0.x), fabsf(a0.y - c0.y), dh[0], dl[0]);
                split2h(fabsf(a1.x - c1.x), fabsf(a1.y - c1.y), dh[1], dl[1]);
                split2h(fabsf(a0.z - c0.z), fabsf(a0.w - c0.w), dh[2], dl[2]);
                split2h(fabsf(a1.z - c1.z), fabsf(a1.w - c1.w), dh[3], dl[3]);
                split2h(a0.x + c0.x, a0.y + c0.y, sh[0], sl[0]);
                split2h(a1.x + c1.x, a1.y + c1.y, sh[1], sl[1]);
                split2h(a0.z + c0.z, a0.w + c0.w, sh[2], sl[2]);
                split2h(a1.z + c1.z, a1.w + c1.w, sh[3], sl[3]);
                run_seg(sd, j, dh, dl);
                run_seg(sd + 1, j, sh, sl);
            }
        }

        // ---- epilogue: bias + LN + ReLU + residual, in registers ----
#pragma unroll
        for (int hf = 0; hf < 2; hf++) {
            const int row = hf ? row1 : row0;
            const bool v_ = hf ? v1 : v0;
            float tv[16];
            float part = 0.f;
#pragma unroll
            for (int nq = 0; nq < 8; nq++) {
                int c = 8 * nq + 2 * t;
                float2 b2 = *(const float2*)(bias + c);
                tv[2 * nq]     = acc[nq][2 * hf]     + b2.x;
                tv[2 * nq + 1] = acc[nq][2 * hf + 1] + b2.y;
                part += tv[2 * nq] + tv[2 * nq + 1];
            }
            part += __shfl_xor_sync(0xFFFFFFFFu, part, 1);
            part += __shfl_xor_sync(0xFFFFFFFFu, part, 2);
            float mu = part * (1.f / 64.f);
            float vp = 0.f;
#pragma unroll
            for (int i = 0; i < 16; i++) { float d = tv[i] - mu; vp += d * d; }
            vp += __shfl_xor_sync(0xFFFFFFFFu, vp, 1);
            vp += __shfl_xor_sync(0xFFFFFFFFu, vp, 2);
            float rsv = rsqrtf(vp * (1.f / 64.f) + 1e-5f);
#pragma unroll
            for (int nq = 0; nq < 8; nq++) {
                int c = 8 * nq + 2 * t;
                float2 g2  = *(const float2*)(lng + c);
                float2 lb2 = *(const float2*)(lnb + c);
                float2 xr  = *(const float2*)(xin + (size_t)(v_ ? row : 0) * 64 + c);
                float y0 = fmaxf((tv[2 * nq]     - mu) * rsv * g2.x + lb2.x, 0.f) + xr.x;
                float y1 = fmaxf((tv[2 * nq + 1] - mu) * rsv * g2.y + lb2.y, 0.f) + xr.y;
                if (!CLS) {
                    if (v_) *(float2*)(out + (size_t)row * 64 + c) = make_float2(y0, y1);
                } else {
                    acc[nq][2 * hf]     = y0;
                    acc[nq][2 * hf + 1] = y1;
                }
            }
        }

        if (CLS) {
            // ---- head GEMM z = y@cw1 + cb1 on HMMA, A-frags direct from acc ----
            float zacc[4][4];
#pragma unroll
            for (int nq = 0; nq < 4; nq++) {
                float b0 = __ldg(cb1 + 8 * nq + 2 * t);
                float b1 = __ldg(cb1 + 8 * nq + 2 * t + 1);
                zacc[nq][0] = b0; zacc[nq][1] = b1; zacc[nq][2] = b0; zacc[nq][3] = b1;
            }
            const u32 c1h = s2u(smc);
#pragma unroll
            for (int j = 0; j < 4; j++) {
                u32 ah[4], al[4];
                split2h(acc[2 * j][0],     acc[2 * j][1],     ah[0], al[0]);
                split2h(acc[2 * j][2],     acc[2 * j][3],     ah[1], al[1]);
                split2h(acc[2 * j + 1][0], acc[2 * j + 1][1], ah[2], al[2]);
                split2h(acc[2 * j + 1][2], acc[2 * j + 1][3], ah[3], al[3]);
                u32 bh[8];
#pragma unroll
                for (int pb = 0; pb < 2; pb++)
                    ldmx4(bh + 4 * pb, c1h + bofs(pb, j));
#pragma unroll
                for (int nq = 0; nq < 4; nq++) {
                    mma_h(zacc[nq], ah, bh[2 * nq], bh[2 * nq + 1]);
                    mma_h(zacc[nq], al, bh[2 * nq], bh[2 * nq + 1]);
                }
            }
            // ---- logit = relu(z)@cw2 + cb2, quad shuffle reduce ----
            float p0 = 0.f, p1 = 0.f;
#pragma unroll
            for (int nq = 0; nq < 4; nq++) {
                float w0 = __ldg(cw2 + 8 * nq + 2 * t);
                float w1 = __ldg(cw2 + 8 * nq + 2 * t + 1);
                p0 += fmaxf(zacc[nq][0], 0.f) * w0 + fmaxf(zacc[nq][1], 0.f) * w1;
                p1 += fmaxf(zacc[nq][2], 0.f) * w0 + fmaxf(zacc[nq][3], 0.f) * w1;
            }
            p0 += __shfl_xor_sync(0xFFFFFFFFu, p0, 1);
            p0 += __shfl_xor_sync(0xFFFFFFFFu, p0, 2);
            p1 += __shfl_xor_sync(0xFFFFFFFFu, p1, 1);
            p1 += __shfl_xor_sync(0xFFFFFFFFu, p1, 2);
            if (t == 0) {
                float c2 = __ldg(cb2);
                if (v0) out[row0] = p0 + c2;
                if (v1) out[row1] = p1 + c2;
            }
        }
    }
}

// ---------------------------------------------------------------------------

extern "C" void kernel_launch(void* const* d_in, const int* in_sizes, int n_in,
                              void* d_out, int out_size)
{
    const float* x      = (const float*)d_in[0];
    const int*   nbr    = (const int*)  d_in[1];
    const float* w0     = (const float*)d_in[2];
    const float* b0     = (const float*)d_in[3];
    const float* w_rest = (const float*)d_in[4];
    const float* b_rest = (const float*)d_in[5];
    const float* ln_g   = (const float*)d_in[6];
    const float* ln_b   = (const float*)d_in[7];
    const float* cw1    = (const float*)d_in[8];
    const float* cb1    = (const float*)d_in[9];
    const float* cw2    = (const float*)d_in[10];
    const float* cb2    = (const float*)d_in[11];
    float* out = (float*)d_out;

    float *bufA, *bufB;
    __half *WRp, *C1p;
    u32 *B0p;
    cudaGetSymbolAddress((void**)&bufA, g_bufA);
    cudaGetSymbolAddress((void**)&bufB, g_bufB);
    cudaGetSymbolAddress((void**)&WRp, g_WR);
    cudaGetSymbolAddress((void**)&B0p, g_B0);
    cudaGetSymbolAddress((void**)&C1p, g_C1);

    cudaFuncSetAttribute(mesh_l0, cudaFuncAttributeMaxDynamicSharedMemorySize, SMEM_L0);
    cudaFuncSetAttribute(mesh_fast<false>, cudaFuncAttributeMaxDynamicSharedMemorySize, NSMEM);
    cudaFuncSetAttribute(mesh_fast<true>,  cudaFuncAttributeMaxDynamicSharedMemorySize, NSMEM);

    prep_w<<<240, 256>>>(w0, w_rest, cw1);

    mesh_l0<<<PGRID, 256, SMEM_L0>>>(x, nbr, B0p, b0, ln_g, ln_b, bufA);

    mesh_fast<false><<<PGRID, 256, NSMEM>>>(
        bufA, nbr, WRp, b_rest, ln_g + 64, ln_b + 64,
        nullptr, nullptr, nullptr, nullptr, bufB);

    mesh_fast<false><<<PGRID, 256, NSMEM>>>(
        bufB, nbr, WRp + 64 * 320, b_rest + 64, ln_g + 128, ln_b + 128,
        nullptr, nullptr, nullptr, nullptr, bufA);

    mesh_fast<true><<<PGRID, 256, NSMEM>>>(
        bufA, nbr, WRp + 2 * 64 * 320, b_rest + 128, ln_g + 192, ln_b + 192,
        C1p, cb1, cw2, cb2, out);
}

// round 13
// speedup vs baseline: 4.3772x; 1.1699x over previous
#include <cuda_runtime.h>
#include <cuda_fp16.h>
#include <cstdint>

typedef unsigned int u32;
typedef unsigned long long u64;

#define E_NODES 1000000
#define NTILES ((E_NODES + 127) / 128)
#define PGRID 304

// Scratch activations (fp16!) + pre-split weights (alloc-free rule)
__device__ __half g_bufA[(size_t)E_NODES * 64];
__device__ __half g_bufB[(size_t)E_NODES * 64];
__device__ __half g_WR[3 * 64 * 320];                // [l][n][kperm]  fp16
__device__ __align__(16) u32 g_B0[4 * 8 * 32 * 2];   // l0 frag-packed B (fp16)
__device__ __align__(16) __half g_C1[32 * 64];       // cls W1 frag tile (fp16)

// ---------------------------------------------------------------------------
// helpers
// ---------------------------------------------------------------------------
__device__ __forceinline__ u32 s2u(const void* p) {
    u32 a;
    asm("{.reg .u64 t; cvta.to.shared.u64 t,%1; cvt.u32.u64 %0,t;}" : "=r"(a) : "l"(p));
    return a;
}
__device__ __forceinline__ u32 swz(u32 b) { return b ^ ((b >> 3) & 0x70); }

__device__ __forceinline__ void ldmx4(u32* r, u32 addr) {
    asm volatile("ldmatrix.sync.aligned.m8n8.x4.shared.b16 {%0,%1,%2,%3},[%4];"
                 : "=r"(r[0]), "=r"(r[1]), "=r"(r[2]), "=r"(r[3]) : "r"(addr));
}
// fp16 HMMA, fp32 accumulate
__device__ __forceinline__ void mma_h(float* d, const u32* a, u32 b0, u32 b1) {
    asm volatile(
        "mma.sync.aligned.m16n8k16.row.col.f32.f16.f16.f32 "
        "{%0,%1,%2,%3},{%4,%5,%6,%7},{%8,%9},{%0,%1,%2,%3};"
        : "+f"(d[0]), "+f"(d[1]), "+f"(d[2]), "+f"(d[3])
        : "r"(a[0]), "r"(a[1]), "r"(a[2]), "r"(a[3]), "r"(b0), "r"(b1));
}

__device__ __forceinline__ u32 bits2h(__half2 v) {
    u32 u; __builtin_memcpy(&u, &v, 4); return u;
}
__device__ __forceinline__ __half2 h2(u32 u) {
    __half2 v; __builtin_memcpy(&v, &u, 4); return v;
}
// split (a,b) fp32 pair into hi/lo fp16x2 packs
__device__ __forceinline__ void split2h(float a, float b, u32& h, u32& l) {
    __half2 hh = __floats2half2_rn(a, b);
    float ra = a - __half2float(__low2half(hh));
    float rb = b - __half2float(__high2half(hh));
    __half2 ll = __floats2half2_rn(ra, rb);
    h = bits2h(hh); l = bits2h(ll);
}

// ---------------------------------------------------------------------------
// weight prep (all fp16 single-plane)
// ---------------------------------------------------------------------------
__global__ void prep_w(const float* __restrict__ w0, const float* __restrict__ wr,
                       const float* __restrict__ cw1)
{
    int i = blockIdx.x * blockDim.x + threadIdx.x;
    if (i < 1024) {
        int lane = i & 31, nq = (i >> 5) & 7, j = (i >> 8) & 3;
        int g = lane >> 2, t = lane & 3, n = nq * 8 + g;
        int ks[4] = {16 * j + 2 * t, 16 * j + 2 * t + 1,
                     16 * j + 2 * t + 8, 16 * j + 2 * t + 9};
        __half b[4];
#pragma unroll
        for (int q = 0; q < 4; q++) {
            int k = ks[q];
            float v = (k < 55) ? w0[k * 64 + n] : 0.f;
            b[q] = __float2half_rn(v);
        }
        g_B0[i * 2]     = bits2h(__halves2half2(b[0], b[1]));
        g_B0[i * 2 + 1] = bits2h(__halves2half2(b[2], b[3]));
    }
    if (i < 2048) {
        int n = i >> 6, k = i & 63;
        float v = cw1[k * 32 + n];
        *(__half*)((char*)g_C1 + swz((u32)(n * 128 + k * 2))) = __float2half_rn(v);
    }
    if (i < 3 * 64 * 320) {
        int l = i / (64 * 320), r = i % (64 * 320);
        int n = r / 320, k = r % 320;
        float v = wr[(size_t)l * 320 * 64 + (size_t)k * 64 + n];
        int kk = k & 15;
        int kp = (k & ~15) | (2 * (kk >> 2) + (kk & 1) + 8 * ((kk >> 1) & 1));
        g_WR[((size_t)l * 64 + n) * 320 + kp] = __float2half_rn(v);
    }
}

// ===========================================================================
// Layer 0 (C=11): persistent, barrier-free, warp-private frag-packed A
// fp32 input -> hi/lo 2-term; fp16 output
// ===========================================================================
constexpr int L0_B0 = 0;                  // 8 KB prepacked B frags (fp16)
constexpr int L0_A  = 8192;               // 8 warps x 4 KB (hi 2KB | lo 2KB)
constexpr int SMEM_L0 = L0_A + 8 * 4096;  // 40960

__global__ __launch_bounds__(256, 2)
void mesh_l0(const float* __restrict__ xin, const int* __restrict__ nbr,
             const u32* __restrict__ B0, const float* __restrict__ bias,
             const float* __restrict__ lng, const float* __restrict__ lnb,
             __half* __restrict__ out)
{
    extern __shared__ char smc[];
    const int tid = threadIdx.x, wid = tid >> 5, lane = tid & 31;

    for (int i = tid; i < 512; i += 256)
        ((uint4*)(smc + L0_B0))[i] = ((const uint4*)B0)[i];
    __syncthreads();

    char* Aw = smc + L0_A + wid * 4096;
    const int  w     = lane >> 1;
    const int  half_ = lane & 1;
    const int  g = lane >> 2, t = lane & 3;

    for (int tile = blockIdx.x; tile < NTILES; tile += gridDim.x) {
        const int node0 = tile * 128;
        const int node  = node0 + wid * 16 + w;
        const bool valid = node < E_NODES;

        __syncwarp();

        auto wrA = [&](int k, float v) {
            __half hh = __float2half_rn(v);
            __half ll = __float2half_rn(v - __half2float(hh));
            int j = k >> 4, kk = k & 15;
            int pair = kk >> 3, tt = (kk >> 1) & 3, ii = kk & 1;
            int reg = pair * 2 + (w >> 3);
            u32 off = (u32)(((j * 32 + (w & 7) * 4 + tt) << 4) + reg * 4 + ii * 2);
            *(__half*)(Aw + off)        = hh;
            *(__half*)(Aw + 2048 + off) = ll;
        };

        if (valid) {
            int4 nb = ((const int4*)nbr)[node];
            if (half_ == 0) {
                const float* xr = xin + (size_t)node * 11;
                const float* A_ = xin + (size_t)nb.x * 11;
                const float* C_ = xin + (size_t)nb.z * 11;
#pragma unroll
                for (int ch = 0; ch < 11; ch++) {
                    wrA(ch, xr[ch]);
                    float a = A_[ch], c = C_[ch];
                    wrA(11 + ch, fabsf(a - c));
                    wrA(22 + ch, a + c);
                }
            } else {
                const float* B_ = xin + (size_t)nb.y * 11;
                const float* D_ = xin + (size_t)nb.w * 11;
#pragma unroll
                for (int ch = 0; ch < 11; ch++) {
                    float b = B_[ch], d = D_[ch];
                    wrA(33 + ch, fabsf(b - d));
                    wrA(44 + ch, b + d);
                }
#pragma unroll
                for (int k = 55; k < 64; k++) wrA(k, 0.f);
            }
        }
        __syncwarp();

        float acc[8][4];
#pragma unroll
        for (int q = 0; q < 8; q++)
#pragma unroll
            for (int c = 0; c < 4; c++) acc[q][c] = 0.f;

#pragma unroll
        for (int j = 0; j < 4; j++) {
            uint4 avh = *(const uint4*)(Aw + (j * 32 + lane) * 16);
            uint4 avl = *(const uint4*)(Aw + 2048 + (j * 32 + lane) * 16);
            u32 ah[4] = {avh.x, avh.y, avh.z, avh.w};
            u32 al[4] = {avl.x, avl.y, avl.z, avl.w};
#pragma unroll
            for (int nq = 0; nq < 8; nq++) {
                uint2 bh = *(const uint2*)(smc + L0_B0 + (size_t)((j * 8 + nq) * 32 + lane) * 8);
                mma_h(acc[nq], ah, bh.x, bh.y);
                mma_h(acc[nq], al, bh.x, bh.y);
            }
        }

#pragma unroll
        for (int hf = 0; hf < 2; hf++) {
            int row = node0 + wid * 16 + g + 8 * hf;
            bool vv = row < E_NODES;
            float tv[16];
            float part = 0.f;
#pragma unroll
            for (int nq = 0; nq < 8; nq++) {
                int c = 8 * nq + 2 * t;
                float2 b2 = *(const float2*)(bias + c);
                tv[2 * nq]     = acc[nq][2 * hf]     + b2.x;
                tv[2 * nq + 1] = acc[nq][2 * hf + 1] + b2.y;
                part += tv[2 * nq] + tv[2 * nq + 1];
            }
            part += __shfl_xor_sync(0xFFFFFFFFu, part, 1);
            part += __shfl_xor_sync(0xFFFFFFFFu, part, 2);
            float mu = part * (1.f / 64.f);
            float vp = 0.f;
#pragma unroll
            for (int i = 0; i < 16; i++) { float d = tv[i] - mu; vp += d * d; }
            vp += __shfl_xor_sync(0xFFFFFFFFu, vp, 1);
            vp += __shfl_xor_sync(0xFFFFFFFFu, vp, 2);
            float rs = rsqrtf(vp * (1.f / 64.f) + 1e-5f);
#pragma unroll
            for (int nq = 0; nq < 8; nq++) {
                int c = 8 * nq + 2 * t;
                float2 g2  = *(const float2*)(lng + c);
                float2 lb2 = *(const float2*)(lnb + c);
                float y0 = fmaxf((tv[2 * nq]     - mu) * rs * g2.x + lb2.x, 0.f);
                float y1 = fmaxf((tv[2 * nq + 1] - mu) * rs * g2.y + lb2.y, 0.f);
                if (vv) *(__half2*)(out + (size_t)row * 64 + c) = __floats2half2_rn(y0, y1);
            }
        }
    }
}

// ===========================================================================
// 64-ch layers: persistent, barrier-free, fp16 activations, 1-term A
// 256 threads, warp = 16 nodes. CLS: HMMA head (2-term) from acc frags
// ===========================================================================
constexpr int NOFF_B  = 8192;                // C1 frag tile lives at 0 (4 KB)
constexpr int NSMEM   = NOFF_B + 5 * 8192;   // 49152

template <bool CLS>
__global__ __launch_bounds__(256, 2)
void mesh_fast(const __half* __restrict__ xin, const int* __restrict__ nbr,
               const __half* __restrict__ Wt,          // [64][320] (k-perm) fp16
               const float* __restrict__ bias, const float* __restrict__ lng,
               const float* __restrict__ lnb,
               const __half* __restrict__ c1t,         // cls frag tile (4 KB)
               const float* __restrict__ cb1,
               const float* __restrict__ cw2, const float* __restrict__ cb2,
               __half* __restrict__ outh, float* __restrict__ outf)
{
    extern __shared__ char smc[];
    const int tid = threadIdx.x, wid = tid >> 5, lane = tid & 31;

    // ---- stage B once: 5 segments, swizzled rows for ldmatrix (40 KB) ----
    for (int j = tid; j < 2560; j += 256) {
        int r = j >> 3, c = j & 7;
        int seg = r >> 6, nrow = r & 63;
        const char* src = (const char*)Wt + (size_t)nrow * 640 + seg * 128 + c * 16;
        char* dst = smc + NOFF_B + seg * 8192;
        *(uint4*)(dst + swz((u32)(nrow * 128 + c * 16))) = *(const uint4*)src;
    }
    if (CLS) {
        for (int i = tid; i < 256; i += 256)
            ((uint4*)smc)[i] = ((const uint4*)c1t)[i];
    }
    __syncthreads();   // the ONLY block barrier

    const int g = lane >> 2, t = lane & 3, t4 = lane >> 3;

    auto bofs = [&](int pb, int k16) -> u32 {
        return swz((u32)(((2 * pb + (t4 >> 1)) * 8 + (lane & 7)) * 128
                         + k16 * 32 + ((t4 & 1) << 4)));
    };

    for (int tile = blockIdx.x; tile < NTILES; tile += gridDim.x) {
        const int node0 = tile * 128;
        const int base = node0 + wid * 16 + g;
        const int row0 = base, row1 = base + 8;
        const bool v0 = row0 < E_NODES, v1 = row1 < E_NODES;
        const int rr0 = v0 ? row0 : 0, rr1 = v1 ? row1 : 0;

        const int4 nb0 = ((const int4*)nbr)[rr0];
        const int4 nb1 = ((const int4*)nbr)[rr1];

        float acc[8][4];
#pragma unroll
        for (int q = 0; q < 8; q++)
#pragma unroll
            for (int c = 0; c < 4; c++) acc[q][c] = 0.f;

        auto run_seg = [&](int seg, int k16, u32 (&ah)[4]) {
            u32 bh[16];
            u32 bh_b = s2u(smc + NOFF_B + seg * 8192);
#pragma unroll
            for (int pb = 0; pb < 4; pb++)
                ldmx4(bh + 4 * pb, bh_b + bofs(pb, k16));
#pragma unroll
            for (int nq = 0; nq < 8; nq++)
                mma_h(acc[nq], ah, bh[2 * nq], bh[2 * nq + 1]);
        };

        // ---- phase 0: x (seg 0) — fp16 rows ARE the A fragments ----
#pragma unroll
        for (int j = 0; j < 4; j++) {
            const int fo = 16 * j + 4 * t;
            uint2 p0 = *(const uint2*)(xin + (size_t)rr0 * 64 + fo);
            uint2 p1 = *(const uint2*)(xin + (size_t)rr1 * 64 + fo);
            u32 ah[4] = {p0.x, p1.x, p0.y, p1.y};
            run_seg(0, j, ah);
        }

        // ---- phases 1,2: neighbor pairs (segs 1,2 and 3,4), fp16 math ----
#pragma unroll
        for (int ph = 0; ph < 2; ph++) {
            const int sd = ph ? 3 : 1;
            const int ia0 = ph ? nb0.y : nb0.x;
            const int ic0 = ph ? nb0.w : nb0.z;
            const int ia1 = ph ? nb1.y : nb1.x;
            const int ic1 = ph ? nb1.w : nb1.z;
            const __half* A0 = xin + (size_t)ia0 * 64;
            const __half* C0 = xin + (size_t)ic0 * 64;
            const __half* A1 = xin + (size_t)ia1 * 64;
            const __half* C1_ = xin + (size_t)ic1 * 64;
#pragma unroll
            for (int j = 0; j < 4; j++) {
                const int fo = 16 * j + 4 * t;
                uint2 a0 = *(const uint2*)(A0 + fo);
                uint2 a1 = *(const uint2*)(A1 + fo);
                uint2 c0 = *(const uint2*)(C0 + fo);
                uint2 c1 = *(const uint2*)(C1_ + fo);
                u32 dh[4], sh[4];
                dh[0] = bits2h(__habs2(__hsub2(h2(a0.x), h2(c0.x))));
                dh[1] = bits2h(__habs2(__hsub2(h2(a1.x), h2(c1.x))));
                dh[2] = bits2h(__habs2(__hsub2(h2(a0.y), h2(c0.y))));
                dh[3] = bits2h(__habs2(__hsub2(h2(a1.y), h2(c1.y))));
                sh[0] = bits2h(__hadd2(h2(a0.x), h2(c0.x)));
                sh[1] = bits2h(__hadd2(h2(a1.x), h2(c1.x)));
                sh[2] = bits2h(__hadd2(h2(a0.y), h2(c0.y)));
                sh[3] = bits2h(__hadd2(h2(a1.y), h2(c1.y)));
                run_seg(sd, j, dh);
                run_seg(sd + 1, j, sh);
            }
        }

        // ---- epilogue: bias + LN + ReLU + residual, in registers ----
#pragma unroll
        for (int hf = 0; hf < 2; hf++) {
            const int row = hf ? row1 : row0;
            const bool v_ = hf ? v1 : v0;
            float tv[16];
            float part = 0.f;
#pragma unroll
            for (int nq = 0; nq < 8; nq++) {
                int c = 8 * nq + 2 * t;
                float2 b2 = *(const float2*)(bias + c);
                tv[2 * nq]     = acc[nq][2 * hf]     + b2.x;
                tv[2 * nq + 1] = acc[nq][2 * hf + 1] + b2.y;
                part += tv[2 * nq] + tv[2 * nq + 1];
            }
            part += __shfl_xor_sync(0xFFFFFFFFu, part, 1);
            part += __shfl_xor_sync(0xFFFFFFFFu, part, 2);
            float mu = part * (1.f / 64.f);
            float vp = 0.f;
#pragma unroll
            for (int i = 0; i < 16; i++) { float d = tv[i] - mu; vp += d * d; }
            vp += __shfl_xor_sync(0xFFFFFFFFu, vp, 1);
            vp += __shfl_xor_sync(0xFFFFFFFFu, vp, 2);
            float rsv = rsqrtf(vp * (1.f / 64.f) + 1e-5f);
#pragma unroll
            for (int nq = 0; nq < 8; nq++) {
                int c = 8 * nq + 2 * t;
                float2 g2  = *(const float2*)(lng + c);
                float2 lb2 = *(const float2*)(lnb + c);
                float2 xr  = __half22float2(*(const __half2*)(xin + (size_t)(v_ ? row : 0) * 64 + c));
                float y0 = fmaxf((tv[2 * nq]     - mu) * rsv * g2.x + lb2.x, 0.f) + xr.x;
                float y1 = fmaxf((tv[2 * nq + 1] - mu) * rsv * g2.y + lb2.y, 0.f) + xr.y;
                if (!CLS) {
                    if (v_) *(__half2*)(outh + (size_t)row * 64 + c) = __floats2half2_rn(y0, y1);
                } else {
                    acc[nq][2 * hf]     = y0;
                    acc[nq][2 * hf + 1] = y1;
                }
            }
        }

        if (CLS) {
            // ---- head GEMM z = y@cw1 + cb1 on HMMA (2-term split) ----
            float zacc[4][4];
#pragma unroll
            for (int nq = 0; nq < 4; nq++) {
                float b0 = __ldg(cb1 + 8 * nq + 2 * t);
                float b1 = __ldg(cb1 + 8 * nq + 2 * t + 1);
                zacc[nq][0] = b0; zacc[nq][1] = b1; zacc[nq][2] = b0; zacc[nq][3] = b1;
            }
            const u32 c1h = s2u(smc);
#pragma unroll
            for (int j = 0; j < 4; j++) {
                u32 ah[4], al[4];
                split2h(acc[2 * j][0],     acc[2 * j][1],     ah[0], al[0]);
                split2h(acc[2 * j][2],     acc[2 * j][3],     ah[1], al[1]);
                split2h(acc[2 * j + 1][0], acc[2 * j + 1][1], ah[2], al[2]);
                split2h(acc[2 * j + 1][2], acc[2 * j + 1][3], ah[3], al[3]);
                u32 bh[8];
#pragma unroll
                for (int pb = 0; pb < 2; pb++)
                    ldmx4(bh + 4 * pb, c1h + bofs(pb, j));
#pragma unroll
                for (int nq = 0; nq < 4; nq++) {
                    mma_h(zacc[nq], ah, bh[2 * nq], bh[2 * nq + 1]);
                    mma_h(zacc[nq], al, bh[2 * nq], bh[2 * nq + 1]);
                }
            }
            float p0 = 0.f, p1 = 0.f;
#pragma unroll
            for (int nq = 0; nq < 4; nq++) {
                float w0 = __ldg(cw2 + 8 * nq + 2 * t);
                float w1 = __ldg(cw2 + 8 * nq + 2 * t + 1);
                p0 += fmaxf(zacc[nq][0], 0.f) * w0 + fmaxf(zacc[nq][1], 0.f) * w1;
                p1 += fmaxf(zacc[nq][2], 0.f) * w0 + fmaxf(zacc[nq][3], 0.f) * w1;
            }
            p0 += __shfl_xor_sync(0xFFFFFFFFu, p0, 1);
            p0 += __shfl_xor_sync(0xFFFFFFFFu, p0, 2);
            p1 += __shfl_xor_sync(0xFFFFFFFFu, p1, 1);
            p1 += __shfl_xor_sync(0xFFFFFFFFu, p1, 2);
            if (t == 0) {
                float c2 = __ldg(cb2);
                if (v0) outf[row0] = p0 + c2;
                if (v1) outf[row1] = p1 + c2;
            }
        }
    }
}

// ---------------------------------------------------------------------------

extern "C" void kernel_launch(void* const* d_in, const int* in_sizes, int n_in,
                              void* d_out, int out_size)
{
    const float* x      = (const float*)d_in[0];
    const int*   nbr    = (const int*)  d_in[1];
    const float* w0     = (const float*)d_in[2];
    const float* b0     = (const float*)d_in[3];
    const float* w_rest = (const float*)d_in[4];
    const float* b_rest = (const float*)d_in[5];
    const float* ln_g   = (const float*)d_in[6];
    const float* ln_b   = (const float*)d_in[7];
    const float* cw1    = (const float*)d_in[8];
    const float* cb1    = (const float*)d_in[9];
    const float* cw2    = (const float*)d_in[10];
    const float* cb2    = (const float*)d_in[11];
    float* out = (float*)d_out;

    __half *bufA, *bufB, *WRp, *C1p;
    u32 *B0p;
    cudaGetSymbolAddress((void**)&bufA, g_bufA);
    cudaGetSymbolAddress((void**)&bufB, g_bufB);
    cudaGetSymbolAddress((void**)&WRp, g_WR);
    cudaGetSymbolAddress((void**)&B0p, g_B0);
    cudaGetSymbolAddress((void**)&C1p, g_C1);

    cudaFuncSetAttribute(mesh_l0, cudaFuncAttributeMaxDynamicSharedMemorySize, SMEM_L0);
    cudaFuncSetAttribute(mesh_fast<false>, cudaFuncAttributeMaxDynamicSharedMemorySize, NSMEM);
    cudaFuncSetAttribute(mesh_fast<true>,  cudaFuncAttributeMaxDynamicSharedMemorySize, NSMEM);

    prep_w<<<240, 256>>>(w0, w_rest, cw1);

    mesh_l0<<<PGRID, 256, SMEM_L0>>>(x, nbr, B0p, b0, ln_g, ln_b, bufA);

    mesh_fast<false><<<PGRID, 256, NSMEM>>>(
        bufA, nbr, WRp, b_rest, ln_g + 64, ln_b + 64,
        nullptr, nullptr, nullptr, nullptr, bufB, nullptr);

    mesh_fast<false><<<PGRID, 256, NSMEM>>>(
        bufB, nbr, WRp + 64 * 320, b_rest + 64, ln_g + 128, ln_b + 128,
        nullptr, nullptr, nullptr, nullptr, bufA, nullptr);

    mesh_fast<true><<<PGRID, 256, NSMEM>>>(
        bufA, nbr, WRp + 2 * 64 * 320, b_rest + 128, ln_g + 192, ln_b + 192,
        C1p, cb1, cw2, cb2, nullptr, out);
}

// round 14
// speedup vs baseline: 5.0712x; 1.1586x over previous
#include <cuda_runtime.h>
#include <cuda_fp16.h>
#include <cstdint>

typedef unsigned int u32;
typedef unsigned long long u64;

#define E_NODES 1000000
#define NTILES ((E_NODES + 127) / 128)
#define PGRID 304

// Scratch activations (fp16) + prepacked weights (alloc-free rule)
__device__ __half g_bufA[(size_t)E_NODES * 64];
__device__ __half g_bufB[(size_t)E_NODES * 64];
__device__ __half g_WR[3 * 64 * 320];                // [l][n][kperm2]  fp16
__device__ __align__(16) u32 g_B0[4 * 8 * 32 * 2];   // l0 frag-packed B (fp16)
__device__ __align__(16) __half g_C1[32 * 64];       // cls W1 frag tile (fp16)

// ---------------------------------------------------------------------------
// helpers
// ---------------------------------------------------------------------------
__device__ __forceinline__ u32 s2u(const void* p) {
    u32 a;
    asm("{.reg .u64 t; cvta.to.shared.u64 t,%1; cvt.u32.u64 %0,t;}" : "=r"(a) : "l"(p));
    return a;
}
__device__ __forceinline__ u32 swz(u32 b) { return b ^ ((b >> 3) & 0x70); }

__device__ __forceinline__ void ldmx4(u32* r, u32 addr) {
    asm volatile("ldmatrix.sync.aligned.m8n8.x4.shared.b16 {%0,%1,%2,%3},[%4];"
                 : "=r"(r[0]), "=r"(r[1]), "=r"(r[2]), "=r"(r[3]) : "r"(addr));
}
__device__ __forceinline__ void mma_h(float* d, const u32* a, u32 b0, u32 b1) {
    asm volatile(
        "mma.sync.aligned.m16n8k16.row.col.f32.f16.f16.f32 "
        "{%0,%1,%2,%3},{%4,%5,%6,%7},{%8,%9},{%0,%1,%2,%3};"
        : "+f"(d[0]), "+f"(d[1]), "+f"(d[2]), "+f"(d[3])
        : "r"(a[0]), "r"(a[1]), "r"(a[2]), "r"(a[3]), "r"(b0), "r"(b1));
}

__device__ __forceinline__ u32 bits2h(__half2 v) {
    u32 u; __builtin_memcpy(&u, &v, 4); return u;
}
__device__ __forceinline__ __half2 h2(u32 u) {
    __half2 v; __builtin_memcpy(&v, &u, 4); return v;
}
__device__ __forceinline__ u32 habsd(u32 a, u32 c) {
    return bits2h(__habs2(__hsub2(h2(a), h2(c))));
}
__device__ __forceinline__ u32 hsum(u32 a, u32 c) {
    return bits2h(__hadd2(h2(a), h2(c)));
}
// split (a,b) fp32 pair into hi/lo fp16x2 packs
__device__ __forceinline__ void split2h(float a, float b, u32& h, u32& l) {
    __half2 hh = __floats2half2_rn(a, b);
    float ra = a - __half2float(__low2half(hh));
    float rb = b - __half2float(__high2half(hh));
    __half2 ll = __floats2half2_rn(ra, rb);
    h = bits2h(hh); l = bits2h(ll);
}

// ---------------------------------------------------------------------------
// weight prep:
//  - mids: transpose to [n][k], K-PERM v2 (paired-uint4 gather layout)
//  - l0:   frag-packed B (logical k), zero-pad K 55->64
//  - cls:  cw1 -> [32 n][64 k] swizzled frag tile (4 KB)
// ---------------------------------------------------------------------------
__global__ void prep_w(const float* __restrict__ w0, const float* __restrict__ wr,
                       const float* __restrict__ cw1)
{
    int i = blockIdx.x * blockDim.x + threadIdx.x;
    if (i < 1024) {
        int lane = i & 31, nq = (i >> 5) & 7, j = (i >> 8) & 3;
        int g = lane >> 2, t = lane & 3, n = nq * 8 + g;
        int ks[4] = {16 * j + 2 * t, 16 * j + 2 * t + 1,
                     16 * j + 2 * t + 8, 16 * j + 2 * t + 9};
        __half b[4];
#pragma unroll
        for (int q = 0; q < 4; q++) {
            int k = ks[q];
            float v = (k < 55) ? w0[k * 64 + n] : 0.f;
            b[q] = __float2half_rn(v);
        }
        g_B0[i * 2]     = bits2h(__halves2half2(b[0], b[1]));
        g_B0[i * 2 + 1] = bits2h(__halves2half2(b[2], b[3]));
    }
    if (i < 2048) {
        int n = i >> 6, k = i & 63;
        float v = cw1[k * 32 + n];
        *(__half*)((char*)g_C1 + swz((u32)(n * 128 + k * 2))) = __float2half_rn(v);
    }
    if (i < 3 * 64 * 320) {
        int l = i / (64 * 320), r = i % (64 * 320);
        int n = r / 320, k = r % 320;
        float v = wr[(size_t)l * 320 * 64 + (size_t)k * 64 + n];
        // k-perm v2 within each 64-half segment: logical ls -> eff E
        int ls = k & 63;
        int p = ls >> 5, q5 = ls & 31, tt = q5 >> 3, q = q5 & 7;
        int E = (p << 5) + ((q >> 2) << 4) + 2 * tt + (q & 1) + (((q >> 1) & 1) << 3);
        int kp = (k & ~63) | E;
        g_WR[((size_t)l * 64 + n) * 320 + kp] = __float2half_rn(v);
    }
}

// ===========================================================================
// Layer 0 (C=11): persistent, barrier-free, warp-private frag-packed A
// fp32 input -> hi/lo 2-term; fp16 output  (unchanged, proven)
// ===========================================================================
constexpr int L0_B0 = 0;
constexpr int L0_A  = 8192;
constexpr int SMEM_L0 = L0_A + 8 * 4096;  // 40960

__global__ __launch_bounds__(256, 2)
void mesh_l0(const float* __restrict__ xin, const int* __restrict__ nbr,
             const u32* __restrict__ B0, const float* __restrict__ bias,
             const float* __restrict__ lng, const float* __restrict__ lnb,
             __half* __restrict__ out)
{
    extern __shared__ char smc[];
    const int tid = threadIdx.x, wid = tid >> 5, lane = tid & 31;

    for (int i = tid; i < 512; i += 256)
        ((uint4*)(smc + L0_B0))[i] = ((const uint4*)B0)[i];
    __syncthreads();

    char* Aw = smc + L0_A + wid * 4096;
    const int  w     = lane >> 1;
    const int  half_ = lane & 1;
    const int  g = lane >> 2, t = lane & 3;

    for (int tile = blockIdx.x; tile < NTILES; tile += gridDim.x) {
        const int node0 = tile * 128;
        const int node  = node0 + wid * 16 + w;
        const bool valid = node < E_NODES;

        __syncwarp();

        auto wrA = [&](int k, float v) {
            __half hh = __float2half_rn(v);
            __half ll = __float2half_rn(v - __half2float(hh));
            int j = k >> 4, kk = k & 15;
            int pair = kk >> 3, tt = (kk >> 1) & 3, ii = kk & 1;
            int reg = pair * 2 + (w >> 3);
            u32 off = (u32)(((j * 32 + (w & 7) * 4 + tt) << 4) + reg * 4 + ii * 2);
            *(__half*)(Aw + off)        = hh;
            *(__half*)(Aw + 2048 + off) = ll;
        };

        if (valid) {
            int4 nb = ((const int4*)nbr)[node];
            if (half_ == 0) {
                const float* xr = xin + (size_t)node * 11;
                const float* A_ = xin + (size_t)nb.x * 11;
                const float* C_ = xin + (size_t)nb.z * 11;
#pragma unroll
                for (int ch = 0; ch < 11; ch++) {
                    wrA(ch, xr[ch]);
                    float a = A_[ch], c = C_[ch];
                    wrA(11 + ch, fabsf(a - c));
                    wrA(22 + ch, a + c);
                }
            } else {
                const float* B_ = xin + (size_t)nb.y * 11;
                const float* D_ = xin + (size_t)nb.w * 11;
#pragma unroll
                for (int ch = 0; ch < 11; ch++) {
                    float b = B_[ch], d = D_[ch];
                    wrA(33 + ch, fabsf(b - d));
                    wrA(44 + ch, b + d);
                }
#pragma unroll
                for (int k = 55; k < 64; k++) wrA(k, 0.f);
            }
        }
        __syncwarp();

        float acc[8][4];
#pragma unroll
        for (int q = 0; q < 8; q++)
#pragma unroll
            for (int c = 0; c < 4; c++) acc[q][c] = 0.f;

#pragma unroll
        for (int j = 0; j < 4; j++) {
            uint4 avh = *(const uint4*)(Aw + (j * 32 + lane) * 16);
            uint4 avl = *(const uint4*)(Aw + 2048 + (j * 32 + lane) * 16);
            u32 ah[4] = {avh.x, avh.y, avh.z, avh.w};
            u32 al[4] = {avl.x, avl.y, avl.z, avl.w};
#pragma unroll
            for (int nq = 0; nq < 8; nq++) {
                uint2 bh = *(const uint2*)(smc + L0_B0 + (size_t)((j * 8 + nq) * 32 + lane) * 8);
                mma_h(acc[nq], ah, bh.x, bh.y);
                mma_h(acc[nq], al, bh.x, bh.y);
            }
        }

#pragma unroll
        for (int hf = 0; hf < 2; hf++) {
            int row = node0 + wid * 16 + g + 8 * hf;
            bool vv = row < E_NODES;
            float tv[16];
            float part = 0.f;
#pragma unroll
            for (int nq = 0; nq < 8; nq++) {
                int c = 8 * nq + 2 * t;
                float2 b2 = *(const float2*)(bias + c);
                tv[2 * nq]     = acc[nq][2 * hf]     + b2.x;
                tv[2 * nq + 1] = acc[nq][2 * hf + 1] + b2.y;
                part += tv[2 * nq] + tv[2 * nq + 1];
            }
            part += __shfl_xor_sync(0xFFFFFFFFu, part, 1);
            part += __shfl_xor_sync(0xFFFFFFFFu, part, 2);
            float mu = part * (1.f / 64.f);
            float vp = 0.f;
#pragma unroll
            for (int i = 0; i < 16; i++) { float d = tv[i] - mu; vp += d * d; }
            vp += __shfl_xor_sync(0xFFFFFFFFu, vp, 1);
            vp += __shfl_xor_sync(0xFFFFFFFFu, vp, 2);
            float rs = rsqrtf(vp * (1.f / 64.f) + 1e-5f);
#pragma unroll
            for (int nq = 0; nq < 8; nq++) {
                int c = 8 * nq + 2 * t;
                float2 g2  = *(const float2*)(lng + c);
                float2 lb2 = *(const float2*)(lnb + c);
                float y0 = fmaxf((tv[2 * nq]     - mu) * rs * g2.x + lb2.x, 0.f);
                float y1 = fmaxf((tv[2 * nq + 1] - mu) * rs * g2.y + lb2.y, 0.f);
                if (vv) *(__half2*)(out + (size_t)row * 64 + c) = __floats2half2_rn(y0, y1);
            }
        }
    }
}

// ===========================================================================
// 64-ch layers: persistent, barrier-free, paired-uint4 gather (k-perm v2)
// 128 threads, 4 warps, warp = 32 nodes (2 m16 row-blocks), tile = 128 nodes
// ===========================================================================
constexpr int NOFF_B  = 8192;                // C1 frag tile lives at 0 (4 KB)
constexpr int NSMEM   = NOFF_B + 5 * 8192;   // 49152

template <bool CLS>
__global__ __launch_bounds__(128, 2)
void mesh_fast(const __half* __restrict__ xin, const int* __restrict__ nbr,
               const __half* __restrict__ Wt,          // [64][320] (k-perm2) fp16
               const float* __restrict__ bias, const float* __restrict__ lng,
               const float* __restrict__ lnb,
               const __half* __restrict__ c1t,         // cls frag tile (4 KB)
               const float* __restrict__ cb1,
               const float* __restrict__ cw2, const float* __restrict__ cb2,
               __half* __restrict__ outh, float* __restrict__ outf)
{
    extern __shared__ char smc[];
    const int tid = threadIdx.x, wid = tid >> 5, lane = tid & 31;

    // ---- stage B once: 5 segments, swizzled rows for ldmatrix (40 KB) ----
    for (int j = tid; j < 2560; j += 128) {
        int r = j >> 3, c = j & 7;
        int seg = r >> 6, nrow = r & 63;
        const char* src = (const char*)Wt + (size_t)nrow * 640 + seg * 128 + c * 16;
        char* dst = smc + NOFF_B + seg * 8192;
        *(uint4*)(dst + swz((u32)(nrow * 128 + c * 16))) = *(const uint4*)src;
    }
    if (CLS) {
        for (int i = tid; i < 256; i += 128)
            ((uint4*)smc)[i] = ((const uint4*)c1t)[i];
    }
    __syncthreads();   // the ONLY block barrier

    const int g = lane >> 2, t = lane & 3, t4 = lane >> 3;

    auto bofs = [&](int pb, int k16) -> u32 {
        return swz((u32)(((2 * pb + (t4 >> 1)) * 8 + (lane & 7)) * 128
                         + k16 * 32 + ((t4 & 1) << 4)));
    };

    for (int tile = blockIdx.x; tile < NTILES; tile += gridDim.x) {
        const int node0 = tile * 128;
        // warp covers 32 rows: row-block rb in {0,1}, half hf in {0,1}
        int  rr[4]; bool vv[4];
#pragma unroll
        for (int i = 0; i < 4; i++) {
            int row = node0 + wid * 32 + 16 * (i >> 1) + 8 * (i & 1) + g;
            vv[i] = row < E_NODES;
            rr[i] = vv[i] ? row : 0;
        }
        int4 nb[4];
#pragma unroll
        for (int i = 0; i < 4; i++) nb[i] = ((const int4*)nbr)[rr[i]];

        float acc[2][8][4];
#pragma unroll
        for (int rb = 0; rb < 2; rb++)
#pragma unroll
            for (int q = 0; q < 8; q++)
#pragma unroll
                for (int c = 0; c < 4; c++) acc[rb][q][c] = 0.f;

        auto run_seg = [&](int seg, int k16, const u32* a0, const u32* a1) {
            u32 bh[16];
            u32 bb = s2u(smc + NOFF_B + seg * 8192);
#pragma unroll
            for (int pb = 0; pb < 4; pb++)
                ldmx4(bh + 4 * pb, bb + bofs(pb, k16));
#pragma unroll
            for (int nq = 0; nq < 8; nq++) {
                mma_h(acc[0][nq], a0, bh[2 * nq], bh[2 * nq + 1]);
                mma_h(acc[1][nq], a1, bh[2 * nq], bh[2 * nq + 1]);
            }
        };

        // ---- phase 0: x (seg 0) — one uint4 covers two k16 blocks ----
#pragma unroll
        for (int p = 0; p < 2; p++) {
            const int fo = 32 * p + 8 * t;
            uint4 x00 = *(const uint4*)(xin + (size_t)rr[0] * 64 + fo);
            uint4 x01 = *(const uint4*)(xin + (size_t)rr[1] * 64 + fo);
            uint4 x10 = *(const uint4*)(xin + (size_t)rr[2] * 64 + fo);
            uint4 x11 = *(const uint4*)(xin + (size_t)rr[3] * 64 + fo);
            u32 aA0[4] = {x00.x, x01.x, x00.y, x01.y};
            u32 aA1[4] = {x10.x, x11.x, x10.y, x11.y};
            run_seg(0, 2 * p, aA0, aA1);
            u32 aB0[4] = {x00.z, x01.z, x00.w, x01.w};
            u32 aB1[4] = {x10.z, x11.z, x10.w, x11.w};
            run_seg(0, 2 * p + 1, aB0, aB1);
        }

        // ---- phases 1,2: neighbor pairs (segs 1,2 and 3,4) ----
#pragma unroll
        for (int ph = 0; ph < 2; ph++) {
            const int sd = ph ? 3 : 1;
            int ia[4], ic[4];
#pragma unroll
            for (int i = 0; i < 4; i++) {
                ia[i] = ph ? nb[i].y : nb[i].x;
                ic[i] = ph ? nb[i].w : nb[i].z;
            }
#pragma unroll
            for (int p = 0; p < 2; p++) {
                const int fo = 32 * p + 8 * t;
                uint4 av[4], cv[4];
#pragma unroll
                for (int i = 0; i < 4; i++) {
                    av[i] = *(const uint4*)(xin + (size_t)ia[i] * 64 + fo);
                    cv[i] = *(const uint4*)(xin + (size_t)ic[i] * 64 + fo);
                }
                u32 dA0[4] = {habsd(av[0].x, cv[0].x), habsd(av[1].x, cv[1].x),
                              habsd(av[0].y, cv[0].y), habsd(av[1].y, cv[1].y)};
                u32 dA1[4] = {habsd(av[2].x, cv[2].x), habsd(av[3].x, cv[3].x),
                              habsd(av[2].y, cv[2].y), habsd(av[3].y, cv[3].y)};
                run_seg(sd, 2 * p, dA0, dA1);
                u32 dB0[4] = {habsd(av[0].z, cv[0].z), habsd(av[1].z, cv[1].z),
                              habsd(av[0].w, cv[0].w), habsd(av[1].w, cv[1].w)};
                u32 dB1[4] = {habsd(av[2].z, cv[2].z), habsd(av[3].z, cv[3].z),
                              habsd(av[2].w, cv[2].w), habsd(av[3].w, cv[3].w)};
                run_seg(sd, 2 * p + 1, dB0, dB1);
                u32 sA0[4] = {hsum(av[0].x, cv[0].x), hsum(av[1].x, cv[1].x),
                              hsum(av[0].y, cv[0].y), hsum(av[1].y, cv[1].y)};
                u32 sA1[4] = {hsum(av[2].x, cv[2].x), hsum(av[3].x, cv[3].x),
                              hsum(av[2].y, cv[2].y), hsum(av[3].y, cv[3].y)};
                run_seg(sd + 1, 2 * p, sA0, sA1);
                u32 sB0[4] = {hsum(av[0].z, cv[0].z), hsum(av[1].z, cv[1].z),
                              hsum(av[0].w, cv[0].w), hsum(av[1].w, cv[1].w)};
                u32 sB1[4] = {hsum(av[2].z, cv[2].z), hsum(av[3].z, cv[3].z),
                              hsum(av[2].w, cv[2].w), hsum(av[3].w, cv[3].w)};
                run_seg(sd + 1, 2 * p + 1, sB0, sB1);
            }
        }

        // ---- epilogue: bias + LN + ReLU + residual, in registers ----
#pragma unroll
        for (int rb = 0; rb < 2; rb++)
#pragma unroll
        for (int hf = 0; hf < 2; hf++) {
            const int idx = rb * 2 + hf;
            const int row = rr[idx];
            const bool v_ = vv[idx];
            float tv[16];
            float part = 0.f;
#pragma unroll
            for (int nq = 0; nq < 8; nq++) {
                int c = 8 * nq + 2 * t;
                float2 b2 = *(const float2*)(bias + c);
                tv[2 * nq]     = acc[rb][nq][2 * hf]     + b2.x;
                tv[2 * nq + 1] = acc[rb][nq][2 * hf + 1] + b2.y;
                part += tv[2 * nq] + tv[2 * nq + 1];
            }
            part += __shfl_xor_sync(0xFFFFFFFFu, part, 1);
            part += __shfl_xor_sync(0xFFFFFFFFu, part, 2);
            float mu = part * (1.f / 64.f);
            float vp = 0.f;
#pragma unroll
            for (int i = 0; i < 16; i++) { float d = tv[i] - mu; vp += d * d; }
            vp += __shfl_xor_sync(0xFFFFFFFFu, vp, 1);
            vp += __shfl_xor_sync(0xFFFFFFFFu, vp, 2);
            float rsv = rsqrtf(vp * (1.f / 64.f) + 1e-5f);
#pragma unroll
            for (int nq = 0; nq < 8; nq++) {
                int c = 8 * nq + 2 * t;
                float2 g2  = *(const float2*)(lng + c);
                float2 lb2 = *(const float2*)(lnb + c);
                float2 xr  = __half22float2(*(const __half2*)(xin + (size_t)row * 64 + c));
                float y0 = fmaxf((tv[2 * nq]     - mu) * rsv * g2.x + lb2.x, 0.f) + xr.x;
                float y1 = fmaxf((tv[2 * nq + 1] - mu) * rsv * g2.y + lb2.y, 0.f) + xr.y;
                if (!CLS) {
                    if (v_) *(__half2*)(outh + (size_t)row * 64 + c) = __floats2half2_rn(y0, y1);
                } else {
                    acc[rb][nq][2 * hf]     = y0;
                    acc[rb][nq][2 * hf + 1] = y1;
                }
            }
        }

        if (CLS) {
            const u32 c1h = s2u(smc);
#pragma unroll
            for (int rb = 0; rb < 2; rb++) {
                // head GEMM z = y@cw1 + cb1 on HMMA (2-term split), per row-block
                float zacc[4][4];
#pragma unroll
                for (int nq = 0; nq < 4; nq++) {
                    float b0 = __ldg(cb1 + 8 * nq + 2 * t);
                    float b1 = __ldg(cb1 + 8 * nq + 2 * t + 1);
                    zacc[nq][0] = b0; zacc[nq][1] = b1; zacc[nq][2] = b0; zacc[nq][3] = b1;
                }
#pragma unroll
                for (int j = 0; j < 4; j++) {
                    u32 ah[4], al[4];
                    split2h(acc[rb][2 * j][0],     acc[rb][2 * j][1],     ah[0], al[0]);
                    split2h(acc[rb][2 * j][2],     acc[rb][2 * j][3],     ah[1], al[1]);
                    split2h(acc[rb][2 * j + 1][0], acc[rb][2 * j + 1][1], ah[2], al[2]);
                    split2h(acc[rb][2 * j + 1][2], acc[rb][2 * j + 1][3], ah[3], al[3]);
                    u32 bh[8];
#pragma unroll
                    for (int pb = 0; pb < 2; pb++)
                        ldmx4(bh + 4 * pb, c1h + bofs(pb, j));
#pragma unroll
                    for (int nq = 0; nq < 4; nq++) {
                        mma_h(zacc[nq], ah, bh[2 * nq], bh[2 * nq + 1]);
                        mma_h(zacc[nq], al, bh[2 * nq], bh[2 * nq + 1]);
                    }
                }
                float p0 = 0.f, p1 = 0.f;
#pragma unroll
                for (int nq = 0; nq < 4; nq++) {
                    float w0 = __ldg(cw2 + 8 * nq + 2 * t);
                    float w1 = __ldg(cw2 + 8 * nq + 2 * t + 1);
                    p0 += fmaxf(zacc[nq][0], 0.f) * w0 + fmaxf(zacc[nq][1], 0.f) * w1;
                    p1 += fmaxf(zacc[nq][2], 0.f) * w0 + fmaxf(zacc[nq][3], 0.f) * w1;
                }
                p0 += __shfl_xor_sync(0xFFFFFFFFu, p0, 1);
                p0 += __shfl_xor_sync(0xFFFFFFFFu, p0, 2);
                p1 += __shfl_xor_sync(0xFFFFFFFFu, p1, 1);
                p1 += __shfl_xor_sync(0xFFFFFFFFu, p1, 2);
                if (t == 0) {
                    float c2 = __ldg(cb2);
                    if (vv[rb * 2 + 0]) outf[rr[rb * 2 + 0]] = p0 + c2;
                    if (vv[rb * 2 + 1]) outf[rr[rb * 2 + 1]] = p1 + c2;
                }
            }
        }
    }
}

// ---------------------------------------------------------------------------

extern "C" void kernel_launch(void* const* d_in, const int* in_sizes, int n_in,
                              void* d_out, int out_size)
{
    const float* x      = (const float*)d_in[0];
    const int*   nbr    = (const int*)  d_in[1];
    const float* w0     = (const float*)d_in[2];
    const float* b0     = (const float*)d_in[3];
    const float* w_rest = (const float*)d_in[4];
    const float* b_rest = (const float*)d_in[5];
    const float* ln_g   = (const float*)d_in[6];
    const float* ln_b   = (const float*)d_in[7];
    const float* cw1    = (const float*)d_in[8];
    const float* cb1    = (const float*)d_in[9];
    const float* cw2    = (const float*)d_in[10];
    const float* cb2    = (const float*)d_in[11];
    float* out = (float*)d_out;

    __half *bufA, *bufB, *WRp, *C1p;
    u32 *B0p;
    cudaGetSymbolAddress((void**)&bufA, g_bufA);
    cudaGetSymbolAddress((void**)&bufB, g_bufB);
    cudaGetSymbolAddress((void**)&WRp, g_WR);
    cudaGetSymbolAddress((void**)&B0p, g_B0);
    cudaGetSymbolAddress((void**)&C1p, g_C1);

    cudaFuncSetAttribute(mesh_l0, cudaFuncAttributeMaxDynamicSharedMemorySize, SMEM_L0);
    cudaFuncSetAttribute(mesh_fast<false>, cudaFuncAttributeMaxDynamicSharedMemorySize, NSMEM);
    cudaFuncSetAttribute(mesh_fast<true>,  cudaFuncAttributeMaxDynamicSharedMemorySize, NSMEM);

    prep_w<<<240, 256>>>(w0, w_rest, cw1);

    mesh_l0<<<PGRID, 256, SMEM_L0>>>(x, nbr, B0p, b0, ln_g, ln_b, bufA);

    mesh_fast<false><<<PGRID, 128, NSMEM>>>(
        bufA, nbr, WRp, b_rest, ln_g + 64, ln_b + 64,
        nullptr, nullptr, nullptr, nullptr, bufB, nullptr);

    mesh_fast<false><<<PGRID, 128, NSMEM>>>(
        bufB, nbr, WRp + 64 * 320, b_rest + 64, ln_g + 128, ln_b + 128,
        nullptr, nullptr, nullptr, nullptr, bufA, nullptr);

    mesh_fast<true><<<PGRID, 128, NSMEM>>>(
        bufA, nbr, WRp + 2 * 64 * 320, b_rest + 128, ln_g + 192, ln_b + 192,
        C1p, cb1, cw2, cb2, nullptr, out);
}